// round 6
// baseline (speedup 1.0000x reference)
#include <cuda_runtime.h>
#include <cstdint>

// ---------------- problem constants ----------------
#define NP   100000
#define NA   200000
#define NSU  1000
#define NTOT (NP + NA + NSU)          // 301000
#define D    64
#define HOPS 5
#define NOUT 16

#define E_PA 800000
#define E_AP 800000
#define E_PS 100000
#define E_SP 100000
#define E_TOT (E_PA + E_AP + E_PS + E_SP)   // 1800000

// row_ptr segment bases (each segment length = Ns+1)
#define RP_PA 0
#define RP_AP (NP + 1)
#define RP_PS (RP_AP + NA + 1)
#define RP_SP (RP_PS + NP + 1)
#define RP_TOT (RP_SP + NSU + 1)

// col array bases
#define CB_PA 0
#define CB_AP E_PA
#define CB_PS (E_PA + E_AP)
#define CB_SP (E_PA + E_AP + E_PS)

// h1 (target-side attention score) bases
#define H1_PA 0                        // len NA  (targets: author)
#define H1_AP NA                       // len NP  (targets: paper)
#define H1_PS (NA + NP)                // len NSU (targets: subject)
#define H1_SP (NA + NP + NSU)          // len NP  (targets: paper)
#define H1_TOT (NA + NP + NSU + NP)    // 401000

// d1/w2 (source-side) segment bases, ordered [pa, ap, ps, sp]
#define D1_PA 0                        // len NP
#define D1_AP NP                       // len NA
#define D1_PS (NP + NA)                // len NP
#define D1_SP (NP + NA + NP)           // len NSU
#define D1_TOT (NP + NA + NP + NSU)    // 401000

// ---------------- scratch (static device memory; no runtime alloc) ----------------
__device__ float g_x [NTOT * D];
__device__ float g_hA[NTOT * D];
__device__ float g_hB[NTOT * D];
__device__ float g_h1[H1_TOT];
__device__ float g_d1[HOPS * D1_TOT];
__device__ float g_w2[HOPS * D1_TOT];
__device__ int   g_rowptr[RP_TOT];
__device__ int   g_cursor[RP_TOT];
__device__ int   g_col[E_TOT];
__device__ int   g_src[E_TOT];
__device__ int2  g_tw[E_TOT];          // packed (target, weight) per hop

// ---------------- tf32 helpers ----------------
__device__ __forceinline__ uint32_t f2tf(float x)
{
    uint32_t r;
    asm("cvt.rna.tf32.f32 %0, %1;" : "=r"(r) : "f"(x));
    return r;
}

__device__ __forceinline__ void split_tf32(float x, float& hi, float& lo)
{
    uint32_t h = f2tf(x);
    float hf = __uint_as_float(h);
    hi = hf;
    lo = __uint_as_float(f2tf(x - hf));
}

#define MMA_TF32(c, a, b) \
    asm volatile("mma.sync.aligned.m16n8k8.row.col.f32.tf32.tf32.f32 " \
                 "{%0,%1,%2,%3},{%4,%5,%6,%7},{%8,%9},{%0,%1,%2,%3};" \
                 : "+f"((c)[0]), "+f"((c)[1]), "+f"((c)[2]), "+f"((c)[3]) \
                 : "r"(__float_as_uint((a)[0])), "r"(__float_as_uint((a)[1])), \
                   "r"(__float_as_uint((a)[2])), "r"(__float_as_uint((a)[3])), \
                   "r"(__float_as_uint((b)[0])), "r"(__float_as_uint((b)[1])))

// ---------------- fc1: Y = relu(X @ W^T + b) via tf32x3 tensor cores ----------------
__global__ void __launch_bounds__(256) fc1_kernel(
    const float* __restrict__ X, const float* __restrict__ W,
    const float* __restrict__ bias, int N, int F, int nodeBase)
{
    __shared__ float Xhi[128][32];
    __shared__ float Xlo[128][32];
    __shared__ float Whi[64][32];
    __shared__ float Wlo[64][32];

    const int tid  = threadIdx.x;
    const int lane = tid & 31;
    const int warp = tid >> 5;
    const int warp_m = warp & 3;
    const int warp_n = warp >> 2;
    const int bm0 = blockIdx.x * 128;

    float c[2][4][4];
#pragma unroll
    for (int mt = 0; mt < 2; mt++)
#pragma unroll
        for (int nt = 0; nt < 4; nt++)
#pragma unroll
            for (int i = 0; i < 4; i++) c[mt][nt][i] = 0.f;

    const int lr = tid >> 3;
    const int lc = (tid & 7) * 4;

    for (int k0 = 0; k0 < F; k0 += 32) {
#pragma unroll
        for (int i = 0; i < 4; i++) {
            int r = lr + i * 32;
            int row = bm0 + r;
            float4 v = make_float4(0.f, 0.f, 0.f, 0.f);
            if (row < N) v = *(const float4*)&X[(long)row * F + k0 + lc];
            int sc = (lc + 4 * r) & 31;
            float h0, l0, h1, l1, h2, l2, h3, l3;
            split_tf32(v.x, h0, l0); split_tf32(v.y, h1, l1);
            split_tf32(v.z, h2, l2); split_tf32(v.w, h3, l3);
            *(float4*)&Xhi[r][sc] = make_float4(h0, h1, h2, h3);
            *(float4*)&Xlo[r][sc] = make_float4(l0, l1, l2, l3);
        }
#pragma unroll
        for (int i = 0; i < 2; i++) {
            int r = lr + i * 32;
            float4 v = *(const float4*)&W[(long)r * F + k0 + lc];
            int sc = (lc + 4 * r) & 31;
            float h0, l0, h1, l1, h2, l2, h3, l3;
            split_tf32(v.x, h0, l0); split_tf32(v.y, h1, l1);
            split_tf32(v.z, h2, l2); split_tf32(v.w, h3, l3);
            *(float4*)&Whi[r][sc] = make_float4(h0, h1, h2, h3);
            *(float4*)&Wlo[r][sc] = make_float4(l0, l1, l2, l3);
        }
        __syncthreads();

        const int ar = lane >> 2;
        const int ac = lane & 3;
#pragma unroll
        for (int ks = 0; ks < 4; ks++) {
            int kk = ks * 8;
            float ahi[2][4], alo[2][4], bhi[4][2], blo[4][2];
#pragma unroll
            for (int mt = 0; mt < 2; mt++) {
                int r0 = warp_m * 32 + mt * 16 + ar;
                int r1 = r0 + 8;
                int c0a = (kk + ac + 4 * r0) & 31;
                int c1a = (kk + ac + 4 * r1) & 31;
                int c0b = (kk + ac + 4 + 4 * r0) & 31;
                int c1b = (kk + ac + 4 + 4 * r1) & 31;
                ahi[mt][0] = Xhi[r0][c0a]; alo[mt][0] = Xlo[r0][c0a];
                ahi[mt][1] = Xhi[r1][c1a]; alo[mt][1] = Xlo[r1][c1a];
                ahi[mt][2] = Xhi[r0][c0b]; alo[mt][2] = Xlo[r0][c0b];
                ahi[mt][3] = Xhi[r1][c1b]; alo[mt][3] = Xlo[r1][c1b];
            }
#pragma unroll
            for (int nt = 0; nt < 4; nt++) {
                int n = warp_n * 32 + nt * 8 + ar;
                int c0a = (kk + ac + 4 * n) & 31;
                int c0b = (kk + ac + 4 + 4 * n) & 31;
                bhi[nt][0] = Whi[n][c0a]; blo[nt][0] = Wlo[n][c0a];
                bhi[nt][1] = Whi[n][c0b]; blo[nt][1] = Wlo[n][c0b];
            }
#pragma unroll
            for (int mt = 0; mt < 2; mt++)
#pragma unroll
                for (int nt = 0; nt < 4; nt++) {
                    MMA_TF32(c[mt][nt], ahi[mt], bhi[nt]);
                    MMA_TF32(c[mt][nt], ahi[mt], blo[nt]);
                    MMA_TF32(c[mt][nt], alo[mt], bhi[nt]);
                }
        }
        __syncthreads();
    }

#pragma unroll
    for (int mt = 0; mt < 2; mt++) {
#pragma unroll
        for (int nt = 0; nt < 4; nt++) {
            int row = bm0 + warp_m * 32 + mt * 16 + (lane >> 2);
            int col = warp_n * 32 + nt * 8 + (lane & 3) * 2;
            float b0 = __ldg(&bias[col]);
            float b1 = __ldg(&bias[col + 1]);
            if (row < N) {
                float v0 = fmaxf(c[mt][nt][0] + b0, 0.f);
                float v1 = fmaxf(c[mt][nt][1] + b1, 0.f);
                long o = (long)(nodeBase + row) * D + col;
                *(float2*)&g_x[o]  = make_float2(v0, v1);
                *(float2*)&g_hA[o] = make_float2(v0, v1);
            }
            if (row + 8 < N) {
                float v2 = fmaxf(c[mt][nt][2] + b0, 0.f);
                float v3 = fmaxf(c[mt][nt][3] + b1, 0.f);
                long o = (long)(nodeBase + row + 8) * D + col;
                *(float2*)&g_x[o]  = make_float2(v2, v3);
                *(float2*)&g_hA[o] = make_float2(v2, v3);
            }
        }
    }
}

// ---------------- CSR build ----------------
__global__ void zero_rowptr_kernel()
{
    int i = blockIdx.x * blockDim.x + threadIdx.x;
    if (i < RP_TOT) g_rowptr[i] = 0;
}

__global__ void hist_kernel(const int* __restrict__ ei_pa, const int* __restrict__ ei_ap,
                            const int* __restrict__ ei_ps, const int* __restrict__ ei_sp)
{
    int e = blockIdx.x * blockDim.x + threadIdx.x;
    if (e >= E_TOT) return;
    const int* ei; int l, rpb;
    if (e < E_PA)                   { ei = ei_pa; l = e;                      rpb = RP_PA; }
    else if (e < E_PA + E_AP)       { ei = ei_ap; l = e - E_PA;               rpb = RP_AP; }
    else if (e < E_PA + E_AP + E_PS){ ei = ei_ps; l = e - E_PA - E_AP;        rpb = RP_PS; }
    else                            { ei = ei_sp; l = e - E_PA - E_AP - E_PS; rpb = RP_SP; }
    atomicAdd(&g_rowptr[rpb + 1 + ei[l]], 1);
}

__global__ void scan_kernel()
{
    __shared__ int ssum[1024];
    int base, n;
    if (blockIdx.x == 0)      { base = RP_PA; n = NP + 1;  }
    else if (blockIdx.x == 1) { base = RP_AP; n = NA + 1;  }
    else if (blockIdx.x == 2) { base = RP_PS; n = NP + 1;  }
    else                      { base = RP_SP; n = NSU + 1; }
    int tid = threadIdx.x;
    int chunk = (n + 1023) >> 10;
    int s0 = tid * chunk;
    int s1 = s0 + chunk; if (s1 > n) s1 = n; if (s0 > n) s0 = n;

    int sum = 0;
    for (int j = s0; j < s1; j++) sum += g_rowptr[base + j];
    ssum[tid] = sum;
    __syncthreads();
    for (int off = 1; off < 1024; off <<= 1) {
        int v = (tid >= off) ? ssum[tid - off] : 0;
        __syncthreads();
        ssum[tid] += v;
        __syncthreads();
    }
    int run = (tid == 0) ? 0 : ssum[tid - 1];
    for (int j = s0; j < s1; j++) {
        run += g_rowptr[base + j];
        g_rowptr[base + j] = run;
        g_cursor[base + j] = run;
    }
}

__global__ void scatter_kernel(const int* __restrict__ ei_pa, const int* __restrict__ ei_ap,
                               const int* __restrict__ ei_ps, const int* __restrict__ ei_sp)
{
    int e = blockIdx.x * blockDim.x + threadIdx.x;
    if (e >= E_TOT) return;
    const int* ei; int l, rpb, cb, En;
    if (e < E_PA)                   { ei = ei_pa; l = e;                      rpb = RP_PA; cb = CB_PA; En = E_PA; }
    else if (e < E_PA + E_AP)       { ei = ei_ap; l = e - E_PA;               rpb = RP_AP; cb = CB_AP; En = E_AP; }
    else if (e < E_PA + E_AP + E_PS){ ei = ei_ps; l = e - E_PA - E_AP;        rpb = RP_PS; cb = CB_PS; En = E_PS; }
    else                            { ei = ei_sp; l = e - E_PA - E_AP - E_PS; rpb = RP_SP; cb = CB_SP; En = E_SP; }
    int s = ei[l];
    int t = ei[En + l];
    int pos = atomicAdd(&g_cursor[rpb + s], 1);
    g_col[cb + pos] = t;
    g_src[cb + pos] = s;
}

// ---------------- warp reduce ----------------
__device__ __forceinline__ float wsum32(float v)
{
#pragma unroll
    for (int o = 16; o; o >>= 1) v += __shfl_xor_sync(0xffffffffu, v, o);
    return v;
}

// ---------------- one-time: source-side d1 and self weight w2, all hops ----------
// index space: warp per node; paper nodes handle k=0 and k=2, author k=1, subject k=3.
__global__ void d1w2_kernel(const float* __restrict__ attn1, const float* __restrict__ attn2)
{
    int gw = (blockIdx.x * blockDim.x + threadIdx.x) >> 5;
    int lane = threadIdx.x & 31;
    if (gw >= NTOT) return;
    const float* xr = g_x + (long)gw * D;
    float x0 = xr[lane], x1 = xr[lane + 32];

    int k0, k1, base0, base1, l;
    if (gw < NP)            { l = gw;            k0 = 0; base0 = D1_PA; k1 = 2; base1 = D1_PS; }
    else if (gw < NP + NA)  { l = gw - NP;       k0 = 1; base0 = D1_AP; k1 = -1; base1 = 0; }
    else                    { l = gw - NP - NA;  k0 = 3; base0 = D1_SP; k1 = -1; base1 = 0; }

#pragma unroll
    for (int hop = 0; hop < HOPS; hop++) {
        {
            const float* a1 = attn1 + (hop * 4 + k0) * D;
            const float* a2 = attn2 + (hop * 4 + k0) * D;
            float d1 = wsum32(x0 * a1[lane] + x1 * a1[lane + 32]);
            float d2 = wsum32(x0 * a2[lane] + x1 * a2[lane + 32]);
            float z = d1 + d2; z = z > 0.f ? z : 0.2f * z;
            if (lane == 0) {
                g_d1[hop * D1_TOT + base0 + l] = d1;
                g_w2[hop * D1_TOT + base0 + l] = __expf(z);
            }
        }
        if (k1 >= 0) {
            const float* a1 = attn1 + (hop * 4 + k1) * D;
            const float* a2 = attn2 + (hop * 4 + k1) * D;
            float d1 = wsum32(x0 * a1[lane] + x1 * a1[lane + 32]);
            float d2 = wsum32(x0 * a2[lane] + x1 * a2[lane + 32]);
            float z = d1 + d2; z = z > 0.f ? z : 0.2f * z;
            if (lane == 0) {
                g_d1[hop * D1_TOT + base1 + l] = d1;
                g_w2[hop * D1_TOT + base1 + l] = __expf(z);
            }
        }
    }
}

// ---------------- per-hop: target-side attention scores h1 = h . a2 ----------------
__global__ void h1_kernel(const float* __restrict__ attn2, int hop, int curB)
{
    int gw = (blockIdx.x * blockDim.x + threadIdx.x) >> 5;
    int lane = threadIdx.x & 31;
    if (gw >= H1_TOT) return;
    const float* h = curB ? g_hB : g_hA;
    int k, node, outIdx;
    if (gw < NA)                 { k = 0; node = NP + gw;        outIdx = H1_PA + gw; }
    else if (gw < NA + NP)       { int l = gw - NA;       k = 1; node = l;            outIdx = H1_AP + l; }
    else if (gw < NA + NP + NSU) { int l = gw - NA - NP;  k = 2; node = NP + NA + l;  outIdx = H1_PS + l; }
    else                         { int l = gw - NA - NP - NSU; k = 3; node = l;       outIdx = H1_SP + l; }
    const float* a2 = attn2 + (hop * 4 + k) * D;
    const float* hr = h + (long)node * D;
    float v = hr[lane] * a2[lane] + hr[lane + 32] * a2[lane + 32];
#pragma unroll
    for (int o = 16; o; o >>= 1) v += __shfl_xor_sync(0xffffffffu, v, o);
    if (lane == 0) g_h1[outIdx] = v;
}

// ---------------- per-hop: edge weights, fully edge-parallel ----------------
__global__ void edge_w_kernel(int hop)
{
    int e = blockIdx.x * blockDim.x + threadIdx.x;
    if (e >= E_TOT) return;
    int d1b, h1b;
    if (e < CB_AP)      { d1b = D1_PA; h1b = H1_PA; }
    else if (e < CB_PS) { d1b = D1_AP; h1b = H1_AP; }
    else if (e < CB_SP) { d1b = D1_PS; h1b = H1_PS; }
    else                { d1b = D1_SP; h1b = H1_SP; }
    int t = g_col[e];
    int s = g_src[e];
    float z = g_d1[hop * D1_TOT + d1b + s] + g_h1[h1b + t];
    z = z > 0.f ? z : 0.2f * z;
    g_tw[e] = make_int2(t, __float_as_int(__expf(z)));
}

// ---------------- per-hop aggregation: 1-deep chain, unroll x4 ----------------
__device__ __forceinline__ void aggr_et(
    int nodeLocal, int rpBase, int colBase, int d1Base, int tOff, int hop,
    const float* __restrict__ h, int lane,
    float x0, float x1, float wk, float& acc0, float& acc1)
{
    float w2 = g_w2[hop * D1_TOT + d1Base + nodeLocal];
    float num0 = w2 * x0, num1 = w2 * x1, div = w2;
    int e0 = g_rowptr[rpBase + nodeLocal];
    int e1 = g_rowptr[rpBase + nodeLocal + 1];
    const float* hb = h + (long)tOff * D;

    int e = e0;
    for (; e + 4 <= e1; e += 4) {
        int2 p0 = __ldg(&g_tw[colBase + e]);
        int2 p1 = __ldg(&g_tw[colBase + e + 1]);
        int2 p2 = __ldg(&g_tw[colBase + e + 2]);
        int2 p3 = __ldg(&g_tw[colBase + e + 3]);
        const float* r0 = hb + (long)p0.x * D;
        const float* r1 = hb + (long)p1.x * D;
        const float* r2 = hb + (long)p2.x * D;
        const float* r3 = hb + (long)p3.x * D;
        float a00 = r0[lane], a01 = r0[lane + 32];
        float a10 = r1[lane], a11 = r1[lane + 32];
        float a20 = r2[lane], a21 = r2[lane + 32];
        float a30 = r3[lane], a31 = r3[lane + 32];
        float w0 = __int_as_float(p0.y), w1 = __int_as_float(p1.y);
        float w2_ = __int_as_float(p2.y), w3 = __int_as_float(p3.y);
        num0 += w0 * a00 + w1 * a10 + w2_ * a20 + w3 * a30;
        num1 += w0 * a01 + w1 * a11 + w2_ * a21 + w3 * a31;
        div  += (w0 + w1) + (w2_ + w3);
    }
    for (; e < e1; e++) {
        int2 p = __ldg(&g_tw[colBase + e]);
        const float* r = hb + (long)p.x * D;
        float w = __int_as_float(p.y);
        num0 += w * r[lane];
        num1 += w * r[lane + 32];
        div  += w;
    }
    float s = wk / div;
    acc0 += num0 * s;
    acc1 += num1 * s;
}

__global__ void __launch_bounds__(256) aggr_kernel(
    const float* __restrict__ lw, int hop, int curB)
{
    int gw = (blockIdx.x * blockDim.x + threadIdx.x) >> 5;
    int lane = threadIdx.x & 31;
    if (gw >= NTOT) return;
    const float* h  = curB ? g_hB : g_hA;
    float*       hn = curB ? g_hA : g_hB;
    const float* xr = g_x + (long)gw * D;
    float x0 = xr[lane], x1 = xr[lane + 32];
    float acc0 = 0.f, acc1 = 0.f;

    if (gw < NP) {
        float l0 = lw[hop * 4 + 0], l2 = lw[hop * 4 + 2];
        float m = fmaxf(l0, l2);
        float e0 = __expf(l0 - m), e2 = __expf(l2 - m);
        float inv = 1.f / (e0 + e2);
        aggr_et(gw, RP_PA, CB_PA, D1_PA, NP,      hop, h, lane, x0, x1, e0 * inv, acc0, acc1);
        aggr_et(gw, RP_PS, CB_PS, D1_PS, NP + NA, hop, h, lane, x0, x1, e2 * inv, acc0, acc1);
    } else if (gw < NP + NA) {
        aggr_et(gw - NP, RP_AP, CB_AP, D1_AP, 0,  hop, h, lane, x0, x1, 1.f, acc0, acc1);
    } else {
        aggr_et(gw - NP - NA, RP_SP, CB_SP, D1_SP, 0, hop, h, lane, x0, x1, 1.f, acc0, acc1);
    }
    acc0 = acc0 > 0.f ? acc0 : __expf(acc0) - 1.f;
    acc1 = acc1 > 0.f ? acc1 : __expf(acc1) - 1.f;
    hn[(long)gw * D + lane]      = acc0;
    hn[(long)gw * D + lane + 32] = acc1;
}

// ---------------- fc2: out = h_paper @ W^T + b (warp per node, W in smem) -----------
__global__ void __launch_bounds__(256) fc2_kernel(
    const float* __restrict__ W, const float* __restrict__ bias,
    float* __restrict__ out)
{
    __shared__ float Ws[NOUT * D];
    __shared__ float bs[NOUT];
    int tid = threadIdx.x;
    for (int i = tid; i < NOUT * D; i += 256) Ws[i] = W[i];
    if (tid < NOUT) bs[tid] = bias[tid];
    __syncthreads();

    int gw = (blockIdx.x * 256 + tid) >> 5;
    int lane = tid & 31;
    if (gw >= NP) return;
    const float* hr = g_hB + (long)gw * D;   // HOPS=5 -> final h in buffer B
    float v0 = hr[lane], v1 = hr[lane + 32];
    float res = 0.f;
#pragma unroll
    for (int o = 0; o < NOUT; o++) {
        float s = v0 * Ws[o * D + lane] + v1 * Ws[o * D + lane + 32];
        s = wsum32(s);
        if (lane == o) res = s;
    }
    if (lane < NOUT) out[gw * NOUT + lane] = res + bs[lane];
}

// ---------------- launch ----------------
extern "C" void kernel_launch(void* const* d_in, const int* in_sizes, int n_in,
                              void* d_out, int out_size)
{
    const float* x_paper   = (const float*)d_in[0];
    const float* x_author  = (const float*)d_in[1];
    const float* x_subject = (const float*)d_in[2];
    const float* fc1p_w = (const float*)d_in[3];
    const float* fc1p_b = (const float*)d_in[4];
    const float* fc1a_w = (const float*)d_in[5];
    const float* fc1a_b = (const float*)d_in[6];
    const float* fc1s_w = (const float*)d_in[7];
    const float* fc1s_b = (const float*)d_in[8];
    const float* attn1  = (const float*)d_in[9];
    const float* attn2  = (const float*)d_in[10];
    const float* lw     = (const float*)d_in[11];
    const float* fc2_w  = (const float*)d_in[12];
    const float* fc2_b  = (const float*)d_in[13];
    const int* ei_pa = (const int*)d_in[14];
    const int* ei_ap = (const int*)d_in[15];
    const int* ei_ps = (const int*)d_in[16];
    const int* ei_sp = (const int*)d_in[17];
    float* out = (float*)d_out;

    zero_rowptr_kernel<<<(RP_TOT + 255) / 256, 256>>>();

    fc1_kernel<<<(NP  + 127) / 128, 256>>>(x_paper,   fc1p_w, fc1p_b, NP,  512, 0);
    fc1_kernel<<<(NA  + 127) / 128, 256>>>(x_author,  fc1a_w, fc1a_b, NA,  256, NP);
    fc1_kernel<<<(NSU + 127) / 128, 256>>>(x_subject, fc1s_w, fc1s_b, NSU, 128, NP + NA);

    hist_kernel<<<(E_TOT + 255) / 256, 256>>>(ei_pa, ei_ap, ei_ps, ei_sp);
    scan_kernel<<<4, 1024>>>();
    scatter_kernel<<<(E_TOT + 255) / 256, 256>>>(ei_pa, ei_ap, ei_ps, ei_sp);

    d1w2_kernel<<<(NTOT * 32 + 255) / 256, 256>>>(attn1, attn2);

    for (int hop = 0; hop < HOPS; hop++) {
        int curB = hop & 1;
        h1_kernel    <<<(H1_TOT * 32 + 255) / 256, 256>>>(attn2, hop, curB);
        edge_w_kernel<<<(E_TOT + 255) / 256, 256>>>(hop);
        aggr_kernel  <<<(NTOT * 32 + 255) / 256, 256>>>(lw, hop, curB);
    }

    fc2_kernel<<<(NP * 32 + 255) / 256, 256>>>(fc2_w, fc2_b, out);
}

// round 7
// speedup vs baseline: 1.0094x; 1.0094x over previous
#include <cuda_runtime.h>
#include <cstdint>

// ---------------- problem constants ----------------
#define NP   100000
#define NA   200000
#define NSU  1000
#define NTOT (NP + NA + NSU)          // 301000
#define D    64
#define HOPS 5
#define NOUT 16

#define E_PA 800000
#define E_AP 800000
#define E_PS 100000
#define E_SP 100000
#define E_TOT (E_PA + E_AP + E_PS + E_SP)   // 1800000

// row_ptr segment bases (each segment length = Ns+1)
#define RP_PA 0
#define RP_AP (NP + 1)
#define RP_PS (RP_AP + NA + 1)
#define RP_SP (RP_PS + NP + 1)
#define RP_TOT (RP_SP + NSU + 1)

// col array bases
#define CB_PA 0
#define CB_AP E_PA
#define CB_PS (E_PA + E_AP)
#define CB_SP (E_PA + E_AP + E_PS)

// h1 (target-side attention score) bases
#define H1_PA 0                        // len NA  (targets: author)
#define H1_AP NA                       // len NP  (targets: paper)
#define H1_PS (NA + NP)                // len NSU (targets: subject)
#define H1_SP (NA + NP + NSU)          // len NP  (targets: paper)
#define H1_TOT (NA + NP + NSU + NP)    // 401000

// d1/w2 (source-side) segment bases, ordered [pa, ap, ps, sp]
#define D1_PA 0                        // len NP
#define D1_AP NP                       // len NA
#define D1_PS (NP + NA)                // len NP
#define D1_SP (NP + NA + NP)           // len NSU
#define D1_TOT (NP + NA + NP + NSU)    // 401000

// ---------------- scratch (static device memory; no runtime alloc) ----------------
__device__ float g_x [NTOT * D];
__device__ float g_hA[NTOT * D];
__device__ float g_hB[NTOT * D];
__device__ float g_h1[H1_TOT];
__device__ float g_d1[HOPS * D1_TOT];
__device__ float g_w2[HOPS * D1_TOT];
__device__ int   g_rowptr[RP_TOT];
__device__ int   g_cursor[RP_TOT];
__device__ int   g_col[E_TOT];

// ---------------- L2 eviction-priority helpers ----------------
__device__ __forceinline__ uint64_t mkpol_evict_last()
{
    uint64_t p;
    asm("createpolicy.fractional.L2::evict_last.b64 %0;" : "=l"(p));
    return p;
}

__device__ __forceinline__ float ldg_keep(const float* p, uint64_t pol)
{
    float v;
    asm("ld.global.nc.L2::cache_hint.f32 %0, [%1], %2;" : "=f"(v) : "l"(p), "l"(pol));
    return v;
}

// ---------------- tf32 helpers ----------------
__device__ __forceinline__ uint32_t f2tf(float x)
{
    uint32_t r;
    asm("cvt.rna.tf32.f32 %0, %1;" : "=r"(r) : "f"(x));
    return r;
}

__device__ __forceinline__ void split_tf32(float x, float& hi, float& lo)
{
    uint32_t h = f2tf(x);
    float hf = __uint_as_float(h);
    hi = hf;
    lo = __uint_as_float(f2tf(x - hf));
}

#define MMA_TF32(c, a, b) \
    asm volatile("mma.sync.aligned.m16n8k8.row.col.f32.tf32.tf32.f32 " \
                 "{%0,%1,%2,%3},{%4,%5,%6,%7},{%8,%9},{%0,%1,%2,%3};" \
                 : "+f"((c)[0]), "+f"((c)[1]), "+f"((c)[2]), "+f"((c)[3]) \
                 : "r"(__float_as_uint((a)[0])), "r"(__float_as_uint((a)[1])), \
                   "r"(__float_as_uint((a)[2])), "r"(__float_as_uint((a)[3])), \
                   "r"(__float_as_uint((b)[0])), "r"(__float_as_uint((b)[1])))

// ---------------- fc1: Y = relu(X @ W^T + b) via tf32x3 tensor cores ----------------
__global__ void __launch_bounds__(256) fc1_kernel(
    const float* __restrict__ X, const float* __restrict__ W,
    const float* __restrict__ bias, int N, int F, int nodeBase)
{
    __shared__ float Xhi[128][32];
    __shared__ float Xlo[128][32];
    __shared__ float Whi[64][32];
    __shared__ float Wlo[64][32];

    const int tid  = threadIdx.x;
    const int lane = tid & 31;
    const int warp = tid >> 5;
    const int warp_m = warp & 3;
    const int warp_n = warp >> 2;
    const int bm0 = blockIdx.x * 128;

    float c[2][4][4];
#pragma unroll
    for (int mt = 0; mt < 2; mt++)
#pragma unroll
        for (int nt = 0; nt < 4; nt++)
#pragma unroll
            for (int i = 0; i < 4; i++) c[mt][nt][i] = 0.f;

    const int lr = tid >> 3;
    const int lc = (tid & 7) * 4;

    for (int k0 = 0; k0 < F; k0 += 32) {
#pragma unroll
        for (int i = 0; i < 4; i++) {
            int r = lr + i * 32;
            int row = bm0 + r;
            float4 v = make_float4(0.f, 0.f, 0.f, 0.f);
            if (row < N) v = *(const float4*)&X[(long)row * F + k0 + lc];
            int sc = (lc + 4 * r) & 31;
            float h0, l0, h1, l1, h2, l2, h3, l3;
            split_tf32(v.x, h0, l0); split_tf32(v.y, h1, l1);
            split_tf32(v.z, h2, l2); split_tf32(v.w, h3, l3);
            *(float4*)&Xhi[r][sc] = make_float4(h0, h1, h2, h3);
            *(float4*)&Xlo[r][sc] = make_float4(l0, l1, l2, l3);
        }
#pragma unroll
        for (int i = 0; i < 2; i++) {
            int r = lr + i * 32;
            float4 v = *(const float4*)&W[(long)r * F + k0 + lc];
            int sc = (lc + 4 * r) & 31;
            float h0, l0, h1, l1, h2, l2, h3, l3;
            split_tf32(v.x, h0, l0); split_tf32(v.y, h1, l1);
            split_tf32(v.z, h2, l2); split_tf32(v.w, h3, l3);
            *(float4*)&Whi[r][sc] = make_float4(h0, h1, h2, h3);
            *(float4*)&Wlo[r][sc] = make_float4(l0, l1, l2, l3);
        }
        __syncthreads();

        const int ar = lane >> 2;
        const int ac = lane & 3;
#pragma unroll
        for (int ks = 0; ks < 4; ks++) {
            int kk = ks * 8;
            float ahi[2][4], alo[2][4], bhi[4][2], blo[4][2];
#pragma unroll
            for (int mt = 0; mt < 2; mt++) {
                int r0 = warp_m * 32 + mt * 16 + ar;
                int r1 = r0 + 8;
                int c0a = (kk + ac + 4 * r0) & 31;
                int c1a = (kk + ac + 4 * r1) & 31;
                int c0b = (kk + ac + 4 + 4 * r0) & 31;
                int c1b = (kk + ac + 4 + 4 * r1) & 31;
                ahi[mt][0] = Xhi[r0][c0a]; alo[mt][0] = Xlo[r0][c0a];
                ahi[mt][1] = Xhi[r1][c1a]; alo[mt][1] = Xlo[r1][c1a];
                ahi[mt][2] = Xhi[r0][c0b]; alo[mt][2] = Xlo[r0][c0b];
                ahi[mt][3] = Xhi[r1][c1b]; alo[mt][3] = Xlo[r1][c1b];
            }
#pragma unroll
            for (int nt = 0; nt < 4; nt++) {
                int n = warp_n * 32 + nt * 8 + ar;
                int c0a = (kk + ac + 4 * n) & 31;
                int c0b = (kk + ac + 4 + 4 * n) & 31;
                bhi[nt][0] = Whi[n][c0a]; blo[nt][0] = Wlo[n][c0a];
                bhi[nt][1] = Whi[n][c0b]; blo[nt][1] = Wlo[n][c0b];
            }
#pragma unroll
            for (int mt = 0; mt < 2; mt++)
#pragma unroll
                for (int nt = 0; nt < 4; nt++) {
                    MMA_TF32(c[mt][nt], ahi[mt], bhi[nt]);
                    MMA_TF32(c[mt][nt], ahi[mt], blo[nt]);
                    MMA_TF32(c[mt][nt], alo[mt], bhi[nt]);
                }
        }
        __syncthreads();
    }

#pragma unroll
    for (int mt = 0; mt < 2; mt++) {
#pragma unroll
        for (int nt = 0; nt < 4; nt++) {
            int row = bm0 + warp_m * 32 + mt * 16 + (lane >> 2);
            int col = warp_n * 32 + nt * 8 + (lane & 3) * 2;
            float b0 = __ldg(&bias[col]);
            float b1 = __ldg(&bias[col + 1]);
            if (row < N) {
                float v0 = fmaxf(c[mt][nt][0] + b0, 0.f);
                float v1 = fmaxf(c[mt][nt][1] + b1, 0.f);
                long o = (long)(nodeBase + row) * D + col;
                *(float2*)&g_x[o]  = make_float2(v0, v1);
                *(float2*)&g_hA[o] = make_float2(v0, v1);
            }
            if (row + 8 < N) {
                float v2 = fmaxf(c[mt][nt][2] + b0, 0.f);
                float v3 = fmaxf(c[mt][nt][3] + b1, 0.f);
                long o = (long)(nodeBase + row + 8) * D + col;
                *(float2*)&g_x[o]  = make_float2(v2, v3);
                *(float2*)&g_hA[o] = make_float2(v2, v3);
            }
        }
    }
}

// ---------------- CSR build ----------------
__global__ void zero_rowptr_kernel()
{
    int i = blockIdx.x * blockDim.x + threadIdx.x;
    if (i < RP_TOT) g_rowptr[i] = 0;
}

__global__ void hist_kernel(const int* __restrict__ ei_pa, const int* __restrict__ ei_ap,
                            const int* __restrict__ ei_ps, const int* __restrict__ ei_sp)
{
    int e = blockIdx.x * blockDim.x + threadIdx.x;
    if (e >= E_TOT) return;
    const int* ei; int l, rpb;
    if (e < E_PA)                   { ei = ei_pa; l = e;                      rpb = RP_PA; }
    else if (e < E_PA + E_AP)       { ei = ei_ap; l = e - E_PA;               rpb = RP_AP; }
    else if (e < E_PA + E_AP + E_PS){ ei = ei_ps; l = e - E_PA - E_AP;        rpb = RP_PS; }
    else                            { ei = ei_sp; l = e - E_PA - E_AP - E_PS; rpb = RP_SP; }
    atomicAdd(&g_rowptr[rpb + 1 + ei[l]], 1);
}

__global__ void scan_kernel()
{
    __shared__ int ssum[1024];
    int base, n;
    if (blockIdx.x == 0)      { base = RP_PA; n = NP + 1;  }
    else if (blockIdx.x == 1) { base = RP_AP; n = NA + 1;  }
    else if (blockIdx.x == 2) { base = RP_PS; n = NP + 1;  }
    else                      { base = RP_SP; n = NSU + 1; }
    int tid = threadIdx.x;
    int chunk = (n + 1023) >> 10;
    int s0 = tid * chunk;
    int s1 = s0 + chunk; if (s1 > n) s1 = n; if (s0 > n) s0 = n;

    int sum = 0;
    for (int j = s0; j < s1; j++) sum += g_rowptr[base + j];
    ssum[tid] = sum;
    __syncthreads();
    for (int off = 1; off < 1024; off <<= 1) {
        int v = (tid >= off) ? ssum[tid - off] : 0;
        __syncthreads();
        ssum[tid] += v;
        __syncthreads();
    }
    int run = (tid == 0) ? 0 : ssum[tid - 1];
    for (int j = s0; j < s1; j++) {
        run += g_rowptr[base + j];
        g_rowptr[base + j] = run;
        g_cursor[base + j] = run;
    }
}

__global__ void scatter_kernel(const int* __restrict__ ei_pa, const int* __restrict__ ei_ap,
                               const int* __restrict__ ei_ps, const int* __restrict__ ei_sp)
{
    int e = blockIdx.x * blockDim.x + threadIdx.x;
    if (e >= E_TOT) return;
    const int* ei; int l, rpb, cb, En;
    if (e < E_PA)                   { ei = ei_pa; l = e;                      rpb = RP_PA; cb = CB_PA; En = E_PA; }
    else if (e < E_PA + E_AP)       { ei = ei_ap; l = e - E_PA;               rpb = RP_AP; cb = CB_AP; En = E_AP; }
    else if (e < E_PA + E_AP + E_PS){ ei = ei_ps; l = e - E_PA - E_AP;        rpb = RP_PS; cb = CB_PS; En = E_PS; }
    else                            { ei = ei_sp; l = e - E_PA - E_AP - E_PS; rpb = RP_SP; cb = CB_SP; En = E_SP; }
    int s = ei[l];
    int t = ei[En + l];
    int pos = atomicAdd(&g_cursor[rpb + s], 1);
    g_col[cb + pos] = t;
}

// ---------------- warp reduce ----------------
__device__ __forceinline__ float wsum32(float v)
{
#pragma unroll
    for (int o = 16; o; o >>= 1) v += __shfl_xor_sync(0xffffffffu, v, o);
    return v;
}

// ---------------- one-time: source-side d1 and self weight w2, all hops ----------
__global__ void d1w2_kernel(const float* __restrict__ attn1, const float* __restrict__ attn2)
{
    int gw = (blockIdx.x * blockDim.x + threadIdx.x) >> 5;
    int lane = threadIdx.x & 31;
    if (gw >= NTOT) return;
    const float* xr = g_x + (long)gw * D;
    float x0 = __ldcs(&xr[lane]), x1 = __ldcs(&xr[lane + 32]);

    int k0, k1, base0, base1, l;
    if (gw < NP)            { l = gw;            k0 = 0; base0 = D1_PA; k1 = 2; base1 = D1_PS; }
    else if (gw < NP + NA)  { l = gw - NP;       k0 = 1; base0 = D1_AP; k1 = -1; base1 = 0; }
    else                    { l = gw - NP - NA;  k0 = 3; base0 = D1_SP; k1 = -1; base1 = 0; }

#pragma unroll
    for (int hop = 0; hop < HOPS; hop++) {
        {
            const float* a1 = attn1 + (hop * 4 + k0) * D;
            const float* a2 = attn2 + (hop * 4 + k0) * D;
            float d1 = wsum32(x0 * a1[lane] + x1 * a1[lane + 32]);
            float d2 = wsum32(x0 * a2[lane] + x1 * a2[lane + 32]);
            float z = d1 + d2; z = z > 0.f ? z : 0.2f * z;
            if (lane == 0) {
                g_d1[hop * D1_TOT + base0 + l] = d1;
                g_w2[hop * D1_TOT + base0 + l] = __expf(z);
            }
        }
        if (k1 >= 0) {
            const float* a1 = attn1 + (hop * 4 + k1) * D;
            const float* a2 = attn2 + (hop * 4 + k1) * D;
            float d1 = wsum32(x0 * a1[lane] + x1 * a1[lane + 32]);
            float d2 = wsum32(x0 * a2[lane] + x1 * a2[lane + 32]);
            float z = d1 + d2; z = z > 0.f ? z : 0.2f * z;
            if (lane == 0) {
                g_d1[hop * D1_TOT + base1 + l] = d1;
                g_w2[hop * D1_TOT + base1 + l] = __expf(z);
            }
        }
    }
}

// ---------------- per-hop: target-side scores h1 = h . a2 (warms L2 with h!) --------
__global__ void h1_kernel(const float* __restrict__ attn2, int hop, int curB)
{
    int gw = (blockIdx.x * blockDim.x + threadIdx.x) >> 5;
    int lane = threadIdx.x & 31;
    if (gw >= H1_TOT) return;
    uint64_t pol = mkpol_evict_last();
    const float* h = curB ? g_hB : g_hA;
    int k, node, outIdx;
    if (gw < NA)                 { k = 0; node = NP + gw;        outIdx = H1_PA + gw; }
    else if (gw < NA + NP)       { int l = gw - NA;       k = 1; node = l;            outIdx = H1_AP + l; }
    else if (gw < NA + NP + NSU) { int l = gw - NA - NP;  k = 2; node = NP + NA + l;  outIdx = H1_PS + l; }
    else                         { int l = gw - NA - NP - NSU; k = 3; node = l;       outIdx = H1_SP + l; }
    const float* a2 = attn2 + (hop * 4 + k) * D;
    const float* hr = h + (long)node * D;
    float v = ldg_keep(&hr[lane], pol) * a2[lane] + ldg_keep(&hr[lane + 32], pol) * a2[lane + 32];
#pragma unroll
    for (int o = 16; o; o >>= 1) v += __shfl_xor_sync(0xffffffffu, v, o);
    if (lane == 0) g_h1[outIdx] = v;
}

// ---------------- per-hop aggregation: pipelined quads, L2-resident gathers ---------
__device__ __forceinline__ void aggr_et(
    int nodeLocal, int rpBase, int colBase, int d1Base, int h1Base, int tOff, int hop,
    const float* __restrict__ h, int lane, uint64_t pol,
    float x0, float x1, float wk, float& acc0, float& acc1)
{
    float d1 = g_d1[hop * D1_TOT + d1Base + nodeLocal];
    float w2 = g_w2[hop * D1_TOT + d1Base + nodeLocal];
    float num0 = w2 * x0, num1 = w2 * x1, div = w2;
    int e0 = g_rowptr[rpBase + nodeLocal];
    int e1 = g_rowptr[rpBase + nodeLocal + 1];
    const float* hb  = h + (long)tOff * D;
    const float* h1b = g_h1 + h1Base;

    // prefetch first quad of column indices (linear addresses, independent)
    int t0 = 0, t1 = 0, t2 = 0, t3 = 0;
    if (e0     < e1) t0 = __ldcs(&g_col[colBase + e0]);
    if (e0 + 1 < e1) t1 = __ldcs(&g_col[colBase + e0 + 1]);
    if (e0 + 2 < e1) t2 = __ldcs(&g_col[colBase + e0 + 2]);
    if (e0 + 3 < e1) t3 = __ldcs(&g_col[colBase + e0 + 3]);

    for (int e = e0; e < e1; e += 4) {
        int c0 = t0, c1 = t1, c2 = t2, c3 = t3;
        // prefetch next quad before dependent loads of this quad
        int en = e + 4;
        t0 = t1 = t2 = t3 = 0;
        if (en     < e1) t0 = __ldcs(&g_col[colBase + en]);
        if (en + 1 < e1) t1 = __ldcs(&g_col[colBase + en + 1]);
        if (en + 2 < e1) t2 = __ldcs(&g_col[colBase + en + 2]);
        if (en + 3 < e1) t3 = __ldcs(&g_col[colBase + en + 3]);

        // dependent loads: h1 scalars + h rows (all 12 independent, L2-resident)
        float p0 = ldg_keep(h1b + c0, pol);
        float p1 = ldg_keep(h1b + c1, pol);
        float p2 = ldg_keep(h1b + c2, pol);
        float p3 = ldg_keep(h1b + c3, pol);
        const float* r0 = hb + (long)c0 * D;
        const float* r1 = hb + (long)c1 * D;
        const float* r2 = hb + (long)c2 * D;
        const float* r3 = hb + (long)c3 * D;
        float a00 = ldg_keep(r0 + lane, pol), a01 = ldg_keep(r0 + lane + 32, pol);
        float a10 = ldg_keep(r1 + lane, pol), a11 = ldg_keep(r1 + lane + 32, pol);
        float a20 = ldg_keep(r2 + lane, pol), a21 = ldg_keep(r2 + lane + 32, pol);
        float a30 = ldg_keep(r3 + lane, pol), a31 = ldg_keep(r3 + lane + 32, pol);

        // masked weights (only j=0 guaranteed in-range)
        float m1 = (e + 1 < e1) ? 1.f : 0.f;
        float m2 = (e + 2 < e1) ? 1.f : 0.f;
        float m3 = (e + 3 < e1) ? 1.f : 0.f;
        float z0 = d1 + p0; z0 = z0 > 0.f ? z0 : 0.2f * z0;
        float z1 = d1 + p1; z1 = z1 > 0.f ? z1 : 0.2f * z1;
        float z2 = d1 + p2; z2 = z2 > 0.f ? z2 : 0.2f * z2;
        float z3 = d1 + p3; z3 = z3 > 0.f ? z3 : 0.2f * z3;
        float w0 = __expf(z0);
        float w1 = m1 * __expf(z1);
        float w2_ = m2 * __expf(z2);
        float w3 = m3 * __expf(z3);

        num0 += w0 * a00 + w1 * a10 + w2_ * a20 + w3 * a30;
        num1 += w0 * a01 + w1 * a11 + w2_ * a21 + w3 * a31;
        div  += (w0 + w1) + (w2_ + w3);
    }
    float s = wk / div;
    acc0 += num0 * s;
    acc1 += num1 * s;
}

__global__ void __launch_bounds__(256) aggr_kernel(
    const float* __restrict__ lw, int hop, int curB)
{
    int gw = (blockIdx.x * blockDim.x + threadIdx.x) >> 5;
    int lane = threadIdx.x & 31;
    if (gw >= NTOT) return;
    uint64_t pol = mkpol_evict_last();
    const float* h  = curB ? g_hB : g_hA;
    float*       hn = curB ? g_hA : g_hB;
    const float* xr = g_x + (long)gw * D;
    float x0 = __ldcs(&xr[lane]), x1 = __ldcs(&xr[lane + 32]);
    float acc0 = 0.f, acc1 = 0.f;

    if (gw < NP) {
        float l0 = lw[hop * 4 + 0], l2 = lw[hop * 4 + 2];
        float m = fmaxf(l0, l2);
        float e0 = __expf(l0 - m), e2 = __expf(l2 - m);
        float inv = 1.f / (e0 + e2);
        aggr_et(gw, RP_PA, CB_PA, D1_PA, H1_PA, NP,      hop, h, lane, pol, x0, x1, e0 * inv, acc0, acc1);
        aggr_et(gw, RP_PS, CB_PS, D1_PS, H1_PS, NP + NA, hop, h, lane, pol, x0, x1, e2 * inv, acc0, acc1);
    } else if (gw < NP + NA) {
        aggr_et(gw - NP, RP_AP, CB_AP, D1_AP, H1_AP, 0,  hop, h, lane, pol, x0, x1, 1.f, acc0, acc1);
    } else {
        aggr_et(gw - NP - NA, RP_SP, CB_SP, D1_SP, H1_SP, 0, hop, h, lane, pol, x0, x1, 1.f, acc0, acc1);
    }
    acc0 = acc0 > 0.f ? acc0 : __expf(acc0) - 1.f;
    acc1 = acc1 > 0.f ? acc1 : __expf(acc1) - 1.f;
    hn[(long)gw * D + lane]      = acc0;
    hn[(long)gw * D + lane + 32] = acc1;
}

// ---------------- fc2: out = h_paper @ W^T + b (warp per node, W in smem) -----------
__global__ void __launch_bounds__(256) fc2_kernel(
    const float* __restrict__ W, const float* __restrict__ bias,
    float* __restrict__ out)
{
    __shared__ float Ws[NOUT * D];
    __shared__ float bs[NOUT];
    int tid = threadIdx.x;
    for (int i = tid; i < NOUT * D; i += 256) Ws[i] = W[i];
    if (tid < NOUT) bs[tid] = bias[tid];
    __syncthreads();

    int gw = (blockIdx.x * 256 + tid) >> 5;
    int lane = tid & 31;
    if (gw >= NP) return;
    const float* hr = g_hB + (long)gw * D;   // HOPS=5 -> final h in buffer B
    float v0 = hr[lane], v1 = hr[lane + 32];
    float res = 0.f;
#pragma unroll
    for (int o = 0; o < NOUT; o++) {
        float s = v0 * Ws[o * D + lane] + v1 * Ws[o * D + lane + 32];
        s = wsum32(s);
        if (lane == o) res = s;
    }
    if (lane < NOUT) out[gw * NOUT + lane] = res + bs[lane];
}

// ---------------- launch ----------------
extern "C" void kernel_launch(void* const* d_in, const int* in_sizes, int n_in,
                              void* d_out, int out_size)
{
    const float* x_paper   = (const float*)d_in[0];
    const float* x_author  = (const float*)d_in[1];
    const float* x_subject = (const float*)d_in[2];
    const float* fc1p_w = (const float*)d_in[3];
    const float* fc1p_b = (const float*)d_in[4];
    const float* fc1a_w = (const float*)d_in[5];
    const float* fc1a_b = (const float*)d_in[6];
    const float* fc1s_w = (const float*)d_in[7];
    const float* fc1s_b = (const float*)d_in[8];
    const float* attn1  = (const float*)d_in[9];
    const float* attn2  = (const float*)d_in[10];
    const float* lw     = (const float*)d_in[11];
    const float* fc2_w  = (const float*)d_in[12];
    const float* fc2_b  = (const float*)d_in[13];
    const int* ei_pa = (const int*)d_in[14];
    const int* ei_ap = (const int*)d_in[15];
    const int* ei_ps = (const int*)d_in[16];
    const int* ei_sp = (const int*)d_in[17];
    float* out = (float*)d_out;

    zero_rowptr_kernel<<<(RP_TOT + 255) / 256, 256>>>();

    fc1_kernel<<<(NP  + 127) / 128, 256>>>(x_paper,   fc1p_w, fc1p_b, NP,  512, 0);
    fc1_kernel<<<(NA  + 127) / 128, 256>>>(x_author,  fc1a_w, fc1a_b, NA,  256, NP);
    fc1_kernel<<<(NSU + 127) / 128, 256>>>(x_subject, fc1s_w, fc1s_b, NSU, 128, NP + NA);

    hist_kernel<<<(E_TOT + 255) / 256, 256>>>(ei_pa, ei_ap, ei_ps, ei_sp);
    scan_kernel<<<4, 1024>>>();
    scatter_kernel<<<(E_TOT + 255) / 256, 256>>>(ei_pa, ei_ap, ei_ps, ei_sp);

    d1w2_kernel<<<(NTOT * 32 + 255) / 256, 256>>>(attn1, attn2);

    for (int hop = 0; hop < HOPS; hop++) {
        int curB = hop & 1;
        h1_kernel  <<<(H1_TOT * 32 + 255) / 256, 256>>>(attn2, hop, curB);
        aggr_kernel<<<(NTOT * 32 + 255) / 256, 256>>>(lw, hop, curB);
    }

    fc2_kernel<<<(NP * 32 + 255) / 256, 256>>>(fc2_w, fc2_b, out);
}

// round 8
// speedup vs baseline: 1.1727x; 1.1618x over previous
#include <cuda_runtime.h>
#include <cstdint>

// ---------------- problem constants ----------------
#define NP   100000
#define NA   200000
#define NSU  1000
#define NTOT (NP + NA + NSU)          // 301000
#define D    64
#define HOPS 5
#define NOUT 16

#define E_PA 800000
#define E_AP 800000
#define E_PS 100000
#define E_SP 100000
#define E_TOT (E_PA + E_AP + E_PS + E_SP)   // 1800000

// row_ptr segment bases (each segment length = Ns+1)
#define RP_PA 0
#define RP_AP (NP + 1)
#define RP_PS (RP_AP + NA + 1)
#define RP_SP (RP_PS + NP + 1)
#define RP_TOT (RP_SP + NSU + 1)

// col array bases
#define CB_PA 0
#define CB_AP E_PA
#define CB_PS (E_PA + E_AP)
#define CB_SP (E_PA + E_AP + E_PS)

// h1 (target-side attention score) bases
#define H1_PA 0                        // len NA  (targets: author)
#define H1_AP NA                       // len NP  (targets: paper)
#define H1_PS (NA + NP)                // len NSU (targets: subject)
#define H1_SP (NA + NP + NSU)          // len NP  (targets: paper)
#define H1_TOT (NA + NP + NSU + NP)    // 401000

// d1/w2 (source-side) segment bases, ordered [pa, ap, ps, sp]
#define D1_PA 0                        // len NP
#define D1_AP NP                       // len NA
#define D1_PS (NP + NA)                // len NP
#define D1_SP (NP + NA + NP)           // len NSU
#define D1_TOT (NP + NA + NP + NSU)    // 401000

// ---------------- scratch (static device memory; no runtime alloc) ----------------
__device__ float g_x  [NTOT * D];
__device__ float g_hA [NTOT * D];
__device__ float g_hB [NTOT * D];
__device__ float g_h1A[H1_TOT];        // h1 double buffer (hop parity)
__device__ float g_h1B[H1_TOT];
__device__ float g_d1 [HOPS * D1_TOT];
__device__ float g_w2 [HOPS * D1_TOT];
__device__ int   g_rowptr[RP_TOT];
__device__ int   g_cursor[RP_TOT];
__device__ int   g_col[E_TOT];

// ---------------- tf32 helpers ----------------
__device__ __forceinline__ uint32_t f2tf(float x)
{
    uint32_t r;
    asm("cvt.rna.tf32.f32 %0, %1;" : "=r"(r) : "f"(x));
    return r;
}

__device__ __forceinline__ void split_tf32(float x, float& hi, float& lo)
{
    uint32_t h = f2tf(x);
    float hf = __uint_as_float(h);
    hi = hf;
    lo = __uint_as_float(f2tf(x - hf));
}

#define MMA_TF32(c, a, b) \
    asm volatile("mma.sync.aligned.m16n8k8.row.col.f32.tf32.tf32.f32 " \
                 "{%0,%1,%2,%3},{%4,%5,%6,%7},{%8,%9},{%0,%1,%2,%3};" \
                 : "+f"((c)[0]), "+f"((c)[1]), "+f"((c)[2]), "+f"((c)[3]) \
                 : "r"(__float_as_uint((a)[0])), "r"(__float_as_uint((a)[1])), \
                   "r"(__float_as_uint((a)[2])), "r"(__float_as_uint((a)[3])), \
                   "r"(__float_as_uint((b)[0])), "r"(__float_as_uint((b)[1])))

// ---------------- fc1: Y = relu(X @ W^T + b) via tf32x3 tensor cores ----------------
__global__ void __launch_bounds__(256) fc1_kernel(
    const float* __restrict__ X, const float* __restrict__ W,
    const float* __restrict__ bias, int N, int F, int nodeBase)
{
    __shared__ float Xhi[128][32];
    __shared__ float Xlo[128][32];
    __shared__ float Whi[64][32];
    __shared__ float Wlo[64][32];

    const int tid  = threadIdx.x;
    const int lane = tid & 31;
    const int warp = tid >> 5;
    const int warp_m = warp & 3;
    const int warp_n = warp >> 2;
    const int bm0 = blockIdx.x * 128;

    float c[2][4][4];
#pragma unroll
    for (int mt = 0; mt < 2; mt++)
#pragma unroll
        for (int nt = 0; nt < 4; nt++)
#pragma unroll
            for (int i = 0; i < 4; i++) c[mt][nt][i] = 0.f;

    const int lr = tid >> 3;
    const int lc = (tid & 7) * 4;

    for (int k0 = 0; k0 < F; k0 += 32) {
#pragma unroll
        for (int i = 0; i < 4; i++) {
            int r = lr + i * 32;
            int row = bm0 + r;
            float4 v = make_float4(0.f, 0.f, 0.f, 0.f);
            if (row < N) v = *(const float4*)&X[(long)row * F + k0 + lc];
            int sc = (lc + 4 * r) & 31;
            float h0, l0, h1, l1, h2, l2, h3, l3;
            split_tf32(v.x, h0, l0); split_tf32(v.y, h1, l1);
            split_tf32(v.z, h2, l2); split_tf32(v.w, h3, l3);
            *(float4*)&Xhi[r][sc] = make_float4(h0, h1, h2, h3);
            *(float4*)&Xlo[r][sc] = make_float4(l0, l1, l2, l3);
        }
#pragma unroll
        for (int i = 0; i < 2; i++) {
            int r = lr + i * 32;
            float4 v = *(const float4*)&W[(long)r * F + k0 + lc];
            int sc = (lc + 4 * r) & 31;
            float h0, l0, h1, l1, h2, l2, h3, l3;
            split_tf32(v.x, h0, l0); split_tf32(v.y, h1, l1);
            split_tf32(v.z, h2, l2); split_tf32(v.w, h3, l3);
            *(float4*)&Whi[r][sc] = make_float4(h0, h1, h2, h3);
            *(float4*)&Wlo[r][sc] = make_float4(l0, l1, l2, l3);
        }
        __syncthreads();

        const int ar = lane >> 2;
        const int ac = lane & 3;
#pragma unroll
        for (int ks = 0; ks < 4; ks++) {
            int kk = ks * 8;
            float ahi[2][4], alo[2][4], bhi[4][2], blo[4][2];
#pragma unroll
            for (int mt = 0; mt < 2; mt++) {
                int r0 = warp_m * 32 + mt * 16 + ar;
                int r1 = r0 + 8;
                int c0a = (kk + ac + 4 * r0) & 31;
                int c1a = (kk + ac + 4 * r1) & 31;
                int c0b = (kk + ac + 4 + 4 * r0) & 31;
                int c1b = (kk + ac + 4 + 4 * r1) & 31;
                ahi[mt][0] = Xhi[r0][c0a]; alo[mt][0] = Xlo[r0][c0a];
                ahi[mt][1] = Xhi[r1][c1a]; alo[mt][1] = Xlo[r1][c1a];
                ahi[mt][2] = Xhi[r0][c0b]; alo[mt][2] = Xlo[r0][c0b];
                ahi[mt][3] = Xhi[r1][c1b]; alo[mt][3] = Xlo[r1][c1b];
            }
#pragma unroll
            for (int nt = 0; nt < 4; nt++) {
                int n = warp_n * 32 + nt * 8 + ar;
                int c0a = (kk + ac + 4 * n) & 31;
                int c0b = (kk + ac + 4 + 4 * n) & 31;
                bhi[nt][0] = Whi[n][c0a]; blo[nt][0] = Wlo[n][c0a];
                bhi[nt][1] = Whi[n][c0b]; blo[nt][1] = Wlo[n][c0b];
            }
#pragma unroll
            for (int mt = 0; mt < 2; mt++)
#pragma unroll
                for (int nt = 0; nt < 4; nt++) {
                    MMA_TF32(c[mt][nt], ahi[mt], bhi[nt]);
                    MMA_TF32(c[mt][nt], ahi[mt], blo[nt]);
                    MMA_TF32(c[mt][nt], alo[mt], bhi[nt]);
                }
        }
        __syncthreads();
    }

#pragma unroll
    for (int mt = 0; mt < 2; mt++) {
#pragma unroll
        for (int nt = 0; nt < 4; nt++) {
            int row = bm0 + warp_m * 32 + mt * 16 + (lane >> 2);
            int col = warp_n * 32 + nt * 8 + (lane & 3) * 2;
            float b0 = __ldg(&bias[col]);
            float b1 = __ldg(&bias[col + 1]);
            if (row < N) {
                float v0 = fmaxf(c[mt][nt][0] + b0, 0.f);
                float v1 = fmaxf(c[mt][nt][1] + b1, 0.f);
                long o = (long)(nodeBase + row) * D + col;
                *(float2*)&g_x[o]  = make_float2(v0, v1);
                *(float2*)&g_hA[o] = make_float2(v0, v1);
            }
            if (row + 8 < N) {
                float v2 = fmaxf(c[mt][nt][2] + b0, 0.f);
                float v3 = fmaxf(c[mt][nt][3] + b1, 0.f);
                long o = (long)(nodeBase + row + 8) * D + col;
                *(float2*)&g_x[o]  = make_float2(v2, v3);
                *(float2*)&g_hA[o] = make_float2(v2, v3);
            }
        }
    }
}

// ---------------- CSR build ----------------
__global__ void zero_rowptr_kernel()
{
    int i = blockIdx.x * blockDim.x + threadIdx.x;
    if (i < RP_TOT) g_rowptr[i] = 0;
}

__global__ void hist_kernel(const int* __restrict__ ei_pa, const int* __restrict__ ei_ap,
                            const int* __restrict__ ei_ps, const int* __restrict__ ei_sp)
{
    int e = blockIdx.x * blockDim.x + threadIdx.x;
    if (e >= E_TOT) return;
    const int* ei; int l, rpb;
    if (e < E_PA)                   { ei = ei_pa; l = e;                      rpb = RP_PA; }
    else if (e < E_PA + E_AP)       { ei = ei_ap; l = e - E_PA;               rpb = RP_AP; }
    else if (e < E_PA + E_AP + E_PS){ ei = ei_ps; l = e - E_PA - E_AP;        rpb = RP_PS; }
    else                            { ei = ei_sp; l = e - E_PA - E_AP - E_PS; rpb = RP_SP; }
    atomicAdd(&g_rowptr[rpb + 1 + ei[l]], 1);
}

__global__ void scan_kernel()
{
    __shared__ int ssum[1024];
    int base, n;
    if (blockIdx.x == 0)      { base = RP_PA; n = NP + 1;  }
    else if (blockIdx.x == 1) { base = RP_AP; n = NA + 1;  }
    else if (blockIdx.x == 2) { base = RP_PS; n = NP + 1;  }
    else                      { base = RP_SP; n = NSU + 1; }
    int tid = threadIdx.x;
    int chunk = (n + 1023) >> 10;
    int s0 = tid * chunk;
    int s1 = s0 + chunk; if (s1 > n) s1 = n; if (s0 > n) s0 = n;

    int sum = 0;
    for (int j = s0; j < s1; j++) sum += g_rowptr[base + j];
    ssum[tid] = sum;
    __syncthreads();
    for (int off = 1; off < 1024; off <<= 1) {
        int v = (tid >= off) ? ssum[tid - off] : 0;
        __syncthreads();
        ssum[tid] += v;
        __syncthreads();
    }
    int run = (tid == 0) ? 0 : ssum[tid - 1];
    for (int j = s0; j < s1; j++) {
        run += g_rowptr[base + j];
        g_rowptr[base + j] = run;
        g_cursor[base + j] = run;
    }
}

__global__ void scatter_kernel(const int* __restrict__ ei_pa, const int* __restrict__ ei_ap,
                               const int* __restrict__ ei_ps, const int* __restrict__ ei_sp)
{
    int e = blockIdx.x * blockDim.x + threadIdx.x;
    if (e >= E_TOT) return;
    const int* ei; int l, rpb, cb, En;
    if (e < E_PA)                   { ei = ei_pa; l = e;                      rpb = RP_PA; cb = CB_PA; En = E_PA; }
    else if (e < E_PA + E_AP)       { ei = ei_ap; l = e - E_PA;               rpb = RP_AP; cb = CB_AP; En = E_AP; }
    else if (e < E_PA + E_AP + E_PS){ ei = ei_ps; l = e - E_PA - E_AP;        rpb = RP_PS; cb = CB_PS; En = E_PS; }
    else                            { ei = ei_sp; l = e - E_PA - E_AP - E_PS; rpb = RP_SP; cb = CB_SP; En = E_SP; }
    int s = ei[l];
    int t = ei[En + l];
    int pos = atomicAdd(&g_cursor[rpb + s], 1);
    g_col[cb + pos] = t;
}

// ---------------- warp reduce ----------------
__device__ __forceinline__ float wsum32(float v)
{
#pragma unroll
    for (int o = 16; o; o >>= 1) v += __shfl_xor_sync(0xffffffffu, v, o);
    return v;
}

// ---------------- one-time: source-side d1/w2 (all hops) + hop-0 target h1 ----------
__global__ void d1w2_kernel(const float* __restrict__ attn1, const float* __restrict__ attn2)
{
    int gw = (blockIdx.x * blockDim.x + threadIdx.x) >> 5;
    int lane = threadIdx.x & 31;
    if (gw >= NTOT) return;
    const float* xr = g_x + (long)gw * D;
    float x0 = xr[lane], x1 = xr[lane + 32];

    int k0, k1, base0, base1, l;
    if (gw < NP)            { l = gw;            k0 = 0; base0 = D1_PA; k1 = 2;  base1 = D1_PS; }
    else if (gw < NP + NA)  { l = gw - NP;       k0 = 1; base0 = D1_AP; k1 = -1; base1 = 0; }
    else                    { l = gw - NP - NA;  k0 = 3; base0 = D1_SP; k1 = -1; base1 = 0; }

#pragma unroll
    for (int hop = 0; hop < HOPS; hop++) {
        {
            const float* a1 = attn1 + (hop * 4 + k0) * D;
            const float* a2 = attn2 + (hop * 4 + k0) * D;
            float d1 = wsum32(x0 * a1[lane] + x1 * a1[lane + 32]);
            float d2 = wsum32(x0 * a2[lane] + x1 * a2[lane + 32]);
            float z = d1 + d2; z = z > 0.f ? z : 0.2f * z;
            if (lane == 0) {
                g_d1[hop * D1_TOT + base0 + l] = d1;
                g_w2[hop * D1_TOT + base0 + l] = __expf(z);
            }
        }
        if (k1 >= 0) {
            const float* a1 = attn1 + (hop * 4 + k1) * D;
            const float* a2 = attn2 + (hop * 4 + k1) * D;
            float d1 = wsum32(x0 * a1[lane] + x1 * a1[lane + 32]);
            float d2 = wsum32(x0 * a2[lane] + x1 * a2[lane + 32]);
            float z = d1 + d2; z = z > 0.f ? z : 0.2f * z;
            if (lane == 0) {
                g_d1[hop * D1_TOT + base1 + l] = d1;
                g_w2[hop * D1_TOT + base1 + l] = __expf(z);
            }
        }
    }

    // hop-0 target-side h1 (h == x at hop 0), written into buffer A
    if (gw < NP) {
        const float* a2a = attn2 + (0 * 4 + 1) * D;   // targets of ap edges
        const float* a2b = attn2 + (0 * 4 + 3) * D;   // targets of sp edges
        float va = wsum32(x0 * a2a[lane] + x1 * a2a[lane + 32]);
        float vb = wsum32(x0 * a2b[lane] + x1 * a2b[lane + 32]);
        if (lane == 0) { g_h1A[H1_AP + l] = va; g_h1A[H1_SP + l] = vb; }
    } else if (gw < NP + NA) {
        const float* a2a = attn2 + (0 * 4 + 0) * D;   // targets of pa edges
        float va = wsum32(x0 * a2a[lane] + x1 * a2a[lane + 32]);
        if (lane == 0) g_h1A[H1_PA + l] = va;
    } else {
        const float* a2a = attn2 + (0 * 4 + 2) * D;   // targets of ps edges
        float va = wsum32(x0 * a2a[lane] + x1 * a2a[lane + 32]);
        if (lane == 0) g_h1A[H1_PS + l] = va;
    }
}

// ---------------- per-hop aggregation (R4 inner loop; h1 fused epilogue) ------------
__device__ __forceinline__ void aggr_et(
    int nodeLocal, int rpBase, int colBase, int d1Base, int tOff, int hop,
    const float* __restrict__ h, const float* __restrict__ h1b, int lane,
    float x0, float x1, float wk, float& acc0, float& acc1)
{
    float d1 = g_d1[hop * D1_TOT + d1Base + nodeLocal];
    float w2 = g_w2[hop * D1_TOT + d1Base + nodeLocal];
    float num0 = w2 * x0, num1 = w2 * x1, div = w2;
    int e0 = g_rowptr[rpBase + nodeLocal];
    int e1 = g_rowptr[rpBase + nodeLocal + 1];
    const float* hb = h + (long)tOff * D;

    int e = e0;
    for (; e + 2 <= e1; e += 2) {
        int t0 = g_col[colBase + e];
        int t1 = g_col[colBase + e + 1];
        float p0 = h1b[t0];
        float p1 = h1b[t1];
        const float* hr0 = hb + (long)t0 * D;
        const float* hr1 = hb + (long)t1 * D;
        float u0 = hr0[lane], u1 = hr0[lane + 32];
        float v0 = hr1[lane], v1 = hr1[lane + 32];
        float z0 = d1 + p0; z0 = z0 > 0.f ? z0 : 0.2f * z0;
        float z1 = d1 + p1; z1 = z1 > 0.f ? z1 : 0.2f * z1;
        float w0 = __expf(z0);
        float w1 = __expf(z1);
        num0 += w0 * u0 + w1 * v0;
        num1 += w0 * u1 + w1 * v1;
        div  += w0 + w1;
    }
    if (e < e1) {
        int t = g_col[colBase + e];
        float zz = d1 + h1b[t];
        zz = zz > 0.f ? zz : 0.2f * zz;
        float w1 = __expf(zz);
        const float* hr = hb + (long)t * D;
        num0 += w1 * hr[lane];
        num1 += w1 * hr[lane + 32];
        div  += w1;
    }
    float s = wk / div;
    acc0 += num0 * s;
    acc1 += num1 * s;
}

__global__ void __launch_bounds__(256) aggr_kernel(
    const float* __restrict__ attn2, const float* __restrict__ lw, int hop, int curB)
{
    int gw = (blockIdx.x * blockDim.x + threadIdx.x) >> 5;
    int lane = threadIdx.x & 31;
    if (gw >= NTOT) return;
    const float* h   = curB ? g_hB : g_hA;
    float*       hn  = curB ? g_hA : g_hB;
    const float* h1r = (hop & 1) ? g_h1B : g_h1A;   // read buffer for this hop
    float*       h1w = (hop & 1) ? g_h1A : g_h1B;   // write buffer for next hop
    const float* xr = g_x + (long)gw * D;
    float x0 = xr[lane], x1 = xr[lane + 32];
    float acc0 = 0.f, acc1 = 0.f;

    if (gw < NP) {
        float l0 = lw[hop * 4 + 0], l2 = lw[hop * 4 + 2];
        float m = fmaxf(l0, l2);
        float e0 = __expf(l0 - m), e2 = __expf(l2 - m);
        float inv = 1.f / (e0 + e2);
        aggr_et(gw, RP_PA, CB_PA, D1_PA, NP,      hop, h, h1r + H1_PA, lane, x0, x1, e0 * inv, acc0, acc1);
        aggr_et(gw, RP_PS, CB_PS, D1_PS, NP + NA, hop, h, h1r + H1_PS, lane, x0, x1, e2 * inv, acc0, acc1);
    } else if (gw < NP + NA) {
        aggr_et(gw - NP, RP_AP, CB_AP, D1_AP, 0,  hop, h, h1r + H1_AP, lane, x0, x1, 1.f, acc0, acc1);
    } else {
        aggr_et(gw - NP - NA, RP_SP, CB_SP, D1_SP, 0, hop, h, h1r + H1_SP, lane, x0, x1, 1.f, acc0, acc1);
    }
    acc0 = acc0 > 0.f ? acc0 : __expf(acc0) - 1.f;
    acc1 = acc1 > 0.f ? acc1 : __expf(acc1) - 1.f;
    hn[(long)gw * D + lane]      = acc0;
    hn[(long)gw * D + lane + 32] = acc1;

    // ---- fused: target-side h1 for the NEXT hop from the fresh hn row ----
    int nhop = hop + 1;
    if (nhop < HOPS) {
        if (gw < NP) {
            const float* a2a = attn2 + (nhop * 4 + 1) * D;
            const float* a2b = attn2 + (nhop * 4 + 3) * D;
            float va = wsum32(acc0 * a2a[lane] + acc1 * a2a[lane + 32]);
            float vb = wsum32(acc0 * a2b[lane] + acc1 * a2b[lane + 32]);
            if (lane == 0) { h1w[H1_AP + gw] = va; h1w[H1_SP + gw] = vb; }
        } else if (gw < NP + NA) {
            const float* a2a = attn2 + (nhop * 4 + 0) * D;
            float va = wsum32(acc0 * a2a[lane] + acc1 * a2a[lane + 32]);
            if (lane == 0) h1w[H1_PA + (gw - NP)] = va;
        } else {
            const float* a2a = attn2 + (nhop * 4 + 2) * D;
            float va = wsum32(acc0 * a2a[lane] + acc1 * a2a[lane + 32]);
            if (lane == 0) h1w[H1_PS + (gw - NP - NA)] = va;
        }
    }
}

// ---------------- fc2: out = h_paper @ W^T + b (warp per node, W in smem) -----------
__global__ void __launch_bounds__(256) fc2_kernel(
    const float* __restrict__ W, const float* __restrict__ bias,
    float* __restrict__ out)
{
    __shared__ float Ws[NOUT * D];
    __shared__ float bs[NOUT];
    int tid = threadIdx.x;
    for (int i = tid; i < NOUT * D; i += 256) Ws[i] = W[i];
    if (tid < NOUT) bs[tid] = bias[tid];
    __syncthreads();

    int gw = (blockIdx.x * 256 + tid) >> 5;
    int lane = tid & 31;
    if (gw >= NP) return;
    const float* hr = g_hB + (long)gw * D;   // HOPS=5 -> final h in buffer B
    float v0 = hr[lane], v1 = hr[lane + 32];
    float res = 0.f;
#pragma unroll
    for (int o = 0; o < NOUT; o++) {
        float s = v0 * Ws[o * D + lane] + v1 * Ws[o * D + lane + 32];
        s = wsum32(s);
        if (lane == o) res = s;
    }
    if (lane < NOUT) out[gw * NOUT + lane] = res + bs[lane];
}

// ---------------- launch ----------------
extern "C" void kernel_launch(void* const* d_in, const int* in_sizes, int n_in,
                              void* d_out, int out_size)
{
    const float* x_paper   = (const float*)d_in[0];
    const float* x_author  = (const float*)d_in[1];
    const float* x_subject = (const float*)d_in[2];
    const float* fc1p_w = (const float*)d_in[3];
    const float* fc1p_b = (const float*)d_in[4];
    const float* fc1a_w = (const float*)d_in[5];
    const float* fc1a_b = (const float*)d_in[6];
    const float* fc1s_w = (const float*)d_in[7];
    const float* fc1s_b = (const float*)d_in[8];
    const float* attn1  = (const float*)d_in[9];
    const float* attn2  = (const float*)d_in[10];
    const float* lw     = (const float*)d_in[11];
    const float* fc2_w  = (const float*)d_in[12];
    const float* fc2_b  = (const float*)d_in[13];
    const int* ei_pa = (const int*)d_in[14];
    const int* ei_ap = (const int*)d_in[15];
    const int* ei_ps = (const int*)d_in[16];
    const int* ei_sp = (const int*)d_in[17];
    float* out = (float*)d_out;

    zero_rowptr_kernel<<<(RP_TOT + 255) / 256, 256>>>();

    fc1_kernel<<<(NP  + 127) / 128, 256>>>(x_paper,   fc1p_w, fc1p_b, NP,  512, 0);
    fc1_kernel<<<(NA  + 127) / 128, 256>>>(x_author,  fc1a_w, fc1a_b, NA,  256, NP);
    fc1_kernel<<<(NSU + 127) / 128, 256>>>(x_subject, fc1s_w, fc1s_b, NSU, 128, NP + NA);

    hist_kernel<<<(E_TOT + 255) / 256, 256>>>(ei_pa, ei_ap, ei_ps, ei_sp);
    scan_kernel<<<4, 1024>>>();
    scatter_kernel<<<(E_TOT + 255) / 256, 256>>>(ei_pa, ei_ap, ei_ps, ei_sp);

    d1w2_kernel<<<(NTOT * 32 + 255) / 256, 256>>>(attn1, attn2);

    for (int hop = 0; hop < HOPS; hop++) {
        int curB = hop & 1;
        aggr_kernel<<<(NTOT * 32 + 255) / 256, 256>>>(attn2, lw, hop, curB);
    }

    fc2_kernel<<<(NP * 32 + 255) / 256, 256>>>(fc2_w, fc2_b, out);
}

// round 9
// speedup vs baseline: 1.2107x; 1.0324x over previous
#include <cuda_runtime.h>
#include <cstdint>

// ---------------- problem constants ----------------
#define NP   100000
#define NA   200000
#define NSU  1000
#define NTOT (NP + NA + NSU)          // 301000
#define D    64
#define HOPS 5
#define NOUT 16

#define E_PA 800000
#define E_AP 800000
#define E_PS 100000
#define E_SP 100000
#define E_TOT (E_PA + E_AP + E_PS + E_SP)   // 1800000

// row_ptr segment bases (each segment length = Ns+1)
#define RP_PA 0
#define RP_AP (NP + 1)
#define RP_PS (RP_AP + NA + 1)
#define RP_SP (RP_PS + NP + 1)
#define RP_TOT (RP_SP + NSU + 1)

// col array bases
#define CB_PA 0
#define CB_AP E_PA
#define CB_PS (E_PA + E_AP)
#define CB_SP (E_PA + E_AP + E_PS)

// h1 (target-side attention score) bases
#define H1_PA 0                        // len NA  (targets: author)
#define H1_AP NA                       // len NP  (targets: paper)
#define H1_PS (NA + NP)                // len NSU (targets: subject)
#define H1_SP (NA + NP + NSU)          // len NP  (targets: paper)
#define H1_TOT (NA + NP + NSU + NP)    // 401000

// d1/w2 (source-side) segment bases, ordered [pa, ap, ps, sp]
#define D1_PA 0                        // len NP
#define D1_AP NP                       // len NA
#define D1_PS (NP + NA)                // len NP
#define D1_SP (NP + NA + NP)           // len NSU
#define D1_TOT (NP + NA + NP + NSU)    // 401000

// ---------------- scratch (static device memory; no runtime alloc) ----------------
__device__ float g_x  [NTOT * D];
__device__ float g_hA [NTOT * D];
__device__ float g_hB [NTOT * D];
__device__ float g_h1A[H1_TOT];        // h1 double buffer (hop parity)
__device__ float g_h1B[H1_TOT];
__device__ float g_d1 [HOPS * D1_TOT];
__device__ float g_w2 [HOPS * D1_TOT];
__device__ int   g_rowptr[RP_TOT];
__device__ int   g_cursor[RP_TOT];
__device__ int   g_col[E_TOT];

// ---------------- tf32 helpers ----------------
__device__ __forceinline__ uint32_t f2tf(float x)
{
    uint32_t r;
    asm("cvt.rna.tf32.f32 %0, %1;" : "=r"(r) : "f"(x));
    return r;
}

__device__ __forceinline__ void split_tf32(float x, float& hi, float& lo)
{
    uint32_t h = f2tf(x);
    float hf = __uint_as_float(h);
    hi = hf;
    lo = __uint_as_float(f2tf(x - hf));
}

#define MMA_TF32(c, a, b) \
    asm volatile("mma.sync.aligned.m16n8k8.row.col.f32.tf32.tf32.f32 " \
                 "{%0,%1,%2,%3},{%4,%5,%6,%7},{%8,%9},{%0,%1,%2,%3};" \
                 : "+f"((c)[0]), "+f"((c)[1]), "+f"((c)[2]), "+f"((c)[3]) \
                 : "r"(__float_as_uint((a)[0])), "r"(__float_as_uint((a)[1])), \
                   "r"(__float_as_uint((a)[2])), "r"(__float_as_uint((a)[3])), \
                   "r"(__float_as_uint((b)[0])), "r"(__float_as_uint((b)[1])))

// ---------------- fc1: Y = relu(X @ W^T + b) via tf32x3 tensor cores ----------------
__global__ void __launch_bounds__(256) fc1_kernel(
    const float* __restrict__ X, const float* __restrict__ W,
    const float* __restrict__ bias, int N, int F, int nodeBase)
{
    __shared__ float Xhi[128][32];
    __shared__ float Xlo[128][32];
    __shared__ float Whi[64][32];
    __shared__ float Wlo[64][32];

    const int tid  = threadIdx.x;
    const int lane = tid & 31;
    const int warp = tid >> 5;
    const int warp_m = warp & 3;
    const int warp_n = warp >> 2;
    const int bm0 = blockIdx.x * 128;

    float c[2][4][4];
#pragma unroll
    for (int mt = 0; mt < 2; mt++)
#pragma unroll
        for (int nt = 0; nt < 4; nt++)
#pragma unroll
            for (int i = 0; i < 4; i++) c[mt][nt][i] = 0.f;

    const int lr = tid >> 3;
    const int lc = (tid & 7) * 4;

    for (int k0 = 0; k0 < F; k0 += 32) {
#pragma unroll
        for (int i = 0; i < 4; i++) {
            int r = lr + i * 32;
            int row = bm0 + r;
            float4 v = make_float4(0.f, 0.f, 0.f, 0.f);
            if (row < N) v = *(const float4*)&X[(long)row * F + k0 + lc];
            int sc = (lc + 4 * r) & 31;
            float h0, l0, h1, l1, h2, l2, h3, l3;
            split_tf32(v.x, h0, l0); split_tf32(v.y, h1, l1);
            split_tf32(v.z, h2, l2); split_tf32(v.w, h3, l3);
            *(float4*)&Xhi[r][sc] = make_float4(h0, h1, h2, h3);
            *(float4*)&Xlo[r][sc] = make_float4(l0, l1, l2, l3);
        }
#pragma unroll
        for (int i = 0; i < 2; i++) {
            int r = lr + i * 32;
            float4 v = *(const float4*)&W[(long)r * F + k0 + lc];
            int sc = (lc + 4 * r) & 31;
            float h0, l0, h1, l1, h2, l2, h3, l3;
            split_tf32(v.x, h0, l0); split_tf32(v.y, h1, l1);
            split_tf32(v.z, h2, l2); split_tf32(v.w, h3, l3);
            *(float4*)&Whi[r][sc] = make_float4(h0, h1, h2, h3);
            *(float4*)&Wlo[r][sc] = make_float4(l0, l1, l2, l3);
        }
        __syncthreads();

        const int ar = lane >> 2;
        const int ac = lane & 3;
#pragma unroll
        for (int ks = 0; ks < 4; ks++) {
            int kk = ks * 8;
            float ahi[2][4], alo[2][4], bhi[4][2], blo[4][2];
#pragma unroll
            for (int mt = 0; mt < 2; mt++) {
                int r0 = warp_m * 32 + mt * 16 + ar;
                int r1 = r0 + 8;
                int c0a = (kk + ac + 4 * r0) & 31;
                int c1a = (kk + ac + 4 * r1) & 31;
                int c0b = (kk + ac + 4 + 4 * r0) & 31;
                int c1b = (kk + ac + 4 + 4 * r1) & 31;
                ahi[mt][0] = Xhi[r0][c0a]; alo[mt][0] = Xlo[r0][c0a];
                ahi[mt][1] = Xhi[r1][c1a]; alo[mt][1] = Xlo[r1][c1a];
                ahi[mt][2] = Xhi[r0][c0b]; alo[mt][2] = Xlo[r0][c0b];
                ahi[mt][3] = Xhi[r1][c1b]; alo[mt][3] = Xlo[r1][c1b];
            }
#pragma unroll
            for (int nt = 0; nt < 4; nt++) {
                int n = warp_n * 32 + nt * 8 + ar;
                int c0a = (kk + ac + 4 * n) & 31;
                int c0b = (kk + ac + 4 + 4 * n) & 31;
                bhi[nt][0] = Whi[n][c0a]; blo[nt][0] = Wlo[n][c0a];
                bhi[nt][1] = Whi[n][c0b]; blo[nt][1] = Wlo[n][c0b];
            }
#pragma unroll
            for (int mt = 0; mt < 2; mt++)
#pragma unroll
                for (int nt = 0; nt < 4; nt++) {
                    MMA_TF32(c[mt][nt], ahi[mt], bhi[nt]);
                    MMA_TF32(c[mt][nt], ahi[mt], blo[nt]);
                    MMA_TF32(c[mt][nt], alo[mt], bhi[nt]);
                }
        }
        __syncthreads();
    }

#pragma unroll
    for (int mt = 0; mt < 2; mt++) {
#pragma unroll
        for (int nt = 0; nt < 4; nt++) {
            int row = bm0 + warp_m * 32 + mt * 16 + (lane >> 2);
            int col = warp_n * 32 + nt * 8 + (lane & 3) * 2;
            float b0 = __ldg(&bias[col]);
            float b1 = __ldg(&bias[col + 1]);
            if (row < N) {
                float v0 = fmaxf(c[mt][nt][0] + b0, 0.f);
                float v1 = fmaxf(c[mt][nt][1] + b1, 0.f);
                long o = (long)(nodeBase + row) * D + col;
                *(float2*)&g_x[o]  = make_float2(v0, v1);
                *(float2*)&g_hA[o] = make_float2(v0, v1);
            }
            if (row + 8 < N) {
                float v2 = fmaxf(c[mt][nt][2] + b0, 0.f);
                float v3 = fmaxf(c[mt][nt][3] + b1, 0.f);
                long o = (long)(nodeBase + row + 8) * D + col;
                *(float2*)&g_x[o]  = make_float2(v2, v3);
                *(float2*)&g_hA[o] = make_float2(v2, v3);
            }
        }
    }
}

// ---------------- CSR build ----------------
__global__ void zero_rowptr_kernel()
{
    int i = blockIdx.x * blockDim.x + threadIdx.x;
    if (i < RP_TOT) g_rowptr[i] = 0;
}

__global__ void hist_kernel(const int* __restrict__ ei_pa, const int* __restrict__ ei_ap,
                            const int* __restrict__ ei_ps, const int* __restrict__ ei_sp)
{
    int e = blockIdx.x * blockDim.x + threadIdx.x;
    if (e >= E_TOT) return;
    const int* ei; int l, rpb;
    if (e < E_PA)                   { ei = ei_pa; l = e;                      rpb = RP_PA; }
    else if (e < E_PA + E_AP)       { ei = ei_ap; l = e - E_PA;               rpb = RP_AP; }
    else if (e < E_PA + E_AP + E_PS){ ei = ei_ps; l = e - E_PA - E_AP;        rpb = RP_PS; }
    else                            { ei = ei_sp; l = e - E_PA - E_AP - E_PS; rpb = RP_SP; }
    atomicAdd(&g_rowptr[rpb + 1 + ei[l]], 1);
}

__global__ void scan_kernel()
{
    __shared__ int ssum[1024];
    int base, n;
    if (blockIdx.x == 0)      { base = RP_PA; n = NP + 1;  }
    else if (blockIdx.x == 1) { base = RP_AP; n = NA + 1;  }
    else if (blockIdx.x == 2) { base = RP_PS; n = NP + 1;  }
    else                      { base = RP_SP; n = NSU + 1; }
    int tid = threadIdx.x;
    int chunk = (n + 1023) >> 10;
    int s0 = tid * chunk;
    int s1 = s0 + chunk; if (s1 > n) s1 = n; if (s0 > n) s0 = n;

    int sum = 0;
    for (int j = s0; j < s1; j++) sum += g_rowptr[base + j];
    ssum[tid] = sum;
    __syncthreads();
    for (int off = 1; off < 1024; off <<= 1) {
        int v = (tid >= off) ? ssum[tid - off] : 0;
        __syncthreads();
        ssum[tid] += v;
        __syncthreads();
    }
    int run = (tid == 0) ? 0 : ssum[tid - 1];
    for (int j = s0; j < s1; j++) {
        run += g_rowptr[base + j];
        g_rowptr[base + j] = run;
        g_cursor[base + j] = run;
    }
}

__global__ void scatter_kernel(const int* __restrict__ ei_pa, const int* __restrict__ ei_ap,
                               const int* __restrict__ ei_ps, const int* __restrict__ ei_sp)
{
    int e = blockIdx.x * blockDim.x + threadIdx.x;
    if (e >= E_TOT) return;
    const int* ei; int l, rpb, cb, En;
    if (e < E_PA)                   { ei = ei_pa; l = e;                      rpb = RP_PA; cb = CB_PA; En = E_PA; }
    else if (e < E_PA + E_AP)       { ei = ei_ap; l = e - E_PA;               rpb = RP_AP; cb = CB_AP; En = E_AP; }
    else if (e < E_PA + E_AP + E_PS){ ei = ei_ps; l = e - E_PA - E_AP;        rpb = RP_PS; cb = CB_PS; En = E_PS; }
    else                            { ei = ei_sp; l = e - E_PA - E_AP - E_PS; rpb = RP_SP; cb = CB_SP; En = E_SP; }
    int s = ei[l];
    int t = ei[En + l];
    int pos = atomicAdd(&g_cursor[rpb + s], 1);
    g_col[cb + pos] = t;
}

// ---------------- reductions ----------------
__device__ __forceinline__ float wsum32(float v)
{
#pragma unroll
    for (int o = 16; o; o >>= 1) v += __shfl_xor_sync(0xffffffffu, v, o);
    return v;
}

__device__ __forceinline__ float wsum16(float v)
{
#pragma unroll
    for (int o = 8; o; o >>= 1) v += __shfl_xor_sync(0xffffffffu, v, o);
    return v;
}

// ---------------- one-time: source-side d1/w2 (all hops) + hop-0 target h1 ----------
__global__ void d1w2_kernel(const float* __restrict__ attn1, const float* __restrict__ attn2)
{
    int gw = (blockIdx.x * blockDim.x + threadIdx.x) >> 5;
    int lane = threadIdx.x & 31;
    if (gw >= NTOT) return;
    const float* xr = g_x + (long)gw * D;
    float x0 = xr[lane], x1 = xr[lane + 32];

    int k0, k1, base0, base1, l;
    if (gw < NP)            { l = gw;            k0 = 0; base0 = D1_PA; k1 = 2;  base1 = D1_PS; }
    else if (gw < NP + NA)  { l = gw - NP;       k0 = 1; base0 = D1_AP; k1 = -1; base1 = 0; }
    else                    { l = gw - NP - NA;  k0 = 3; base0 = D1_SP; k1 = -1; base1 = 0; }

#pragma unroll
    for (int hop = 0; hop < HOPS; hop++) {
        {
            const float* a1 = attn1 + (hop * 4 + k0) * D;
            const float* a2 = attn2 + (hop * 4 + k0) * D;
            float d1 = wsum32(x0 * a1[lane] + x1 * a1[lane + 32]);
            float d2 = wsum32(x0 * a2[lane] + x1 * a2[lane + 32]);
            float z = d1 + d2; z = z > 0.f ? z : 0.2f * z;
            if (lane == 0) {
                g_d1[hop * D1_TOT + base0 + l] = d1;
                g_w2[hop * D1_TOT + base0 + l] = __expf(z);
            }
        }
        if (k1 >= 0) {
            const float* a1 = attn1 + (hop * 4 + k1) * D;
            const float* a2 = attn2 + (hop * 4 + k1) * D;
            float d1 = wsum32(x0 * a1[lane] + x1 * a1[lane + 32]);
            float d2 = wsum32(x0 * a2[lane] + x1 * a2[lane + 32]);
            float z = d1 + d2; z = z > 0.f ? z : 0.2f * z;
            if (lane == 0) {
                g_d1[hop * D1_TOT + base1 + l] = d1;
                g_w2[hop * D1_TOT + base1 + l] = __expf(z);
            }
        }
    }

    // hop-0 target-side h1 (h == x at hop 0), written into buffer A
    if (gw < NP) {
        const float* a2a = attn2 + (0 * 4 + 1) * D;   // targets of ap edges
        const float* a2b = attn2 + (0 * 4 + 3) * D;   // targets of sp edges
        float va = wsum32(x0 * a2a[lane] + x1 * a2a[lane + 32]);
        float vb = wsum32(x0 * a2b[lane] + x1 * a2b[lane + 32]);
        if (lane == 0) { g_h1A[H1_AP + l] = va; g_h1A[H1_SP + l] = vb; }
    } else if (gw < NP + NA) {
        const float* a2a = attn2 + (0 * 4 + 0) * D;   // targets of pa edges
        float va = wsum32(x0 * a2a[lane] + x1 * a2a[lane + 32]);
        if (lane == 0) g_h1A[H1_PA + l] = va;
    } else {
        const float* a2a = attn2 + (0 * 4 + 2) * D;   // targets of ps edges
        float va = wsum32(x0 * a2a[lane] + x1 * a2a[lane + 32]);
        if (lane == 0) g_h1A[H1_PS + l] = va;
    }
}

// ---------------- per-hop aggregation: HALF-WARP per node, float4 rows --------------
__device__ __forceinline__ void aggr_et_h(
    int nodeLocal, int rpBase, int colBase, int d1Base, int tOff, int hop,
    const float* __restrict__ h, const float* __restrict__ h1b, int hlane,
    const float4& x4, float wk, float4& acc)
{
    float d1 = g_d1[hop * D1_TOT + d1Base + nodeLocal];
    float w2 = g_w2[hop * D1_TOT + d1Base + nodeLocal];
    float4 num = make_float4(w2 * x4.x, w2 * x4.y, w2 * x4.z, w2 * x4.w);
    float div = w2;
    int e0 = g_rowptr[rpBase + nodeLocal];
    int e1 = g_rowptr[rpBase + nodeLocal + 1];
    const float* hb = h + (long)tOff * D;

    int e = e0;
    for (; e + 2 <= e1; e += 2) {
        int t0 = g_col[colBase + e];
        int t1 = g_col[colBase + e + 1];
        float p0 = h1b[t0];
        float p1 = h1b[t1];
        float4 u = *(const float4*)(hb + (long)t0 * D + 4 * hlane);
        float4 v = *(const float4*)(hb + (long)t1 * D + 4 * hlane);
        float z0 = d1 + p0; z0 = z0 > 0.f ? z0 : 0.2f * z0;
        float z1 = d1 + p1; z1 = z1 > 0.f ? z1 : 0.2f * z1;
        float w0 = __expf(z0);
        float w1 = __expf(z1);
        num.x += w0 * u.x + w1 * v.x;
        num.y += w0 * u.y + w1 * v.y;
        num.z += w0 * u.z + w1 * v.z;
        num.w += w0 * u.w + w1 * v.w;
        div   += w0 + w1;
    }
    if (e < e1) {
        int t = g_col[colBase + e];
        float zz = d1 + h1b[t];
        zz = zz > 0.f ? zz : 0.2f * zz;
        float w1 = __expf(zz);
        float4 u = *(const float4*)(hb + (long)t * D + 4 * hlane);
        num.x += w1 * u.x; num.y += w1 * u.y; num.z += w1 * u.z; num.w += w1 * u.w;
        div   += w1;
    }
    float s = wk / div;
    acc.x += num.x * s; acc.y += num.y * s; acc.z += num.z * s; acc.w += num.w * s;
}

__global__ void __launch_bounds__(256) aggr_kernel(
    const float* __restrict__ attn2, const float* __restrict__ lw, int hop, int curB)
{
    int gn = (blockIdx.x * blockDim.x + threadIdx.x) >> 4;   // half-warp id = node
    int hlane = threadIdx.x & 15;
    if (gn >= NTOT) return;
    const float* h   = curB ? g_hB : g_hA;
    float*       hn  = curB ? g_hA : g_hB;
    const float* h1r = (hop & 1) ? g_h1B : g_h1A;
    float*       h1w = (hop & 1) ? g_h1A : g_h1B;
    const float4 x4 = *(const float4*)(g_x + (long)gn * D + 4 * hlane);
    float4 acc = make_float4(0.f, 0.f, 0.f, 0.f);

    if (gn < NP) {
        float l0 = lw[hop * 4 + 0], l2 = lw[hop * 4 + 2];
        float m = fmaxf(l0, l2);
        float e0 = __expf(l0 - m), e2 = __expf(l2 - m);
        float inv = 1.f / (e0 + e2);
        aggr_et_h(gn, RP_PA, CB_PA, D1_PA, NP,      hop, h, h1r + H1_PA, hlane, x4, e0 * inv, acc);
        aggr_et_h(gn, RP_PS, CB_PS, D1_PS, NP + NA, hop, h, h1r + H1_PS, hlane, x4, e2 * inv, acc);
    } else if (gn < NP + NA) {
        aggr_et_h(gn - NP, RP_AP, CB_AP, D1_AP, 0,  hop, h, h1r + H1_AP, hlane, x4, 1.f, acc);
    } else {
        aggr_et_h(gn - NP - NA, RP_SP, CB_SP, D1_SP, 0, hop, h, h1r + H1_SP, hlane, x4, 1.f, acc);
    }
    acc.x = acc.x > 0.f ? acc.x : __expf(acc.x) - 1.f;
    acc.y = acc.y > 0.f ? acc.y : __expf(acc.y) - 1.f;
    acc.z = acc.z > 0.f ? acc.z : __expf(acc.z) - 1.f;
    acc.w = acc.w > 0.f ? acc.w : __expf(acc.w) - 1.f;
    *(float4*)(hn + (long)gn * D + 4 * hlane) = acc;

    // ---- fused: target-side h1 for the NEXT hop from the fresh hn row ----
    int nhop = hop + 1;
    if (nhop < HOPS) {
        if (gn < NP) {
            const float4 a2a = *(const float4*)(attn2 + (nhop * 4 + 1) * D + 4 * hlane);
            const float4 a2b = *(const float4*)(attn2 + (nhop * 4 + 3) * D + 4 * hlane);
            float va = wsum16(acc.x * a2a.x + acc.y * a2a.y + acc.z * a2a.z + acc.w * a2a.w);
            float vb = wsum16(acc.x * a2b.x + acc.y * a2b.y + acc.z * a2b.z + acc.w * a2b.w);
            if (hlane == 0) { h1w[H1_AP + gn] = va; h1w[H1_SP + gn] = vb; }
        } else if (gn < NP + NA) {
            const float4 a2a = *(const float4*)(attn2 + (nhop * 4 + 0) * D + 4 * hlane);
            float va = wsum16(acc.x * a2a.x + acc.y * a2a.y + acc.z * a2a.z + acc.w * a2a.w);
            if (hlane == 0) h1w[H1_PA + (gn - NP)] = va;
        } else {
            const float4 a2a = *(const float4*)(attn2 + (nhop * 4 + 2) * D + 4 * hlane);
            float va = wsum16(acc.x * a2a.x + acc.y * a2a.y + acc.z * a2a.z + acc.w * a2a.w);
            if (hlane == 0) h1w[H1_PS + (gn - NP - NA)] = va;
        }
    }
}

// ---------------- fc2: out = h_paper @ W^T + b (warp per node, W in smem) -----------
__global__ void __launch_bounds__(256) fc2_kernel(
    const float* __restrict__ W, const float* __restrict__ bias,
    float* __restrict__ out)
{
    __shared__ float Ws[NOUT * D];
    __shared__ float bs[NOUT];
    int tid = threadIdx.x;
    for (int i = tid; i < NOUT * D; i += 256) Ws[i] = W[i];
    if (tid < NOUT) bs[tid] = bias[tid];
    __syncthreads();

    int gw = (blockIdx.x * 256 + tid) >> 5;
    int lane = tid & 31;
    if (gw >= NP) return;
    const float* hr = g_hB + (long)gw * D;   // HOPS=5 -> final h in buffer B
    float v0 = hr[lane], v1 = hr[lane + 32];
    float res = 0.f;
#pragma unroll
    for (int o = 0; o < NOUT; o++) {
        float s = v0 * Ws[o * D + lane] + v1 * Ws[o * D + lane + 32];
        s = wsum32(s);
        if (lane == o) res = s;
    }
    if (lane < NOUT) out[gw * NOUT + lane] = res + bs[lane];
}

// ---------------- launch ----------------
extern "C" void kernel_launch(void* const* d_in, const int* in_sizes, int n_in,
                              void* d_out, int out_size)
{
    const float* x_paper   = (const float*)d_in[0];
    const float* x_author  = (const float*)d_in[1];
    const float* x_subject = (const float*)d_in[2];
    const float* fc1p_w = (const float*)d_in[3];
    const float* fc1p_b = (const float*)d_in[4];
    const float* fc1a_w = (const float*)d_in[5];
    const float* fc1a_b = (const float*)d_in[6];
    const float* fc1s_w = (const float*)d_in[7];
    const float* fc1s_b = (const float*)d_in[8];
    const float* attn1  = (const float*)d_in[9];
    const float* attn2  = (const float*)d_in[10];
    const float* lw     = (const float*)d_in[11];
    const float* fc2_w  = (const float*)d_in[12];
    const float* fc2_b  = (const float*)d_in[13];
    const int* ei_pa = (const int*)d_in[14];
    const int* ei_ap = (const int*)d_in[15];
    const int* ei_ps = (const int*)d_in[16];
    const int* ei_sp = (const int*)d_in[17];
    float* out = (float*)d_out;

    zero_rowptr_kernel<<<(RP_TOT + 255) / 256, 256>>>();

    fc1_kernel<<<(NP  + 127) / 128, 256>>>(x_paper,   fc1p_w, fc1p_b, NP,  512, 0);
    fc1_kernel<<<(NA  + 127) / 128, 256>>>(x_author,  fc1a_w, fc1a_b, NA,  256, NP);
    fc1_kernel<<<(NSU + 127) / 128, 256>>>(x_subject, fc1s_w, fc1s_b, NSU, 128, NP + NA);

    hist_kernel<<<(E_TOT + 255) / 256, 256>>>(ei_pa, ei_ap, ei_ps, ei_sp);
    scan_kernel<<<4, 1024>>>();
    scatter_kernel<<<(E_TOT + 255) / 256, 256>>>(ei_pa, ei_ap, ei_ps, ei_sp);

    d1w2_kernel<<<(NTOT * 32 + 255) / 256, 256>>>(attn1, attn2);

    for (int hop = 0; hop < HOPS; hop++) {
        int curB = hop & 1;
        aggr_kernel<<<(NTOT * 16 + 255) / 256, 256>>>(attn2, lw, hop, curB);
    }

    fc2_kernel<<<(NP * 32 + 255) / 256, 256>>>(fc2_w, fc2_b, out);
}

// round 10
// speedup vs baseline: 1.3342x; 1.1020x over previous
#include <cuda_runtime.h>
#include <cstdint>

// ---------------- problem constants ----------------
#define NP   100000
#define NA   200000
#define NSU  1000
#define NTOT (NP + NA + NSU)          // 301000
#define D    64
#define HOPS 5
#define NOUT 16

#define E_PA 800000
#define E_AP 800000
#define E_PS 100000
#define E_SP 100000
#define E_TOT (E_PA + E_AP + E_PS + E_SP)   // 1800000

// row_ptr segment bases (each segment length = Ns+1)
#define RP_PA 0
#define RP_AP (NP + 1)
#define RP_PS (RP_AP + NA + 1)
#define RP_SP (RP_PS + NP + 1)
#define RP_TOT (RP_SP + NSU + 1)

// col array bases
#define CB_PA 0
#define CB_AP E_PA
#define CB_PS (E_PA + E_AP)
#define CB_SP (E_PA + E_AP + E_PS)

// h1 (target-side attention score) bases
#define H1_PA 0                        // len NA  (targets: author)
#define H1_AP NA                       // len NP  (targets: paper)
#define H1_PS (NA + NP)                // len NSU (targets: subject)
#define H1_SP (NA + NP + NSU)          // len NP  (targets: paper)
#define H1_TOT (NA + NP + NSU + NP)    // 401000

// d1/w2 (source-side) segment bases, ordered [pa, ap, ps, sp]
#define D1_PA 0                        // len NP
#define D1_AP NP                       // len NA
#define D1_PS (NP + NA)                // len NP
#define D1_SP (NP + NA + NP)           // len NSU
#define D1_TOT (NP + NA + NP + NSU)    // 401000

// ---------------- scratch (static device memory; no runtime alloc) ----------------
__device__ float g_x  [NTOT * D];
__device__ float g_hA [NTOT * D];
__device__ float g_hB [NTOT * D];
__device__ float g_h1A[H1_TOT];        // h1 double buffer (hop parity)
__device__ float g_h1B[H1_TOT];
__device__ float g_d1 [HOPS * D1_TOT];
__device__ float g_w2 [HOPS * D1_TOT];
__device__ int   g_rowptr[RP_TOT];
__device__ int   g_cursor[RP_TOT];
__device__ int   g_col[E_TOT];

// ---------------- L2 policy helpers ----------------
__device__ __forceinline__ uint64_t mkpol_evict_last()
{
    uint64_t p;
    asm("createpolicy.fractional.L2::evict_last.b64 %0;" : "=l"(p));
    return p;
}

__device__ __forceinline__ float ldg_keep(const float* p, uint64_t pol)
{
    float v;
    asm("ld.global.nc.L2::cache_hint.f32 %0, [%1], %2;" : "=f"(v) : "l"(p), "l"(pol));
    return v;
}

__device__ __forceinline__ float4 ldg4_keep(const float* p, uint64_t pol)
{
    float4 v;
    asm("ld.global.nc.L2::cache_hint.v4.f32 {%0,%1,%2,%3}, [%4], %5;"
        : "=f"(v.x), "=f"(v.y), "=f"(v.z), "=f"(v.w) : "l"(p), "l"(pol));
    return v;
}

// ---------------- tf32 helpers ----------------
__device__ __forceinline__ uint32_t f2tf(float x)
{
    uint32_t r;
    asm("cvt.rna.tf32.f32 %0, %1;" : "=r"(r) : "f"(x));
    return r;
}

__device__ __forceinline__ void split_tf32(float x, float& hi, float& lo)
{
    uint32_t h = f2tf(x);
    float hf = __uint_as_float(h);
    hi = hf;
    lo = __uint_as_float(f2tf(x - hf));
}

#define MMA_TF32(c, a, b) \
    asm volatile("mma.sync.aligned.m16n8k8.row.col.f32.tf32.tf32.f32 " \
                 "{%0,%1,%2,%3},{%4,%5,%6,%7},{%8,%9},{%0,%1,%2,%3};" \
                 : "+f"((c)[0]), "+f"((c)[1]), "+f"((c)[2]), "+f"((c)[3]) \
                 : "r"(__float_as_uint((a)[0])), "r"(__float_as_uint((a)[1])), \
                   "r"(__float_as_uint((a)[2])), "r"(__float_as_uint((a)[3])), \
                   "r"(__float_as_uint((b)[0])), "r"(__float_as_uint((b)[1])))

// ---------------- fc1: Y = relu(X @ W^T + b) via tf32x3 tensor cores ----------------
__global__ void __launch_bounds__(256) fc1_kernel(
    const float* __restrict__ X, const float* __restrict__ W,
    const float* __restrict__ bias, int N, int F, int nodeBase)
{
    __shared__ float Xhi[128][32];
    __shared__ float Xlo[128][32];
    __shared__ float Whi[64][32];
    __shared__ float Wlo[64][32];

    const int tid  = threadIdx.x;
    const int lane = tid & 31;
    const int warp = tid >> 5;
    const int warp_m = warp & 3;
    const int warp_n = warp >> 2;
    const int bm0 = blockIdx.x * 128;

    float c[2][4][4];
#pragma unroll
    for (int mt = 0; mt < 2; mt++)
#pragma unroll
        for (int nt = 0; nt < 4; nt++)
#pragma unroll
            for (int i = 0; i < 4; i++) c[mt][nt][i] = 0.f;

    const int lr = tid >> 3;
    const int lc = (tid & 7) * 4;

    for (int k0 = 0; k0 < F; k0 += 32) {
#pragma unroll
        for (int i = 0; i < 4; i++) {
            int r = lr + i * 32;
            int row = bm0 + r;
            float4 v = make_float4(0.f, 0.f, 0.f, 0.f);
            if (row < N) v = *(const float4*)&X[(long)row * F + k0 + lc];
            int sc = (lc + 4 * r) & 31;
            float h0, l0, h1, l1, h2, l2, h3, l3;
            split_tf32(v.x, h0, l0); split_tf32(v.y, h1, l1);
            split_tf32(v.z, h2, l2); split_tf32(v.w, h3, l3);
            *(float4*)&Xhi[r][sc] = make_float4(h0, h1, h2, h3);
            *(float4*)&Xlo[r][sc] = make_float4(l0, l1, l2, l3);
        }
#pragma unroll
        for (int i = 0; i < 2; i++) {
            int r = lr + i * 32;
            float4 v = *(const float4*)&W[(long)r * F + k0 + lc];
            int sc = (lc + 4 * r) & 31;
            float h0, l0, h1, l1, h2, l2, h3, l3;
            split_tf32(v.x, h0, l0); split_tf32(v.y, h1, l1);
            split_tf32(v.z, h2, l2); split_tf32(v.w, h3, l3);
            *(float4*)&Whi[r][sc] = make_float4(h0, h1, h2, h3);
            *(float4*)&Wlo[r][sc] = make_float4(l0, l1, l2, l3);
        }
        __syncthreads();

        const int ar = lane >> 2;
        const int ac = lane & 3;
#pragma unroll
        for (int ks = 0; ks < 4; ks++) {
            int kk = ks * 8;
            float ahi[2][4], alo[2][4], bhi[4][2], blo[4][2];
#pragma unroll
            for (int mt = 0; mt < 2; mt++) {
                int r0 = warp_m * 32 + mt * 16 + ar;
                int r1 = r0 + 8;
                int c0a = (kk + ac + 4 * r0) & 31;
                int c1a = (kk + ac + 4 * r1) & 31;
                int c0b = (kk + ac + 4 + 4 * r0) & 31;
                int c1b = (kk + ac + 4 + 4 * r1) & 31;
                ahi[mt][0] = Xhi[r0][c0a]; alo[mt][0] = Xlo[r0][c0a];
                ahi[mt][1] = Xhi[r1][c1a]; alo[mt][1] = Xlo[r1][c1a];
                ahi[mt][2] = Xhi[r0][c0b]; alo[mt][2] = Xlo[r0][c0b];
                ahi[mt][3] = Xhi[r1][c1b]; alo[mt][3] = Xlo[r1][c1b];
            }
#pragma unroll
            for (int nt = 0; nt < 4; nt++) {
                int n = warp_n * 32 + nt * 8 + ar;
                int c0a = (kk + ac + 4 * n) & 31;
                int c0b = (kk + ac + 4 + 4 * n) & 31;
                bhi[nt][0] = Whi[n][c0a]; blo[nt][0] = Wlo[n][c0a];
                bhi[nt][1] = Whi[n][c0b]; blo[nt][1] = Wlo[n][c0b];
            }
#pragma unroll
            for (int mt = 0; mt < 2; mt++)
#pragma unroll
                for (int nt = 0; nt < 4; nt++) {
                    MMA_TF32(c[mt][nt], ahi[mt], bhi[nt]);
                    MMA_TF32(c[mt][nt], ahi[mt], blo[nt]);
                    MMA_TF32(c[mt][nt], alo[mt], bhi[nt]);
                }
        }
        __syncthreads();
    }

#pragma unroll
    for (int mt = 0; mt < 2; mt++) {
#pragma unroll
        for (int nt = 0; nt < 4; nt++) {
            int row = bm0 + warp_m * 32 + mt * 16 + (lane >> 2);
            int col = warp_n * 32 + nt * 8 + (lane & 3) * 2;
            float b0 = __ldg(&bias[col]);
            float b1 = __ldg(&bias[col + 1]);
            if (row < N) {
                float v0 = fmaxf(c[mt][nt][0] + b0, 0.f);
                float v1 = fmaxf(c[mt][nt][1] + b1, 0.f);
                long o = (long)(nodeBase + row) * D + col;
                *(float2*)&g_x[o]  = make_float2(v0, v1);
                *(float2*)&g_hA[o] = make_float2(v0, v1);
            }
            if (row + 8 < N) {
                float v2 = fmaxf(c[mt][nt][2] + b0, 0.f);
                float v3 = fmaxf(c[mt][nt][3] + b1, 0.f);
                long o = (long)(nodeBase + row + 8) * D + col;
                *(float2*)&g_x[o]  = make_float2(v2, v3);
                *(float2*)&g_hA[o] = make_float2(v2, v3);
            }
        }
    }
}

// ---------------- CSR build ----------------
__global__ void zero_rowptr_kernel()
{
    int i = blockIdx.x * blockDim.x + threadIdx.x;
    if (i < RP_TOT) g_rowptr[i] = 0;
}

__global__ void hist_kernel(const int* __restrict__ ei_pa, const int* __restrict__ ei_ap,
                            const int* __restrict__ ei_ps, const int* __restrict__ ei_sp)
{
    int e = blockIdx.x * blockDim.x + threadIdx.x;
    if (e >= E_TOT) return;
    const int* ei; int l, rpb;
    if (e < E_PA)                   { ei = ei_pa; l = e;                      rpb = RP_PA; }
    else if (e < E_PA + E_AP)       { ei = ei_ap; l = e - E_PA;               rpb = RP_AP; }
    else if (e < E_PA + E_AP + E_PS){ ei = ei_ps; l = e - E_PA - E_AP;        rpb = RP_PS; }
    else                            { ei = ei_sp; l = e - E_PA - E_AP - E_PS; rpb = RP_SP; }
    atomicAdd(&g_rowptr[rpb + 1 + ei[l]], 1);
}

__global__ void scan_kernel()
{
    __shared__ int ssum[1024];
    int base, n;
    if (blockIdx.x == 0)      { base = RP_PA; n = NP + 1;  }
    else if (blockIdx.x == 1) { base = RP_AP; n = NA + 1;  }
    else if (blockIdx.x == 2) { base = RP_PS; n = NP + 1;  }
    else                      { base = RP_SP; n = NSU + 1; }
    int tid = threadIdx.x;
    int chunk = (n + 1023) >> 10;
    int s0 = tid * chunk;
    int s1 = s0 + chunk; if (s1 > n) s1 = n; if (s0 > n) s0 = n;

    int sum = 0;
    for (int j = s0; j < s1; j++) sum += g_rowptr[base + j];
    ssum[tid] = sum;
    __syncthreads();
    for (int off = 1; off < 1024; off <<= 1) {
        int v = (tid >= off) ? ssum[tid - off] : 0;
        __syncthreads();
        ssum[tid] += v;
        __syncthreads();
    }
    int run = (tid == 0) ? 0 : ssum[tid - 1];
    for (int j = s0; j < s1; j++) {
        run += g_rowptr[base + j];
        g_rowptr[base + j] = run;
        g_cursor[base + j] = run;
    }
}

__global__ void scatter_kernel(const int* __restrict__ ei_pa, const int* __restrict__ ei_ap,
                               const int* __restrict__ ei_ps, const int* __restrict__ ei_sp)
{
    int e = blockIdx.x * blockDim.x + threadIdx.x;
    if (e >= E_TOT) return;
    const int* ei; int l, rpb, cb, En;
    if (e < E_PA)                   { ei = ei_pa; l = e;                      rpb = RP_PA; cb = CB_PA; En = E_PA; }
    else if (e < E_PA + E_AP)       { ei = ei_ap; l = e - E_PA;               rpb = RP_AP; cb = CB_AP; En = E_AP; }
    else if (e < E_PA + E_AP + E_PS){ ei = ei_ps; l = e - E_PA - E_AP;        rpb = RP_PS; cb = CB_PS; En = E_PS; }
    else                            { ei = ei_sp; l = e - E_PA - E_AP - E_PS; rpb = RP_SP; cb = CB_SP; En = E_SP; }
    int s = ei[l];
    int t = ei[En + l];
    int pos = atomicAdd(&g_cursor[rpb + s], 1);
    g_col[cb + pos] = t;
}

// ---------------- reductions ----------------
__device__ __forceinline__ float wsum32(float v)
{
#pragma unroll
    for (int o = 16; o; o >>= 1) v += __shfl_xor_sync(0xffffffffu, v, o);
    return v;
}

__device__ __forceinline__ float wsum16(float v)
{
#pragma unroll
    for (int o = 8; o; o >>= 1) v += __shfl_xor_sync(0xffffffffu, v, o);
    return v;
}

// ---------------- one-time: source-side d1/w2 (all hops) + hop-0 target h1 ----------
__global__ void d1w2_kernel(const float* __restrict__ attn1, const float* __restrict__ attn2)
{
    int gw = (blockIdx.x * blockDim.x + threadIdx.x) >> 5;
    int lane = threadIdx.x & 31;
    if (gw >= NTOT) return;
    const float* xr = g_x + (long)gw * D;
    float x0 = xr[lane], x1 = xr[lane + 32];

    int k0, k1, base0, base1, l;
    if (gw < NP)            { l = gw;            k0 = 0; base0 = D1_PA; k1 = 2;  base1 = D1_PS; }
    else if (gw < NP + NA)  { l = gw - NP;       k0 = 1; base0 = D1_AP; k1 = -1; base1 = 0; }
    else                    { l = gw - NP - NA;  k0 = 3; base0 = D1_SP; k1 = -1; base1 = 0; }

#pragma unroll
    for (int hop = 0; hop < HOPS; hop++) {
        {
            const float* a1 = attn1 + (hop * 4 + k0) * D;
            const float* a2 = attn2 + (hop * 4 + k0) * D;
            float d1 = wsum32(x0 * a1[lane] + x1 * a1[lane + 32]);
            float d2 = wsum32(x0 * a2[lane] + x1 * a2[lane + 32]);
            float z = d1 + d2; z = z > 0.f ? z : 0.2f * z;
            if (lane == 0) {
                g_d1[hop * D1_TOT + base0 + l] = d1;
                g_w2[hop * D1_TOT + base0 + l] = __expf(z);
            }
        }
        if (k1 >= 0) {
            const float* a1 = attn1 + (hop * 4 + k1) * D;
            const float* a2 = attn2 + (hop * 4 + k1) * D;
            float d1 = wsum32(x0 * a1[lane] + x1 * a1[lane + 32]);
            float d2 = wsum32(x0 * a2[lane] + x1 * a2[lane + 32]);
            float z = d1 + d2; z = z > 0.f ? z : 0.2f * z;
            if (lane == 0) {
                g_d1[hop * D1_TOT + base1 + l] = d1;
                g_w2[hop * D1_TOT + base1 + l] = __expf(z);
            }
        }
    }

    // hop-0 target-side h1 (h == x at hop 0), written into buffer A
    if (gw < NP) {
        const float* a2a = attn2 + (0 * 4 + 1) * D;   // targets of ap edges
        const float* a2b = attn2 + (0 * 4 + 3) * D;   // targets of sp edges
        float va = wsum32(x0 * a2a[lane] + x1 * a2a[lane + 32]);
        float vb = wsum32(x0 * a2b[lane] + x1 * a2b[lane + 32]);
        if (lane == 0) { g_h1A[H1_AP + l] = va; g_h1A[H1_SP + l] = vb; }
    } else if (gw < NP + NA) {
        const float* a2a = attn2 + (0 * 4 + 0) * D;   // targets of pa edges
        float va = wsum32(x0 * a2a[lane] + x1 * a2a[lane + 32]);
        if (lane == 0) g_h1A[H1_PA + l] = va;
    } else {
        const float* a2a = attn2 + (0 * 4 + 2) * D;   // targets of ps edges
        float va = wsum32(x0 * a2a[lane] + x1 * a2a[lane + 32]);
        if (lane == 0) g_h1A[H1_PS + l] = va;
    }
}

// ---------------- per-hop aggregation: half-warp per node, L2-policied -------------
__device__ __forceinline__ void aggr_et_h(
    int nodeLocal, int rpBase, int colBase, int d1Base, int tOff, int hop,
    const float* __restrict__ h, const float* __restrict__ h1b, int hlane,
    uint64_t pol, const float4& x4, float wk, float4& acc)
{
    float d1 = g_d1[hop * D1_TOT + d1Base + nodeLocal];
    float w2 = g_w2[hop * D1_TOT + d1Base + nodeLocal];
    float4 num = make_float4(w2 * x4.x, w2 * x4.y, w2 * x4.z, w2 * x4.w);
    float div = w2;
    int e0 = g_rowptr[rpBase + nodeLocal];
    int e1 = g_rowptr[rpBase + nodeLocal + 1];
    const float* hb = h + (long)tOff * D;

    int e = e0;
    for (; e + 2 <= e1; e += 2) {
        int t0 = __ldcs(&g_col[colBase + e]);
        int t1 = __ldcs(&g_col[colBase + e + 1]);
        float p0 = ldg_keep(h1b + t0, pol);
        float p1 = ldg_keep(h1b + t1, pol);
        float4 u = ldg4_keep(hb + (long)t0 * D + 4 * hlane, pol);
        float4 v = ldg4_keep(hb + (long)t1 * D + 4 * hlane, pol);
        float z0 = d1 + p0; z0 = z0 > 0.f ? z0 : 0.2f * z0;
        float z1 = d1 + p1; z1 = z1 > 0.f ? z1 : 0.2f * z1;
        float w0 = __expf(z0);
        float w1 = __expf(z1);
        num.x += w0 * u.x + w1 * v.x;
        num.y += w0 * u.y + w1 * v.y;
        num.z += w0 * u.z + w1 * v.z;
        num.w += w0 * u.w + w1 * v.w;
        div   += w0 + w1;
    }
    if (e < e1) {
        int t = __ldcs(&g_col[colBase + e]);
        float zz = d1 + ldg_keep(h1b + t, pol);
        zz = zz > 0.f ? zz : 0.2f * zz;
        float w1 = __expf(zz);
        float4 u = ldg4_keep(hb + (long)t * D + 4 * hlane, pol);
        num.x += w1 * u.x; num.y += w1 * u.y; num.z += w1 * u.z; num.w += w1 * u.w;
        div   += w1;
    }
    float s = wk / div;
    acc.x += num.x * s; acc.y += num.y * s; acc.z += num.z * s; acc.w += num.w * s;
}

__global__ void __launch_bounds__(256) aggr_kernel(
    const float* __restrict__ attn2, const float* __restrict__ lw, int hop, int curB)
{
    int gn0 = (blockIdx.x * blockDim.x + threadIdx.x) >> 4;  // half-warp slot
    int hlane = threadIdx.x & 15;
    if (gn0 >= NTOT) return;
    // subject nodes first (highest degree -> avoid end-of-grid tail)
    int gn = (gn0 < NSU) ? (NP + NA + gn0) : (gn0 - NSU);
    uint64_t pol = mkpol_evict_last();
    const float* h   = curB ? g_hB : g_hA;
    float*       hn  = curB ? g_hA : g_hB;
    const float* h1r = (hop & 1) ? g_h1B : g_h1A;
    float*       h1w = (hop & 1) ? g_h1A : g_h1B;
    const float4 x4 = __ldcs((const float4*)(g_x + (long)gn * D + 4 * hlane));
    float4 acc = make_float4(0.f, 0.f, 0.f, 0.f);

    if (gn < NP) {
        float l0 = lw[hop * 4 + 0], l2 = lw[hop * 4 + 2];
        float m = fmaxf(l0, l2);
        float e0 = __expf(l0 - m), e2 = __expf(l2 - m);
        float inv = 1.f / (e0 + e2);
        aggr_et_h(gn, RP_PA, CB_PA, D1_PA, NP,      hop, h, h1r + H1_PA, hlane, pol, x4, e0 * inv, acc);
        aggr_et_h(gn, RP_PS, CB_PS, D1_PS, NP + NA, hop, h, h1r + H1_PS, hlane, pol, x4, e2 * inv, acc);
    } else if (gn < NP + NA) {
        aggr_et_h(gn - NP, RP_AP, CB_AP, D1_AP, 0,  hop, h, h1r + H1_AP, hlane, pol, x4, 1.f, acc);
    } else {
        aggr_et_h(gn - NP - NA, RP_SP, CB_SP, D1_SP, 0, hop, h, h1r + H1_SP, hlane, pol, x4, 1.f, acc);
    }
    acc.x = acc.x > 0.f ? acc.x : __expf(acc.x) - 1.f;
    acc.y = acc.y > 0.f ? acc.y : __expf(acc.y) - 1.f;
    acc.z = acc.z > 0.f ? acc.z : __expf(acc.z) - 1.f;
    acc.w = acc.w > 0.f ? acc.w : __expf(acc.w) - 1.f;
    __stcs((float4*)(hn + (long)gn * D + 4 * hlane), acc);

    // ---- fused: target-side h1 for the NEXT hop from the fresh hn row ----
    int nhop = hop + 1;
    if (nhop < HOPS) {
        if (gn < NP) {
            const float4 a2a = *(const float4*)(attn2 + (nhop * 4 + 1) * D + 4 * hlane);
            const float4 a2b = *(const float4*)(attn2 + (nhop * 4 + 3) * D + 4 * hlane);
            float va = wsum16(acc.x * a2a.x + acc.y * a2a.y + acc.z * a2a.z + acc.w * a2a.w);
            float vb = wsum16(acc.x * a2b.x + acc.y * a2b.y + acc.z * a2b.z + acc.w * a2b.w);
            if (hlane == 0) { h1w[H1_AP + gn] = va; h1w[H1_SP + gn] = vb; }
        } else if (gn < NP + NA) {
            const float4 a2a = *(const float4*)(attn2 + (nhop * 4 + 0) * D + 4 * hlane);
            float va = wsum16(acc.x * a2a.x + acc.y * a2a.y + acc.z * a2a.z + acc.w * a2a.w);
            if (hlane == 0) h1w[H1_PA + (gn - NP)] = va;
        } else {
            const float4 a2a = *(const float4*)(attn2 + (nhop * 4 + 2) * D + 4 * hlane);
            float va = wsum16(acc.x * a2a.x + acc.y * a2a.y + acc.z * a2a.z + acc.w * a2a.w);
            if (hlane == 0) h1w[H1_PS + (gn - NP - NA)] = va;
        }
    }
}

// ---------------- fc2: out = h_paper @ W^T + b (warp per node, W in smem) -----------
__global__ void __launch_bounds__(256) fc2_kernel(
    const float* __restrict__ W, const float* __restrict__ bias,
    float* __restrict__ out)
{
    __shared__ float Ws[NOUT * D];
    __shared__ float bs[NOUT];
    int tid = threadIdx.x;
    for (int i = tid; i < NOUT * D; i += 256) Ws[i] = W[i];
    if (tid < NOUT) bs[tid] = bias[tid];
    __syncthreads();

    int gw = (blockIdx.x * 256 + tid) >> 5;
    int lane = tid & 31;
    if (gw >= NP) return;
    const float* hr = g_hB + (long)gw * D;   // HOPS=5 -> final h in buffer B
    float v0 = hr[lane], v1 = hr[lane + 32];
    float res = 0.f;
#pragma unroll
    for (int o = 0; o < NOUT; o++) {
        float s = v0 * Ws[o * D + lane] + v1 * Ws[o * D + lane + 32];
        s = wsum32(s);
        if (lane == o) res = s;
    }
    if (lane < NOUT) out[gw * NOUT + lane] = res + bs[lane];
}

// ---------------- launch ----------------
extern "C" void kernel_launch(void* const* d_in, const int* in_sizes, int n_in,
                              void* d_out, int out_size)
{
    const float* x_paper   = (const float*)d_in[0];
    const float* x_author  = (const float*)d_in[1];
    const float* x_subject = (const float*)d_in[2];
    const float* fc1p_w = (const float*)d_in[3];
    const float* fc1p_b = (const float*)d_in[4];
    const float* fc1a_w = (const float*)d_in[5];
    const float* fc1a_b = (const float*)d_in[6];
    const float* fc1s_w = (const float*)d_in[7];
    const float* fc1s_b = (const float*)d_in[8];
    const float* attn1  = (const float*)d_in[9];
    const float* attn2  = (const float*)d_in[10];
    const float* lw     = (const float*)d_in[11];
    const float* fc2_w  = (const float*)d_in[12];
    const float* fc2_b  = (const float*)d_in[13];
    const int* ei_pa = (const int*)d_in[14];
    const int* ei_ap = (const int*)d_in[15];
    const int* ei_ps = (const int*)d_in[16];
    const int* ei_sp = (const int*)d_in[17];
    float* out = (float*)d_out;

    zero_rowptr_kernel<<<(RP_TOT + 255) / 256, 256>>>();

    fc1_kernel<<<(NP  + 127) / 128, 256>>>(x_paper,   fc1p_w, fc1p_b, NP,  512, 0);
    fc1_kernel<<<(NA  + 127) / 128, 256>>>(x_author,  fc1a_w, fc1a_b, NA,  256, NP);
    fc1_kernel<<<(NSU + 127) / 128, 256>>>(x_subject, fc1s_w, fc1s_b, NSU, 128, NP + NA);

    hist_kernel<<<(E_TOT + 255) / 256, 256>>>(ei_pa, ei_ap, ei_ps, ei_sp);
    scan_kernel<<<4, 1024>>>();
    scatter_kernel<<<(E_TOT + 255) / 256, 256>>>(ei_pa, ei_ap, ei_ps, ei_sp);

    d1w2_kernel<<<(NTOT * 32 + 255) / 256, 256>>>(attn1, attn2);

    for (int hop = 0; hop < HOPS; hop++) {
        int curB = hop & 1;
        aggr_kernel<<<(NTOT * 16 + 255) / 256, 256>>>(attn2, lw, hop, curB);
    }

    fc2_kernel<<<(NP * 32 + 255) / 256, 256>>>(fc2_w, fc2_b, out);
}

// round 13
// speedup vs baseline: 1.3745x; 1.0302x over previous
#include <cuda_runtime.h>
#include <cuda_fp16.h>
#include <cstdint>

// ---------------- problem constants ----------------
#define NP   100000
#define NA   200000
#define NSU  1000
#define NTOT (NP + NA + NSU)          // 301000
#define D    64
#define HOPS 5
#define NOUT 16

#define E_PA 800000
#define E_AP 800000
#define E_PS 100000
#define E_SP 100000
#define E_TOT (E_PA + E_AP + E_PS + E_SP)   // 1800000

// row_ptr segment bases (each segment length = Ns+1)
#define RP_PA 0
#define RP_AP (NP + 1)
#define RP_PS (RP_AP + NA + 1)
#define RP_SP (RP_PS + NP + 1)
#define RP_TOT (RP_SP + NSU + 1)

// col array bases
#define CB_PA 0
#define CB_AP E_PA
#define CB_PS (E_PA + E_AP)
#define CB_SP (E_PA + E_AP + E_PS)

// h1 (target-side attention score) bases
#define H1_PA 0                        // len NA  (targets: author)
#define H1_AP NA                       // len NP  (targets: paper)
#define H1_PS (NA + NP)                // len NSU (targets: subject)
#define H1_SP (NA + NP + NSU)          // len NP  (targets: paper)
#define H1_TOT (NA + NP + NSU + NP)    // 401000

// d1/w2 (source-side) segment bases, ordered [pa, ap, ps, sp]
#define D1_PA 0                        // len NP
#define D1_AP NP                       // len NA
#define D1_PS (NP + NA)                // len NP
#define D1_SP (NP + NA + NP)           // len NSU
#define D1_TOT (NP + NA + NP + NSU)    // 401000

#define H2W 32                         // half2 words per h row (64 halves)

// ---------------- scratch (static device memory; no runtime alloc) ----------------
__device__ float  g_x  [NTOT * D];
__device__ __half2 g_hA [NTOT * H2W];  // h double buffers in fp16
__device__ __half2 g_hB [NTOT * H2W];
__device__ float  g_h1A[H1_TOT];       // h1 double buffer (hop parity)
__device__ float  g_h1B[H1_TOT];
__device__ float  g_d1 [HOPS * D1_TOT];
__device__ float  g_w2 [HOPS * D1_TOT];
__device__ int    g_rowptr[RP_TOT];
__device__ int    g_cursor[RP_TOT];
__device__ int    g_col[E_TOT];

// ---------------- L2 policy helpers ----------------
__device__ __forceinline__ uint64_t mkpol_evict_last()
{
    uint64_t p;
    asm("createpolicy.fractional.L2::evict_last.b64 %0;" : "=l"(p));
    return p;
}

__device__ __forceinline__ float ldg_keep(const float* p, uint64_t pol)
{
    float v;
    asm("ld.global.nc.L2::cache_hint.f32 %0, [%1], %2;" : "=f"(v) : "l"(p), "l"(pol));
    return v;
}

__device__ __forceinline__ uint2 ldg2u_keep(const void* p, uint64_t pol)
{
    uint2 v;
    asm("ld.global.nc.L2::cache_hint.v2.u32 {%0,%1}, [%2], %3;"
        : "=r"(v.x), "=r"(v.y) : "l"(p), "l"(pol));
    return v;
}

// ---------------- tf32 helpers ----------------
__device__ __forceinline__ uint32_t f2tf(float x)
{
    uint32_t r;
    asm("cvt.rna.tf32.f32 %0, %1;" : "=r"(r) : "f"(x));
    return r;
}

__device__ __forceinline__ void split_tf32(float x, float& hi, float& lo)
{
    uint32_t h = f2tf(x);
    float hf = __uint_as_float(h);
    hi = hf;
    lo = __uint_as_float(f2tf(x - hf));
}

#define MMA_TF32(c, a, b) \
    asm volatile("mma.sync.aligned.m16n8k8.row.col.f32.tf32.tf32.f32 " \
                 "{%0,%1,%2,%3},{%4,%5,%6,%7},{%8,%9},{%0,%1,%2,%3};" \
                 : "+f"((c)[0]), "+f"((c)[1]), "+f"((c)[2]), "+f"((c)[3]) \
                 : "r"(__float_as_uint((a)[0])), "r"(__float_as_uint((a)[1])), \
                   "r"(__float_as_uint((a)[2])), "r"(__float_as_uint((a)[3])), \
                   "r"(__float_as_uint((b)[0])), "r"(__float_as_uint((b)[1])))

// ---------------- fc1: Y = relu(X @ W^T + b) via tf32x3 tensor cores ----------------
__global__ void __launch_bounds__(256) fc1_kernel(
    const float* __restrict__ X, const float* __restrict__ W,
    const float* __restrict__ bias, int N, int F, int nodeBase)
{
    __shared__ float Xhi[128][32];
    __shared__ float Xlo[128][32];
    __shared__ float Whi[64][32];
    __shared__ float Wlo[64][32];

    const int tid  = threadIdx.x;
    const int lane = tid & 31;
    const int warp = tid >> 5;
    const int warp_m = warp & 3;
    const int warp_n = warp >> 2;
    const int bm0 = blockIdx.x * 128;

    float c[2][4][4];
#pragma unroll
    for (int mt = 0; mt < 2; mt++)
#pragma unroll
        for (int nt = 0; nt < 4; nt++)
#pragma unroll
            for (int i = 0; i < 4; i++) c[mt][nt][i] = 0.f;

    const int lr = tid >> 3;
    const int lc = (tid & 7) * 4;

    for (int k0 = 0; k0 < F; k0 += 32) {
#pragma unroll
        for (int i = 0; i < 4; i++) {
            int r = lr + i * 32;
            int row = bm0 + r;
            float4 v = make_float4(0.f, 0.f, 0.f, 0.f);
            if (row < N) v = *(const float4*)&X[(long)row * F + k0 + lc];
            int sc = (lc + 4 * r) & 31;
            float h0, l0, h1, l1, h2, l2, h3, l3;
            split_tf32(v.x, h0, l0); split_tf32(v.y, h1, l1);
            split_tf32(v.z, h2, l2); split_tf32(v.w, h3, l3);
            *(float4*)&Xhi[r][sc] = make_float4(h0, h1, h2, h3);
            *(float4*)&Xlo[r][sc] = make_float4(l0, l1, l2, l3);
        }
#pragma unroll
        for (int i = 0; i < 2; i++) {
            int r = lr + i * 32;
            float4 v = *(const float4*)&W[(long)r * F + k0 + lc];
            int sc = (lc + 4 * r) & 31;
            float h0, l0, h1, l1, h2, l2, h3, l3;
            split_tf32(v.x, h0, l0); split_tf32(v.y, h1, l1);
            split_tf32(v.z, h2, l2); split_tf32(v.w, h3, l3);
            *(float4*)&Whi[r][sc] = make_float4(h0, h1, h2, h3);
            *(float4*)&Wlo[r][sc] = make_float4(l0, l1, l2, l3);
        }
        __syncthreads();

        const int ar = lane >> 2;
        const int ac = lane & 3;
#pragma unroll
        for (int ks = 0; ks < 4; ks++) {
            int kk = ks * 8;
            float ahi[2][4], alo[2][4], bhi[4][2], blo[4][2];
#pragma unroll
            for (int mt = 0; mt < 2; mt++) {
                int r0 = warp_m * 32 + mt * 16 + ar;
                int r1 = r0 + 8;
                int c0a = (kk + ac + 4 * r0) & 31;
                int c1a = (kk + ac + 4 * r1) & 31;
                int c0b = (kk + ac + 4 + 4 * r0) & 31;
                int c1b = (kk + ac + 4 + 4 * r1) & 31;
                ahi[mt][0] = Xhi[r0][c0a]; alo[mt][0] = Xlo[r0][c0a];
                ahi[mt][1] = Xhi[r1][c1a]; alo[mt][1] = Xlo[r1][c1a];
                ahi[mt][2] = Xhi[r0][c0b]; alo[mt][2] = Xlo[r0][c0b];
                ahi[mt][3] = Xhi[r1][c1b]; alo[mt][3] = Xlo[r1][c1b];
            }
#pragma unroll
            for (int nt = 0; nt < 4; nt++) {
                int n = warp_n * 32 + nt * 8 + ar;
                int c0a = (kk + ac + 4 * n) & 31;
                int c0b = (kk + ac + 4 + 4 * n) & 31;
                bhi[nt][0] = Whi[n][c0a]; blo[nt][0] = Wlo[n][c0a];
                bhi[nt][1] = Whi[n][c0b]; blo[nt][1] = Wlo[n][c0b];
            }
#pragma unroll
            for (int mt = 0; mt < 2; mt++)
#pragma unroll
                for (int nt = 0; nt < 4; nt++) {
                    MMA_TF32(c[mt][nt], ahi[mt], bhi[nt]);
                    MMA_TF32(c[mt][nt], ahi[mt], blo[nt]);
                    MMA_TF32(c[mt][nt], alo[mt], bhi[nt]);
                }
        }
        __syncthreads();
    }

#pragma unroll
    for (int mt = 0; mt < 2; mt++) {
#pragma unroll
        for (int nt = 0; nt < 4; nt++) {
            int row = bm0 + warp_m * 32 + mt * 16 + (lane >> 2);
            int col = warp_n * 32 + nt * 8 + (lane & 3) * 2;
            float b0 = __ldg(&bias[col]);
            float b1 = __ldg(&bias[col + 1]);
            if (row < N) {
                float v0 = fmaxf(c[mt][nt][0] + b0, 0.f);
                float v1 = fmaxf(c[mt][nt][1] + b1, 0.f);
                long node = nodeBase + row;
                *(float2*)&g_x[node * D + col] = make_float2(v0, v1);
                g_hA[node * H2W + (col >> 1)] = __floats2half2_rn(v0, v1);
            }
            if (row + 8 < N) {
                float v2 = fmaxf(c[mt][nt][2] + b0, 0.f);
                float v3 = fmaxf(c[mt][nt][3] + b1, 0.f);
                long node = nodeBase + row + 8;
                *(float2*)&g_x[node * D + col] = make_float2(v2, v3);
                g_hA[node * H2W + (col >> 1)] = __floats2half2_rn(v2, v3);
            }
        }
    }
}

// ---------------- CSR build ----------------
__global__ void zero_rowptr_kernel()
{
    int i = blockIdx.x * blockDim.x + threadIdx.x;
    if (i < RP_TOT) g_rowptr[i] = 0;
}

__global__ void hist_kernel(const int* __restrict__ ei_pa, const int* __restrict__ ei_ap,
                            const int* __restrict__ ei_ps, const int* __restrict__ ei_sp)
{
    int e = blockIdx.x * blockDim.x + threadIdx.x;
    if (e >= E_TOT) return;
    const int* ei; int l, rpb;
    if (e < E_PA)                   { ei = ei_pa; l = e;                      rpb = RP_PA; }
    else if (e < E_PA + E_AP)       { ei = ei_ap; l = e - E_PA;               rpb = RP_AP; }
    else if (e < E_PA + E_AP + E_PS){ ei = ei_ps; l = e - E_PA - E_AP;        rpb = RP_PS; }
    else                            { ei = ei_sp; l = e - E_PA - E_AP - E_PS; rpb = RP_SP; }
    atomicAdd(&g_rowptr[rpb + 1 + ei[l]], 1);
}

__global__ void scan_kernel()
{
    __shared__ int ssum[1024];
    int base, n;
    if (blockIdx.x == 0)      { base = RP_PA; n = NP + 1;  }
    else if (blockIdx.x == 1) { base = RP_AP; n = NA + 1;  }
    else if (blockIdx.x == 2) { base = RP_PS; n = NP + 1;  }
    else                      { base = RP_SP; n = NSU + 1; }
    int tid = threadIdx.x;
    int chunk = (n + 1023) >> 10;
    int s0 = tid * chunk;
    int s1 = s0 + chunk; if (s1 > n) s1 = n; if (s0 > n) s0 = n;

    int sum = 0;
    for (int j = s0; j < s1; j++) sum += g_rowptr[base + j];
    ssum[tid] = sum;
    __syncthreads();
    for (int off = 1; off < 1024; off <<= 1) {
        int v = (tid >= off) ? ssum[tid - off] : 0;
        __syncthreads();
        ssum[tid] += v;
        __syncthreads();
    }
    int run = (tid == 0) ? 0 : ssum[tid - 1];
    for (int j = s0; j < s1; j++) {
        run += g_rowptr[base + j];
        g_rowptr[base + j] = run;
        g_cursor[base + j] = run;
    }
}

__global__ void scatter_kernel(const int* __restrict__ ei_pa, const int* __restrict__ ei_ap,
                               const int* __restrict__ ei_ps, const int* __restrict__ ei_sp)
{
    int e = blockIdx.x * blockDim.x + threadIdx.x;
    if (e >= E_TOT) return;
    const int* ei; int l, rpb, cb, En;
    if (e < E_PA)                   { ei = ei_pa; l = e;                      rpb = RP_PA; cb = CB_PA; En = E_PA; }
    else if (e < E_PA + E_AP)       { ei = ei_ap; l = e - E_PA;               rpb = RP_AP; cb = CB_AP; En = E_AP; }
    else if (e < E_PA + E_AP + E_PS){ ei = ei_ps; l = e - E_PA - E_AP;        rpb = RP_PS; cb = CB_PS; En = E_PS; }
    else                            { ei = ei_sp; l = e - E_PA - E_AP - E_PS; rpb = RP_SP; cb = CB_SP; En = E_SP; }
    int s = ei[l];
    int t = ei[En + l];
    int pos = atomicAdd(&g_cursor[rpb + s], 1);
    g_col[cb + pos] = t;
}

// ---------------- reductions ----------------
__device__ __forceinline__ float wsum32(float v)
{
#pragma unroll
    for (int o = 16; o; o >>= 1) v += __shfl_xor_sync(0xffffffffu, v, o);
    return v;
}

__device__ __forceinline__ float wsum16(float v)
{
#pragma unroll
    for (int o = 8; o; o >>= 1) v += __shfl_xor_sync(0xffffffffu, v, o);
    return v;
}

// ---------------- one-time: source-side d1/w2 (all hops) + hop-0 target h1 ----------
__global__ void d1w2_kernel(const float* __restrict__ attn1, const float* __restrict__ attn2)
{
    int gw = (blockIdx.x * blockDim.x + threadIdx.x) >> 5;
    int lane = threadIdx.x & 31;
    if (gw >= NTOT) return;
    const float* xr = g_x + (long)gw * D;
    float x0 = xr[lane], x1 = xr[lane + 32];

    int k0, k1, base0, base1, l;
    if (gw < NP)            { l = gw;            k0 = 0; base0 = D1_PA; k1 = 2;  base1 = D1_PS; }
    else if (gw < NP + NA)  { l = gw - NP;       k0 = 1; base0 = D1_AP; k1 = -1; base1 = 0; }
    else                    { l = gw - NP - NA;  k0 = 3; base0 = D1_SP; k1 = -1; base1 = 0; }

#pragma unroll
    for (int hop = 0; hop < HOPS; hop++) {
        {
            const float* a1 = attn1 + (hop * 4 + k0) * D;
            const float* a2 = attn2 + (hop * 4 + k0) * D;
            float d1 = wsum32(x0 * a1[lane] + x1 * a1[lane + 32]);
            float d2 = wsum32(x0 * a2[lane] + x1 * a2[lane + 32]);
            float z = d1 + d2; z = z > 0.f ? z : 0.2f * z;
            if (lane == 0) {
                g_d1[hop * D1_TOT + base0 + l] = d1;
                g_w2[hop * D1_TOT + base0 + l] = __expf(z);
            }
        }
        if (k1 >= 0) {
            const float* a1 = attn1 + (hop * 4 + k1) * D;
            const float* a2 = attn2 + (hop * 4 + k1) * D;
            float d1 = wsum32(x0 * a1[lane] + x1 * a1[lane + 32]);
            float d2 = wsum32(x0 * a2[lane] + x1 * a2[lane + 32]);
            float z = d1 + d2; z = z > 0.f ? z : 0.2f * z;
            if (lane == 0) {
                g_d1[hop * D1_TOT + base1 + l] = d1;
                g_w2[hop * D1_TOT + base1 + l] = __expf(z);
            }
        }
    }

    // hop-0 target-side h1 (h == x at hop 0), written into buffer A
    if (gw < NP) {
        const float* a2a = attn2 + (0 * 4 + 1) * D;   // targets of ap edges
        const float* a2b = attn2 + (0 * 4 + 3) * D;   // targets of sp edges
        float va = wsum32(x0 * a2a[lane] + x1 * a2a[lane + 32]);
        float vb = wsum32(x0 * a2b[lane] + x1 * a2b[lane + 32]);
        if (lane == 0) { g_h1A[H1_AP + l] = va; g_h1A[H1_SP + l] = vb; }
    } else if (gw < NP + NA) {
        const float* a2a = attn2 + (0 * 4 + 0) * D;   // targets of pa edges
        float va = wsum32(x0 * a2a[lane] + x1 * a2a[lane + 32]);
        if (lane == 0) g_h1A[H1_PA + l] = va;
    } else {
        const float* a2a = attn2 + (0 * 4 + 2) * D;   // targets of ps edges
        float va = wsum32(x0 * a2a[lane] + x1 * a2a[lane + 32]);
        if (lane == 0) g_h1A[H1_PS + l] = va;
    }
}

// ---------------- per-hop aggregation: half-warp per node, fp16 h gather ------------
__device__ __forceinline__ void aggr_et_h(
    int nodeLocal, int rpBase, int colBase, int d1Base, int tOff, int hop,
    const __half2* __restrict__ h, const float* __restrict__ h1b, int hlane,
    uint64_t pol, const float4& x4, float wk, float4& acc)
{
    float d1 = g_d1[hop * D1_TOT + d1Base + nodeLocal];
    float w2 = g_w2[hop * D1_TOT + d1Base + nodeLocal];
    float4 num = make_float4(w2 * x4.x, w2 * x4.y, w2 * x4.z, w2 * x4.w);
    float div = w2;
    int e0 = g_rowptr[rpBase + nodeLocal];
    int e1 = g_rowptr[rpBase + nodeLocal + 1];
    const __half2* hb = h + (long)tOff * H2W + 2 * hlane;

    int e = e0;
    for (; e + 2 <= e1; e += 2) {
        int t0 = __ldcs(&g_col[colBase + e]);
        int t1 = __ldcs(&g_col[colBase + e + 1]);
        float p0 = ldg_keep(h1b + t0, pol);
        float p1 = ldg_keep(h1b + t1, pol);
        uint2 ru = ldg2u_keep(hb + (long)t0 * H2W, pol);
        uint2 rv = ldg2u_keep(hb + (long)t1 * H2W, pol);
        float2 u0 = __half22float2(*(__half2*)&ru.x);
        float2 u1 = __half22float2(*(__half2*)&ru.y);
        float2 v0 = __half22float2(*(__half2*)&rv.x);
        float2 v1 = __half22float2(*(__half2*)&rv.y);
        float z0 = d1 + p0; z0 = z0 > 0.f ? z0 : 0.2f * z0;
        float z1 = d1 + p1; z1 = z1 > 0.f ? z1 : 0.2f * z1;
        float w0 = __expf(z0);
        float w1 = __expf(z1);
        num.x += w0 * u0.x + w1 * v0.x;
        num.y += w0 * u0.y + w1 * v0.y;
        num.z += w0 * u1.x + w1 * v1.x;
        num.w += w0 * u1.y + w1 * v1.y;
        div   += w0 + w1;
    }
    if (e < e1) {
        int t = __ldcs(&g_col[colBase + e]);
        float zz = d1 + ldg_keep(h1b + t, pol);
        zz = zz > 0.f ? zz : 0.2f * zz;
        float w1 = __expf(zz);
        uint2 ru = ldg2u_keep(hb + (long)t * H2W, pol);
        float2 u0 = __half22float2(*(__half2*)&ru.x);
        float2 u1 = __half22float2(*(__half2*)&ru.y);
        num.x += w1 * u0.x; num.y += w1 * u0.y;
        num.z += w1 * u1.x; num.w += w1 * u1.y;
        div   += w1;
    }
    float s = wk / div;
    acc.x += num.x * s; acc.y += num.y * s; acc.z += num.z * s; acc.w += num.w * s;
}

__global__ void __launch_bounds__(256) aggr_kernel(
    const float* __restrict__ attn2, const float* __restrict__ lw, int hop, int curB)
{
    int gn0 = (blockIdx.x * blockDim.x + threadIdx.x) >> 4;  // half-warp slot
    int hlane = threadIdx.x & 15;
    if (gn0 >= NTOT) return;
    // subject nodes first (highest degree -> avoid end-of-grid tail)
    int gn = (gn0 < NSU) ? (NP + NA + gn0) : (gn0 - NSU);
    uint64_t pol = mkpol_evict_last();
    const __half2* h  = curB ? g_hB : g_hA;
    __half2*       hn = curB ? g_hA : g_hB;
    const float* h1r = (hop & 1) ? g_h1B : g_h1A;
    float*       h1w = (hop & 1) ? g_h1A : g_h1B;
    const float4 x4 = __ldcs((const float4*)(g_x + (long)gn * D + 4 * hlane));
    float4 acc = make_float4(0.f, 0.f, 0.f, 0.f);

    if (gn < NP) {
        float l0 = lw[hop * 4 + 0], l2 = lw[hop * 4 + 2];
        float m = fmaxf(l0, l2);
        float e0 = __expf(l0 - m), e2 = __expf(l2 - m);
        float inv = 1.f / (e0 + e2);
        aggr_et_h(gn, RP_PA, CB_PA, D1_PA, NP,      hop, h, h1r + H1_PA, hlane, pol, x4, e0 * inv, acc);
        aggr_et_h(gn, RP_PS, CB_PS, D1_PS, NP + NA, hop, h, h1r + H1_PS, hlane, pol, x4, e2 * inv, acc);
    } else if (gn < NP + NA) {
        aggr_et_h(gn - NP, RP_AP, CB_AP, D1_AP, 0,  hop, h, h1r + H1_AP, hlane, pol, x4, 1.f, acc);
    } else {
        aggr_et_h(gn - NP - NA, RP_SP, CB_SP, D1_SP, 0, hop, h, h1r + H1_SP, hlane, pol, x4, 1.f, acc);
    }
    acc.x = acc.x > 0.f ? acc.x : __expf(acc.x) - 1.f;
    acc.y = acc.y > 0.f ? acc.y : __expf(acc.y) - 1.f;
    acc.z = acc.z > 0.f ? acc.z : __expf(acc.z) - 1.f;
    acc.w = acc.w > 0.f ? acc.w : __expf(acc.w) - 1.f;
    {
        uint2 packed;
        *(__half2*)&packed.x = __floats2half2_rn(acc.x, acc.y);
        *(__half2*)&packed.y = __floats2half2_rn(acc.z, acc.w);
        __stcs((uint2*)(hn + (long)gn * H2W + 2 * hlane), packed);
    }

    // ---- fused: target-side h1 for the NEXT hop from the fresh hn row ----
    int nhop = hop + 1;
    if (nhop < HOPS) {
        if (gn < NP) {
            const float4 a2a = *(const float4*)(attn2 + (nhop * 4 + 1) * D + 4 * hlane);
            const float4 a2b = *(const float4*)(attn2 + (nhop * 4 + 3) * D + 4 * hlane);
            float va = wsum16(acc.x * a2a.x + acc.y * a2a.y + acc.z * a2a.z + acc.w * a2a.w);
            float vb = wsum16(acc.x * a2b.x + acc.y * a2b.y + acc.z * a2b.z + acc.w * a2b.w);
            if (hlane == 0) { h1w[H1_AP + gn] = va; h1w[H1_SP + gn] = vb; }
        } else if (gn < NP + NA) {
            const float4 a2a = *(const float4*)(attn2 + (nhop * 4 + 0) * D + 4 * hlane);
            float va = wsum16(acc.x * a2a.x + acc.y * a2a.y + acc.z * a2a.z + acc.w * a2a.w);
            if (hlane == 0) h1w[H1_PA + (gn - NP)] = va;
        } else {
            const float4 a2a = *(const float4*)(attn2 + (nhop * 4 + 2) * D + 4 * hlane);
            float va = wsum16(acc.x * a2a.x + acc.y * a2a.y + acc.z * a2a.z + acc.w * a2a.w);
            if (hlane == 0) h1w[H1_PS + (gn - NP - NA)] = va;
        }
    }
}

// ---------------- fc2: out = h_paper @ W^T + b (warp per node, W in smem) -----------
// Lane l owns half2 word l of the node's 32-word row -> dims 2l, 2l+1.
// Max Ws index: 15*64 + 63 = 1023 < 1024. Max g_hB index: (NP-1)*32 + 31 < NTOT*32.
__global__ void __launch_bounds__(256) fc2_kernel(
    const float* __restrict__ W, const float* __restrict__ bias,
    float* __restrict__ out)
{
    __shared__ float Ws[NOUT * D];
    __shared__ float bs[NOUT];
    int tid = threadIdx.x;
    for (int i = tid; i < NOUT * D; i += 256) Ws[i] = W[i];
    if (tid < NOUT) bs[tid] = bias[tid];
    __syncthreads();

    int gw = (blockIdx.x * 256 + tid) >> 5;
    int lane = tid & 31;
    if (gw >= NP) return;
    // HOPS=5 -> final h in buffer B (fp16)
    float2 p = __half22float2(g_hB[(long)gw * H2W + lane]);
    float res = 0.f;
#pragma unroll
    for (int o = 0; o < NOUT; o++) {
        float s = p.x * Ws[o * D + 2 * lane] + p.y * Ws[o * D + 2 * lane + 1];
        s = wsum32(s);
        if (lane == o) res = s;
    }
    if (lane < NOUT) out[gw * NOUT + lane] = res + bs[lane];
}

// ---------------- launch ----------------
extern "C" void kernel_launch(void* const* d_in, const int* in_sizes, int n_in,
                              void* d_out, int out_size)
{
    const float* x_paper   = (const float*)d_in[0];
    const float* x_author  = (const float*)d_in[1];
    const float* x_subject = (const float*)d_in[2];
    const float* fc1p_w = (const float*)d_in[3];
    const float* fc1p_b = (const float*)d_in[4];
    const float* fc1a_w = (const float*)d_in[5];
    const float* fc1a_b = (const float*)d_in[6];
    const float* fc1s_w = (const float*)d_in[7];
    const float* fc1s_b = (const float*)d_in[8];
    const float* attn1  = (const float*)d_in[9];
    const float* attn2  = (const float*)d_in[10];
    const float* lw     = (const float*)d_in[11];
    const float* fc2_w  = (const float*)d_in[12];
    const float* fc2_b  = (const float*)d_in[13];
    const int* ei_pa = (const int*)d_in[14];
    const int* ei_ap = (const int*)d_in[15];
    const int* ei_ps = (const int*)d_in[16];
    const int* ei_sp = (const int*)d_in[17];
    float* out = (float*)d_out;

    zero_rowptr_kernel<<<(RP_TOT + 255) / 256, 256>>>();

    fc1_kernel<<<(NP  + 127) / 128, 256>>>(x_paper,   fc1p_w, fc1p_b, NP,  512, 0);
    fc1_kernel<<<(NA  + 127) / 128, 256>>>(x_author,  fc1a_w, fc1a_b, NA,  256, NP);
    fc1_kernel<<<(NSU + 127) / 128, 256>>>(x_subject, fc1s_w, fc1s_b, NSU, 128, NP + NA);

    hist_kernel<<<(E_TOT + 255) / 256, 256>>>(ei_pa, ei_ap, ei_ps, ei_sp);
    scan_kernel<<<4, 1024>>>();
    scatter_kernel<<<(E_TOT + 255) / 256, 256>>>(ei_pa, ei_ap, ei_ps, ei_sp);

    d1w2_kernel<<<(NTOT * 32 + 255) / 256, 256>>>(attn1, attn2);

    for (int hop = 0; hop < HOPS; hop++) {
        int curB = hop & 1;
        aggr_kernel<<<(NTOT * 16 + 255) / 256, 256>>>(attn2, lw, hop, curB);
    }

    fc2_kernel<<<(NP * 32 + 255) / 256, 256>>>(fc2_w, fc2_b, out);
}

// round 14
// speedup vs baseline: 1.4327x; 1.0424x over previous
#include <cuda_runtime.h>
#include <cuda_fp16.h>
#include <cstdint>

// ---------------- problem constants ----------------
#define NP   100000
#define NA   200000
#define NSU  1000
#define NTOT (NP + NA + NSU)          // 301000
#define D    64
#define HOPS 5
#define NOUT 16

#define E_PA 800000
#define E_AP 800000
#define E_PS 100000
#define E_SP 100000
#define E_TOT (E_PA + E_AP + E_PS + E_SP)   // 1800000

// row_ptr segment bases (each segment length = Ns+1)
#define RP_PA 0
#define RP_AP (NP + 1)
#define RP_PS (RP_AP + NA + 1)
#define RP_SP (RP_PS + NP + 1)
#define RP_TOT (RP_SP + NSU + 1)

// col array bases
#define CB_PA 0
#define CB_AP E_PA
#define CB_PS (E_PA + E_AP)
#define CB_SP (E_PA + E_AP + E_PS)

// h1 (target-side attention score) bases
#define H1_PA 0                        // len NA  (targets: author)
#define H1_AP NA                       // len NP  (targets: paper)
#define H1_PS (NA + NP)                // len NSU (targets: subject)
#define H1_SP (NA + NP + NSU)          // len NP  (targets: paper)
#define H1_TOT (NA + NP + NSU + NP)    // 401000

// d1/w2 (source-side) segment bases, ordered [pa, ap, ps, sp]
#define D1_PA 0                        // len NP
#define D1_AP NP                       // len NA
#define D1_PS (NP + NA)                // len NP
#define D1_SP (NP + NA + NP)           // len NSU
#define D1_TOT (NP + NA + NP + NSU)    // 401000

#define H2W 32                         // half2 words per h row (64 halves)

// ---------------- scratch (static device memory; no runtime alloc) ----------------
__device__ float  g_x  [NTOT * D];
__device__ __half2 g_hA [NTOT * H2W];  // h double buffers in fp16
__device__ __half2 g_hB [NTOT * H2W];
__device__ float  g_h1A[H1_TOT];       // h1 double buffer (hop parity)
__device__ float  g_h1B[H1_TOT];
__device__ float  g_d1 [HOPS * D1_TOT];
__device__ float  g_w2 [HOPS * D1_TOT];
__device__ int    g_rowptr[RP_TOT];
__device__ int    g_cursor[RP_TOT];
__device__ int    g_col[E_TOT];

// ---------------- L2 policy helpers ----------------
__device__ __forceinline__ uint64_t mkpol_evict_last()
{
    uint64_t p;
    asm("createpolicy.fractional.L2::evict_last.b64 %0;" : "=l"(p));
    return p;
}

__device__ __forceinline__ float ldg_keep(const float* p, uint64_t pol)
{
    float v;
    asm("ld.global.nc.L2::cache_hint.f32 %0, [%1], %2;" : "=f"(v) : "l"(p), "l"(pol));
    return v;
}

__device__ __forceinline__ uint2 ldg2u_keep(const void* p, uint64_t pol)
{
    uint2 v;
    asm("ld.global.nc.L2::cache_hint.v2.u32 {%0,%1}, [%2], %3;"
        : "=r"(v.x), "=r"(v.y) : "l"(p), "l"(pol));
    return v;
}

// ---------------- tf32 helpers ----------------
__device__ __forceinline__ uint32_t f2tf(float x)
{
    uint32_t r;
    asm("cvt.rna.tf32.f32 %0, %1;" : "=r"(r) : "f"(x));
    return r;
}

__device__ __forceinline__ void split_tf32(float x, float& hi, float& lo)
{
    uint32_t h = f2tf(x);
    float hf = __uint_as_float(h);
    hi = hf;
    lo = __uint_as_float(f2tf(x - hf));
}

#define MMA_TF32(c, a, b) \
    asm volatile("mma.sync.aligned.m16n8k8.row.col.f32.tf32.tf32.f32 " \
                 "{%0,%1,%2,%3},{%4,%5,%6,%7},{%8,%9},{%0,%1,%2,%3};" \
                 : "+f"((c)[0]), "+f"((c)[1]), "+f"((c)[2]), "+f"((c)[3]) \
                 : "r"(__float_as_uint((a)[0])), "r"(__float_as_uint((a)[1])), \
                   "r"(__float_as_uint((a)[2])), "r"(__float_as_uint((a)[3])), \
                   "r"(__float_as_uint((b)[0])), "r"(__float_as_uint((b)[1])))

// ---------------- fc1: Y = relu(X @ W^T + b) via tf32x3 tensor cores ----------------
__global__ void __launch_bounds__(256) fc1_kernel(
    const float* __restrict__ X, const float* __restrict__ W,
    const float* __restrict__ bias, int N, int F, int nodeBase)
{
    __shared__ float Xhi[128][32];
    __shared__ float Xlo[128][32];
    __shared__ float Whi[64][32];
    __shared__ float Wlo[64][32];

    const int tid  = threadIdx.x;
    const int lane = tid & 31;
    const int warp = tid >> 5;
    const int warp_m = warp & 3;
    const int warp_n = warp >> 2;
    const int bm0 = blockIdx.x * 128;

    float c[2][4][4];
#pragma unroll
    for (int mt = 0; mt < 2; mt++)
#pragma unroll
        for (int nt = 0; nt < 4; nt++)
#pragma unroll
            for (int i = 0; i < 4; i++) c[mt][nt][i] = 0.f;

    const int lr = tid >> 3;
    const int lc = (tid & 7) * 4;

    for (int k0 = 0; k0 < F; k0 += 32) {
#pragma unroll
        for (int i = 0; i < 4; i++) {
            int r = lr + i * 32;
            int row = bm0 + r;
            float4 v = make_float4(0.f, 0.f, 0.f, 0.f);
            if (row < N) v = *(const float4*)&X[(long)row * F + k0 + lc];
            int sc = (lc + 4 * r) & 31;
            float h0, l0, h1, l1, h2, l2, h3, l3;
            split_tf32(v.x, h0, l0); split_tf32(v.y, h1, l1);
            split_tf32(v.z, h2, l2); split_tf32(v.w, h3, l3);
            *(float4*)&Xhi[r][sc] = make_float4(h0, h1, h2, h3);
            *(float4*)&Xlo[r][sc] = make_float4(l0, l1, l2, l3);
        }
#pragma unroll
        for (int i = 0; i < 2; i++) {
            int r = lr + i * 32;
            float4 v = *(const float4*)&W[(long)r * F + k0 + lc];
            int sc = (lc + 4 * r) & 31;
            float h0, l0, h1, l1, h2, l2, h3, l3;
            split_tf32(v.x, h0, l0); split_tf32(v.y, h1, l1);
            split_tf32(v.z, h2, l2); split_tf32(v.w, h3, l3);
            *(float4*)&Whi[r][sc] = make_float4(h0, h1, h2, h3);
            *(float4*)&Wlo[r][sc] = make_float4(l0, l1, l2, l3);
        }
        __syncthreads();

        const int ar = lane >> 2;
        const int ac = lane & 3;
#pragma unroll
        for (int ks = 0; ks < 4; ks++) {
            int kk = ks * 8;
            float ahi[2][4], alo[2][4], bhi[4][2], blo[4][2];
#pragma unroll
            for (int mt = 0; mt < 2; mt++) {
                int r0 = warp_m * 32 + mt * 16 + ar;
                int r1 = r0 + 8;
                int c0a = (kk + ac + 4 * r0) & 31;
                int c1a = (kk + ac + 4 * r1) & 31;
                int c0b = (kk + ac + 4 + 4 * r0) & 31;
                int c1b = (kk + ac + 4 + 4 * r1) & 31;
                ahi[mt][0] = Xhi[r0][c0a]; alo[mt][0] = Xlo[r0][c0a];
                ahi[mt][1] = Xhi[r1][c1a]; alo[mt][1] = Xlo[r1][c1a];
                ahi[mt][2] = Xhi[r0][c0b]; alo[mt][2] = Xlo[r0][c0b];
                ahi[mt][3] = Xhi[r1][c1b]; alo[mt][3] = Xlo[r1][c1b];
            }
#pragma unroll
            for (int nt = 0; nt < 4; nt++) {
                int n = warp_n * 32 + nt * 8 + ar;
                int c0a = (kk + ac + 4 * n) & 31;
                int c0b = (kk + ac + 4 + 4 * n) & 31;
                bhi[nt][0] = Whi[n][c0a]; blo[nt][0] = Wlo[n][c0a];
                bhi[nt][1] = Whi[n][c0b]; blo[nt][1] = Wlo[n][c0b];
            }
#pragma unroll
            for (int mt = 0; mt < 2; mt++)
#pragma unroll
                for (int nt = 0; nt < 4; nt++) {
                    MMA_TF32(c[mt][nt], ahi[mt], bhi[nt]);
                    MMA_TF32(c[mt][nt], ahi[mt], blo[nt]);
                    MMA_TF32(c[mt][nt], alo[mt], bhi[nt]);
                }
        }
        __syncthreads();
    }

#pragma unroll
    for (int mt = 0; mt < 2; mt++) {
#pragma unroll
        for (int nt = 0; nt < 4; nt++) {
            int row = bm0 + warp_m * 32 + mt * 16 + (lane >> 2);
            int col = warp_n * 32 + nt * 8 + (lane & 3) * 2;
            float b0 = __ldg(&bias[col]);
            float b1 = __ldg(&bias[col + 1]);
            if (row < N) {
                float v0 = fmaxf(c[mt][nt][0] + b0, 0.f);
                float v1 = fmaxf(c[mt][nt][1] + b1, 0.f);
                long node = nodeBase + row;
                *(float2*)&g_x[node * D + col] = make_float2(v0, v1);
                g_hA[node * H2W + (col >> 1)] = __floats2half2_rn(v0, v1);
            }
            if (row + 8 < N) {
                float v2 = fmaxf(c[mt][nt][2] + b0, 0.f);
                float v3 = fmaxf(c[mt][nt][3] + b1, 0.f);
                long node = nodeBase + row + 8;
                *(float2*)&g_x[node * D + col] = make_float2(v2, v3);
                g_hA[node * H2W + (col >> 1)] = __floats2half2_rn(v2, v3);
            }
        }
    }
}

// ---------------- CSR build ----------------
__global__ void zero_rowptr_kernel()
{
    int i = blockIdx.x * blockDim.x + threadIdx.x;
    if (i < RP_TOT) g_rowptr[i] = 0;
}

__global__ void hist_kernel(const int* __restrict__ ei_pa, const int* __restrict__ ei_ap,
                            const int* __restrict__ ei_ps, const int* __restrict__ ei_sp)
{
    int e = blockIdx.x * blockDim.x + threadIdx.x;
    if (e >= E_TOT) return;
    const int* ei; int l, rpb;
    if (e < E_PA)                   { ei = ei_pa; l = e;                      rpb = RP_PA; }
    else if (e < E_PA + E_AP)       { ei = ei_ap; l = e - E_PA;               rpb = RP_AP; }
    else if (e < E_PA + E_AP + E_PS){ ei = ei_ps; l = e - E_PA - E_AP;        rpb = RP_PS; }
    else                            { ei = ei_sp; l = e - E_PA - E_AP - E_PS; rpb = RP_SP; }
    atomicAdd(&g_rowptr[rpb + 1 + ei[l]], 1);
}

__global__ void scan_kernel()
{
    __shared__ int ssum[1024];
    int base, n;
    if (blockIdx.x == 0)      { base = RP_PA; n = NP + 1;  }
    else if (blockIdx.x == 1) { base = RP_AP; n = NA + 1;  }
    else if (blockIdx.x == 2) { base = RP_PS; n = NP + 1;  }
    else                      { base = RP_SP; n = NSU + 1; }
    int tid = threadIdx.x;
    int chunk = (n + 1023) >> 10;
    int s0 = tid * chunk;
    int s1 = s0 + chunk; if (s1 > n) s1 = n; if (s0 > n) s0 = n;

    int sum = 0;
    for (int j = s0; j < s1; j++) sum += g_rowptr[base + j];
    ssum[tid] = sum;
    __syncthreads();
    for (int off = 1; off < 1024; off <<= 1) {
        int v = (tid >= off) ? ssum[tid - off] : 0;
        __syncthreads();
        ssum[tid] += v;
        __syncthreads();
    }
    int run = (tid == 0) ? 0 : ssum[tid - 1];
    for (int j = s0; j < s1; j++) {
        run += g_rowptr[base + j];
        g_rowptr[base + j] = run;
        g_cursor[base + j] = run;
    }
}

__global__ void scatter_kernel(const int* __restrict__ ei_pa, const int* __restrict__ ei_ap,
                               const int* __restrict__ ei_ps, const int* __restrict__ ei_sp)
{
    int e = blockIdx.x * blockDim.x + threadIdx.x;
    if (e >= E_TOT) return;
    const int* ei; int l, rpb, cb, En;
    if (e < E_PA)                   { ei = ei_pa; l = e;                      rpb = RP_PA; cb = CB_PA; En = E_PA; }
    else if (e < E_PA + E_AP)       { ei = ei_ap; l = e - E_PA;               rpb = RP_AP; cb = CB_AP; En = E_AP; }
    else if (e < E_PA + E_AP + E_PS){ ei = ei_ps; l = e - E_PA - E_AP;        rpb = RP_PS; cb = CB_PS; En = E_PS; }
    else                            { ei = ei_sp; l = e - E_PA - E_AP - E_PS; rpb = RP_SP; cb = CB_SP; En = E_SP; }
    int s = ei[l];
    int t = ei[En + l];
    int pos = atomicAdd(&g_cursor[rpb + s], 1);
    g_col[cb + pos] = t;
}

// ---------------- reductions ----------------
__device__ __forceinline__ float wsum32(float v)
{
#pragma unroll
    for (int o = 16; o; o >>= 1) v += __shfl_xor_sync(0xffffffffu, v, o);
    return v;
}

__device__ __forceinline__ float wsum16(float v)
{
#pragma unroll
    for (int o = 8; o; o >>= 1) v += __shfl_xor_sync(0xffffffffu, v, o);
    return v;
}

// ---------------- one-time: source-side d1/w2 + hop-0 target h1 ----------
// Author/subject skip hop HOPS-1 (their final-hop aggregation is dead work).
__global__ void d1w2_kernel(const float* __restrict__ attn1, const float* __restrict__ attn2)
{
    int gw = (blockIdx.x * blockDim.x + threadIdx.x) >> 5;
    int lane = threadIdx.x & 31;
    if (gw >= NTOT) return;
    const float* xr = g_x + (long)gw * D;
    float x0 = xr[lane], x1 = xr[lane + 32];

    int k0, k1, base0, base1, l;
    if (gw < NP)            { l = gw;            k0 = 0; base0 = D1_PA; k1 = 2;  base1 = D1_PS; }
    else if (gw < NP + NA)  { l = gw - NP;       k0 = 1; base0 = D1_AP; k1 = -1; base1 = 0; }
    else                    { l = gw - NP - NA;  k0 = 3; base0 = D1_SP; k1 = -1; base1 = 0; }

#pragma unroll
    for (int hop = 0; hop < HOPS; hop++) {
        if (k1 >= 0 || hop < HOPS - 1) {
            const float* a1 = attn1 + (hop * 4 + k0) * D;
            const float* a2 = attn2 + (hop * 4 + k0) * D;
            float d1 = wsum32(x0 * a1[lane] + x1 * a1[lane + 32]);
            float d2 = wsum32(x0 * a2[lane] + x1 * a2[lane + 32]);
            float z = d1 + d2; z = z > 0.f ? z : 0.2f * z;
            if (lane == 0) {
                g_d1[hop * D1_TOT + base0 + l] = d1;
                g_w2[hop * D1_TOT + base0 + l] = __expf(z);
            }
        }
        if (k1 >= 0) {
            const float* a1 = attn1 + (hop * 4 + k1) * D;
            const float* a2 = attn2 + (hop * 4 + k1) * D;
            float d1 = wsum32(x0 * a1[lane] + x1 * a1[lane + 32]);
            float d2 = wsum32(x0 * a2[lane] + x1 * a2[lane + 32]);
            float z = d1 + d2; z = z > 0.f ? z : 0.2f * z;
            if (lane == 0) {
                g_d1[hop * D1_TOT + base1 + l] = d1;
                g_w2[hop * D1_TOT + base1 + l] = __expf(z);
            }
        }
    }

    // hop-0 target-side h1 (h == x at hop 0), written into buffer A
    if (gw < NP) {
        const float* a2a = attn2 + (0 * 4 + 1) * D;   // targets of ap edges
        const float* a2b = attn2 + (0 * 4 + 3) * D;   // targets of sp edges
        float va = wsum32(x0 * a2a[lane] + x1 * a2a[lane + 32]);
        float vb = wsum32(x0 * a2b[lane] + x1 * a2b[lane + 32]);
        if (lane == 0) { g_h1A[H1_AP + l] = va; g_h1A[H1_SP + l] = vb; }
    } else if (gw < NP + NA) {
        const float* a2a = attn2 + (0 * 4 + 0) * D;   // targets of pa edges
        float va = wsum32(x0 * a2a[lane] + x1 * a2a[lane + 32]);
        if (lane == 0) g_h1A[H1_PA + l] = va;
    } else {
        const float* a2a = attn2 + (0 * 4 + 2) * D;   // targets of ps edges
        float va = wsum32(x0 * a2a[lane] + x1 * a2a[lane + 32]);
        if (lane == 0) g_h1A[H1_PS + l] = va;
    }
}

// ---------------- shared inner loop: half-warp per node, fp16 h gather --------------
__device__ __forceinline__ void aggr_et_h(
    int nodeLocal, int rpBase, int colBase, int d1Base, int tOff, int hop,
    const __half2* __restrict__ h, const float* __restrict__ h1b, int hlane,
    uint64_t pol, const float4& x4, float wk, float4& acc)
{
    float d1 = g_d1[hop * D1_TOT + d1Base + nodeLocal];
    float w2 = g_w2[hop * D1_TOT + d1Base + nodeLocal];
    float4 num = make_float4(w2 * x4.x, w2 * x4.y, w2 * x4.z, w2 * x4.w);
    float div = w2;
    int e0 = g_rowptr[rpBase + nodeLocal];
    int e1 = g_rowptr[rpBase + nodeLocal + 1];
    const __half2* hb = h + (long)tOff * H2W + 2 * hlane;

    int e = e0;
    for (; e + 2 <= e1; e += 2) {
        int t0 = __ldcs(&g_col[colBase + e]);
        int t1 = __ldcs(&g_col[colBase + e + 1]);
        float p0 = ldg_keep(h1b + t0, pol);
        float p1 = ldg_keep(h1b + t1, pol);
        uint2 ru = ldg2u_keep(hb + (long)t0 * H2W, pol);
        uint2 rv = ldg2u_keep(hb + (long)t1 * H2W, pol);
        float2 u0 = __half22float2(*(__half2*)&ru.x);
        float2 u1 = __half22float2(*(__half2*)&ru.y);
        float2 v0 = __half22float2(*(__half2*)&rv.x);
        float2 v1 = __half22float2(*(__half2*)&rv.y);
        float z0 = d1 + p0; z0 = z0 > 0.f ? z0 : 0.2f * z0;
        float z1 = d1 + p1; z1 = z1 > 0.f ? z1 : 0.2f * z1;
        float w0 = __expf(z0);
        float w1 = __expf(z1);
        num.x += w0 * u0.x + w1 * v0.x;
        num.y += w0 * u0.y + w1 * v0.y;
        num.z += w0 * u1.x + w1 * v1.x;
        num.w += w0 * u1.y + w1 * v1.y;
        div   += w0 + w1;
    }
    if (e < e1) {
        int t = __ldcs(&g_col[colBase + e]);
        float zz = d1 + ldg_keep(h1b + t, pol);
        zz = zz > 0.f ? zz : 0.2f * zz;
        float w1 = __expf(zz);
        uint2 ru = ldg2u_keep(hb + (long)t * H2W, pol);
        float2 u0 = __half22float2(*(__half2*)&ru.x);
        float2 u1 = __half22float2(*(__half2*)&ru.y);
        num.x += w1 * u0.x; num.y += w1 * u0.y;
        num.z += w1 * u1.x; num.w += w1 * u1.y;
        div   += w1;
    }
    float s = wk / div;
    acc.x += num.x * s; acc.y += num.y * s; acc.z += num.z * s; acc.w += num.w * s;
}

// ---------------- hops 0..HOPS-2: all nodes, h1 epilogue for next hop ---------------
__global__ void __launch_bounds__(256) aggr_kernel(
    const float* __restrict__ attn2, const float* __restrict__ lw, int hop, int curB)
{
    int gn0 = (blockIdx.x * blockDim.x + threadIdx.x) >> 4;  // half-warp slot
    int hlane = threadIdx.x & 15;
    if (gn0 >= NTOT) return;
    // subject nodes first (highest degree -> avoid end-of-grid tail)
    int gn = (gn0 < NSU) ? (NP + NA + gn0) : (gn0 - NSU);
    uint64_t pol = mkpol_evict_last();
    const __half2* h  = curB ? g_hB : g_hA;
    __half2*       hn = curB ? g_hA : g_hB;
    const float* h1r = (hop & 1) ? g_h1B : g_h1A;
    float*       h1w = (hop & 1) ? g_h1A : g_h1B;
    const float4 x4 = __ldcs((const float4*)(g_x + (long)gn * D + 4 * hlane));
    float4 acc = make_float4(0.f, 0.f, 0.f, 0.f);

    if (gn < NP) {
        float l0 = lw[hop * 4 + 0], l2 = lw[hop * 4 + 2];
        float m = fmaxf(l0, l2);
        float e0 = __expf(l0 - m), e2 = __expf(l2 - m);
        float inv = 1.f / (e0 + e2);
        aggr_et_h(gn, RP_PA, CB_PA, D1_PA, NP,      hop, h, h1r + H1_PA, hlane, pol, x4, e0 * inv, acc);
        aggr_et_h(gn, RP_PS, CB_PS, D1_PS, NP + NA, hop, h, h1r + H1_PS, hlane, pol, x4, e2 * inv, acc);
    } else if (gn < NP + NA) {
        aggr_et_h(gn - NP, RP_AP, CB_AP, D1_AP, 0,  hop, h, h1r + H1_AP, hlane, pol, x4, 1.f, acc);
    } else {
        aggr_et_h(gn - NP - NA, RP_SP, CB_SP, D1_SP, 0, hop, h, h1r + H1_SP, hlane, pol, x4, 1.f, acc);
    }
    acc.x = acc.x > 0.f ? acc.x : __expf(acc.x) - 1.f;
    acc.y = acc.y > 0.f ? acc.y : __expf(acc.y) - 1.f;
    acc.z = acc.z > 0.f ? acc.z : __expf(acc.z) - 1.f;
    acc.w = acc.w > 0.f ? acc.w : __expf(acc.w) - 1.f;
    {
        uint2 packed;
        *(__half2*)&packed.x = __floats2half2_rn(acc.x, acc.y);
        *(__half2*)&packed.y = __floats2half2_rn(acc.z, acc.w);
        __stcs((uint2*)(hn + (long)gn * H2W + 2 * hlane), packed);
    }

    // ---- fused: target-side h1 for the NEXT hop from the fresh hn row ----
    int nhop = hop + 1;
    {
        if (gn < NP) {
            const float4 a2a = *(const float4*)(attn2 + (nhop * 4 + 1) * D + 4 * hlane);
            const float4 a2b = *(const float4*)(attn2 + (nhop * 4 + 3) * D + 4 * hlane);
            float va = wsum16(acc.x * a2a.x + acc.y * a2a.y + acc.z * a2a.z + acc.w * a2a.w);
            float vb = wsum16(acc.x * a2b.x + acc.y * a2b.y + acc.z * a2b.z + acc.w * a2b.w);
            if (hlane == 0) { h1w[H1_AP + gn] = va; h1w[H1_SP + gn] = vb; }
        } else if (gn < NP + NA) {
            const float4 a2a = *(const float4*)(attn2 + (nhop * 4 + 0) * D + 4 * hlane);
            float va = wsum16(acc.x * a2a.x + acc.y * a2a.y + acc.z * a2a.z + acc.w * a2a.w);
            if (hlane == 0) h1w[H1_PA + (gn - NP)] = va;
        } else {
            const float4 a2a = *(const float4*)(attn2 + (nhop * 4 + 2) * D + 4 * hlane);
            float va = wsum16(acc.x * a2a.x + acc.y * a2a.y + acc.z * a2a.z + acc.w * a2a.w);
            if (hlane == 0) h1w[H1_PS + (gn - NP - NA)] = va;
        }
    }
}

// ---------------- final hop: paper nodes only, fc2 fused ----------------------------
// hop = HOPS-1 = 4 (even) -> reads g_hA / g_h1A. No hn or h1 writes.
// Half-warp per paper node; lane l owns dims 4l..4l+3; Ws max index 15*64+63 = 1023.
__global__ void __launch_bounds__(256) aggr_final_kernel(
    const float* __restrict__ W, const float* __restrict__ bias,
    const float* __restrict__ lw, float* __restrict__ out)
{
    __shared__ float Ws[NOUT * D];
    __shared__ float bs[NOUT];
    int tid = threadIdx.x;
    for (int i = tid; i < NOUT * D; i += 256) Ws[i] = W[i];
    if (tid < NOUT) bs[tid] = bias[tid];
    __syncthreads();

    int gn = (blockIdx.x * 256 + tid) >> 4;
    int hlane = tid & 15;
    if (gn >= NP) return;
    const int hop = HOPS - 1;   // 4
    uint64_t pol = mkpol_evict_last();
    const float4 x4 = __ldcs((const float4*)(g_x + (long)gn * D + 4 * hlane));
    float4 acc = make_float4(0.f, 0.f, 0.f, 0.f);

    float l0 = lw[hop * 4 + 0], l2 = lw[hop * 4 + 2];
    float m = fmaxf(l0, l2);
    float e0 = __expf(l0 - m), e2 = __expf(l2 - m);
    float inv = 1.f / (e0 + e2);
    aggr_et_h(gn, RP_PA, CB_PA, D1_PA, NP,      hop, g_hA, g_h1A + H1_PA, hlane, pol, x4, e0 * inv, acc);
    aggr_et_h(gn, RP_PS, CB_PS, D1_PS, NP + NA, hop, g_hA, g_h1A + H1_PS, hlane, pol, x4, e2 * inv, acc);

    acc.x = acc.x > 0.f ? acc.x : __expf(acc.x) - 1.f;
    acc.y = acc.y > 0.f ? acc.y : __expf(acc.y) - 1.f;
    acc.z = acc.z > 0.f ? acc.z : __expf(acc.z) - 1.f;
    acc.w = acc.w > 0.f ? acc.w : __expf(acc.w) - 1.f;

    // fused fc2: out[gn, o] = sum_d acc_d * W[o, d] + b[o]
    float res = 0.f;
#pragma unroll
    for (int o = 0; o < NOUT; o++) {
        const float* wr = Ws + o * D + 4 * hlane;
        float s = acc.x * wr[0] + acc.y * wr[1] + acc.z * wr[2] + acc.w * wr[3];
        s = wsum16(s);
        if (hlane == o) res = s;
    }
    out[gn * NOUT + hlane] = res + bs[hlane];
}

// ---------------- launch ----------------
extern "C" void kernel_launch(void* const* d_in, const int* in_sizes, int n_in,
                              void* d_out, int out_size)
{
    const float* x_paper   = (const float*)d_in[0];
    const float* x_author  = (const float*)d_in[1];
    const float* x_subject = (const float*)d_in[2];
    const float* fc1p_w = (const float*)d_in[3];
    const float* fc1p_b = (const float*)d_in[4];
    const float* fc1a_w = (const float*)d_in[5];
    const float* fc1a_b = (const float*)d_in[6];
    const float* fc1s_w = (const float*)d_in[7];
    const float* fc1s_b = (const float*)d_in[8];
    const float* attn1  = (const float*)d_in[9];
    const float* attn2  = (const float*)d_in[10];
    const float* lw     = (const float*)d_in[11];
    const float* fc2_w  = (const float*)d_in[12];
    const float* fc2_b  = (const float*)d_in[13];
    const int* ei_pa = (const int*)d_in[14];
    const int* ei_ap = (const int*)d_in[15];
    const int* ei_ps = (const int*)d_in[16];
    const int* ei_sp = (const int*)d_in[17];
    float* out = (float*)d_out;

    zero_rowptr_kernel<<<(RP_TOT + 255) / 256, 256>>>();

    fc1_kernel<<<(NP  + 127) / 128, 256>>>(x_paper,   fc1p_w, fc1p_b, NP,  512, 0);
    fc1_kernel<<<(NA  + 127) / 128, 256>>>(x_author,  fc1a_w, fc1a_b, NA,  256, NP);
    fc1_kernel<<<(NSU + 127) / 128, 256>>>(x_subject, fc1s_w, fc1s_b, NSU, 128, NP + NA);

    hist_kernel<<<(E_TOT + 255) / 256, 256>>>(ei_pa, ei_ap, ei_ps, ei_sp);
    scan_kernel<<<4, 1024>>>();
    scatter_kernel<<<(E_TOT + 255) / 256, 256>>>(ei_pa, ei_ap, ei_ps, ei_sp);

    d1w2_kernel<<<(NTOT * 32 + 255) / 256, 256>>>(attn1, attn2);

    for (int hop = 0; hop < HOPS - 1; hop++) {
        int curB = hop & 1;
        aggr_kernel<<<(NTOT * 16 + 255) / 256, 256>>>(attn2, lw, hop, curB);
    }

    aggr_final_kernel<<<(NP * 16 + 255) / 256, 256>>>(fc2_w, fc2_b, lw, out);
}

// round 15
// speedup vs baseline: 1.5828x; 1.1048x over previous
#include <cuda_runtime.h>
#include <cuda_fp16.h>
#include <cstdint>

// ---------------- problem constants ----------------
#define NP   100000
#define NA   200000
#define NSU  1000
#define NTOT (NP + NA + NSU)          // 301000
#define D    64
#define HOPS 5
#define NOUT 16

#define E_PA 800000
#define E_AP 800000
#define E_PS 100000
#define E_SP 100000
#define E_TOT (E_PA + E_AP + E_PS + E_SP)   // 1800000

// row_ptr segment bases (each segment length = Ns+1)
#define RP_PA 0
#define RP_AP (NP + 1)
#define RP_PS (RP_AP + NA + 1)
#define RP_SP (RP_PS + NP + 1)
#define RP_TOT (RP_SP + NSU + 1)

// col array bases
#define CB_PA 0
#define CB_AP E_PA
#define CB_PS (E_PA + E_AP)
#define CB_SP (E_PA + E_AP + E_PS)

// h1 (target-side attention score) bases
#define H1_PA 0                        // len NA  (targets: author)
#define H1_AP NA                       // len NP  (targets: paper)
#define H1_PS (NA + NP)                // len NSU (targets: subject)
#define H1_SP (NA + NP + NSU)          // len NP  (targets: paper)
#define H1_TOT (NA + NP + NSU + NP)    // 401000

// d1/w2 (source-side) segment bases, ordered [pa, ap, ps, sp]
#define D1_PA 0                        // len NP
#define D1_AP NP                       // len NA
#define D1_PS (NP + NA)                // len NP
#define D1_SP (NP + NA + NP)           // len NSU
#define D1_TOT (NP + NA + NP + NSU)    // 401000

#define H2W 32                         // half2 words per h row (64 halves)
#define XS  20                         // fc1 smem stride in half2 words (bank-conflict-free)

// ---------------- scratch (static device memory; no runtime alloc) ----------------
__device__ float  g_x  [NTOT * D];
__device__ __half2 g_hA [NTOT * H2W];  // h double buffers in fp16
__device__ __half2 g_hB [NTOT * H2W];
__device__ float  g_h1A[H1_TOT];       // h1 double buffer (hop parity)
__device__ float  g_h1B[H1_TOT];
__device__ float  g_d1 [HOPS * D1_TOT];
__device__ float  g_w2 [HOPS * D1_TOT];
__device__ int    g_rowptr[RP_TOT];
__device__ int    g_cursor[RP_TOT];
__device__ int    g_col[E_TOT];

// ---------------- L2 policy helpers ----------------
__device__ __forceinline__ uint64_t mkpol_evict_last()
{
    uint64_t p;
    asm("createpolicy.fractional.L2::evict_last.b64 %0;" : "=l"(p));
    return p;
}

__device__ __forceinline__ float ldg_keep(const float* p, uint64_t pol)
{
    float v;
    asm("ld.global.nc.L2::cache_hint.f32 %0, [%1], %2;" : "=f"(v) : "l"(p), "l"(pol));
    return v;
}

__device__ __forceinline__ uint2 ldg2u_keep(const void* p, uint64_t pol)
{
    uint2 v;
    asm("ld.global.nc.L2::cache_hint.v2.u32 {%0,%1}, [%2], %3;"
        : "=r"(v.x), "=r"(v.y) : "l"(p), "l"(pol));
    return v;
}

// ---------------- bf16 helpers ----------------
// pack(lo_elem -> bits[15:0], hi_elem -> bits[31:16])
__device__ __forceinline__ uint32_t packbf(float e_lo, float e_hi)
{
    uint32_t r;
    asm("cvt.rn.bf16x2.f32 %0, %1, %2;" : "=r"(r) : "f"(e_hi), "f"(e_lo));
    return r;
}

__device__ __forceinline__ float2 unpackbf(uint32_t h)
{
    float2 r;
    r.x = __uint_as_float(h << 16);
    r.y = __uint_as_float(h & 0xffff0000u);
    return r;
}

#define MMA_BF16(c, a, b) \
    asm volatile("mma.sync.aligned.m16n8k16.row.col.f32.bf16.bf16.f32 " \
                 "{%0,%1,%2,%3},{%4,%5,%6,%7},{%8,%9},{%0,%1,%2,%3};" \
                 : "+f"((c)[0]), "+f"((c)[1]), "+f"((c)[2]), "+f"((c)[3]) \
                 : "r"((a)[0]), "r"((a)[1]), "r"((a)[2]), "r"((a)[3]), \
                   "r"((b)[0]), "r"((b)[1]))

// ---------------- fc1: Y = relu(X @ W^T + b) via bf16x3 tensor cores (m16n8k16) ----
// Block tile 128(M) x 64(N) x 32(K); 8 warps (warp_m 0..3, warp_n 0..1).
// Smem rows padded to XS=20 half2 words: r*20 mod 32 = {0,20,8,28,16,4,24,12}
// -> all fragment loads (g=0..7, tg=0..3) touch 32 distinct banks.
__global__ void __launch_bounds__(256) fc1_kernel(
    const float* __restrict__ X, const float* __restrict__ W,
    const float* __restrict__ bias, int N, int F, int nodeBase)
{
    __shared__ uint32_t Xhi[128][XS];
    __shared__ uint32_t Xlo[128][XS];
    __shared__ uint32_t Whi[64][XS];
    __shared__ uint32_t Wlo[64][XS];

    const int tid  = threadIdx.x;
    const int lane = tid & 31;
    const int warp = tid >> 5;
    const int warp_m = warp & 3;
    const int warp_n = warp >> 2;
    const int bm0 = blockIdx.x * 128;

    float c[2][4][4];
#pragma unroll
    for (int mt = 0; mt < 2; mt++)
#pragma unroll
        for (int nt = 0; nt < 4; nt++)
#pragma unroll
            for (int i = 0; i < 4; i++) c[mt][nt][i] = 0.f;

    const int lr = tid >> 3;          // 0..31 : row within 32-row chunk
    const int lc = (tid & 7) * 4;     // float k-offset 0,4,...,28
    const int wq = (tid & 7) * 2;     // half2 word index (even)

    for (int k0 = 0; k0 < F; k0 += 32) {
        // ---- X tile (128 x 32 floats) -> bf16 hi/lo ----
#pragma unroll
        for (int i = 0; i < 4; i++) {
            int r = lr + i * 32;
            int row = bm0 + r;
            float4 v = make_float4(0.f, 0.f, 0.f, 0.f);
            if (row < N) v = *(const float4*)&X[(long)row * F + k0 + lc];
            uint32_t h01 = packbf(v.x, v.y);
            uint32_t h23 = packbf(v.z, v.w);
            float2 b01 = unpackbf(h01);
            float2 b23 = unpackbf(h23);
            uint32_t l01 = packbf(v.x - b01.x, v.y - b01.y);
            uint32_t l23 = packbf(v.z - b23.x, v.w - b23.y);
            *(uint2*)&Xhi[r][wq] = make_uint2(h01, h23);
            *(uint2*)&Xlo[r][wq] = make_uint2(l01, l23);
        }
        // ---- W tile (64 x 32 floats) ----
#pragma unroll
        for (int i = 0; i < 2; i++) {
            int r = lr + i * 32;
            float4 v = *(const float4*)&W[(long)r * F + k0 + lc];
            uint32_t h01 = packbf(v.x, v.y);
            uint32_t h23 = packbf(v.z, v.w);
            float2 b01 = unpackbf(h01);
            float2 b23 = unpackbf(h23);
            uint32_t l01 = packbf(v.x - b01.x, v.y - b01.y);
            uint32_t l23 = packbf(v.z - b23.x, v.w - b23.y);
            *(uint2*)&Whi[r][wq] = make_uint2(h01, h23);
            *(uint2*)&Wlo[r][wq] = make_uint2(l01, l23);
        }
        __syncthreads();

        const int g  = lane >> 2;     // 0..7
        const int tg = lane & 3;      // 0..3
#pragma unroll
        for (int ks = 0; ks < 2; ks++) {
            int wb = ks * 8;
            uint32_t ahi[2][4], alo[2][4], bhi[4][2], blo[4][2];
#pragma unroll
            for (int mt = 0; mt < 2; mt++) {
                int r0 = warp_m * 32 + mt * 16 + g;
                ahi[mt][0] = Xhi[r0][wb + tg];
                ahi[mt][1] = Xhi[r0 + 8][wb + tg];
                ahi[mt][2] = Xhi[r0][wb + tg + 4];
                ahi[mt][3] = Xhi[r0 + 8][wb + tg + 4];
                alo[mt][0] = Xlo[r0][wb + tg];
                alo[mt][1] = Xlo[r0 + 8][wb + tg];
                alo[mt][2] = Xlo[r0][wb + tg + 4];
                alo[mt][3] = Xlo[r0 + 8][wb + tg + 4];
            }
#pragma unroll
            for (int nt = 0; nt < 4; nt++) {
                int n = warp_n * 32 + nt * 8 + g;
                bhi[nt][0] = Whi[n][wb + tg];
                bhi[nt][1] = Whi[n][wb + tg + 4];
                blo[nt][0] = Wlo[n][wb + tg];
                blo[nt][1] = Wlo[n][wb + tg + 4];
            }
#pragma unroll
            for (int mt = 0; mt < 2; mt++)
#pragma unroll
                for (int nt = 0; nt < 4; nt++) {
                    MMA_BF16(c[mt][nt], ahi[mt], bhi[nt]);
                    MMA_BF16(c[mt][nt], ahi[mt], blo[nt]);
                    MMA_BF16(c[mt][nt], alo[mt], bhi[nt]);
                }
        }
        __syncthreads();
    }

    // ---- epilogue: bias + relu, write g_x (fp32) and g_hA (fp16) ----
#pragma unroll
    for (int mt = 0; mt < 2; mt++) {
#pragma unroll
        for (int nt = 0; nt < 4; nt++) {
            int row = bm0 + warp_m * 32 + mt * 16 + (lane >> 2);
            int col = warp_n * 32 + nt * 8 + (lane & 3) * 2;
            float b0 = __ldg(&bias[col]);
            float b1 = __ldg(&bias[col + 1]);
            if (row < N) {
                float v0 = fmaxf(c[mt][nt][0] + b0, 0.f);
                float v1 = fmaxf(c[mt][nt][1] + b1, 0.f);
                long node = nodeBase + row;
                *(float2*)&g_x[node * D + col] = make_float2(v0, v1);
                g_hA[node * H2W + (col >> 1)] = __floats2half2_rn(v0, v1);
            }
            if (row + 8 < N) {
                float v2 = fmaxf(c[mt][nt][2] + b0, 0.f);
                float v3 = fmaxf(c[mt][nt][3] + b1, 0.f);
                long node = nodeBase + row + 8;
                *(float2*)&g_x[node * D + col] = make_float2(v2, v3);
                g_hA[node * H2W + (col >> 1)] = __floats2half2_rn(v2, v3);
            }
        }
    }
}

// ---------------- CSR build ----------------
__global__ void zero_rowptr_kernel()
{
    int i = blockIdx.x * blockDim.x + threadIdx.x;
    if (i < RP_TOT) g_rowptr[i] = 0;
}

__global__ void hist_kernel(const int* __restrict__ ei_pa, const int* __restrict__ ei_ap,
                            const int* __restrict__ ei_ps, const int* __restrict__ ei_sp)
{
    int e = blockIdx.x * blockDim.x + threadIdx.x;
    if (e >= E_TOT) return;
    const int* ei; int l, rpb;
    if (e < E_PA)                   { ei = ei_pa; l = e;                      rpb = RP_PA; }
    else if (e < E_PA + E_AP)       { ei = ei_ap; l = e - E_PA;               rpb = RP_AP; }
    else if (e < E_PA + E_AP + E_PS){ ei = ei_ps; l = e - E_PA - E_AP;        rpb = RP_PS; }
    else                            { ei = ei_sp; l = e - E_PA - E_AP - E_PS; rpb = RP_SP; }
    atomicAdd(&g_rowptr[rpb + 1 + ei[l]], 1);
}

__global__ void scan_kernel()
{
    __shared__ int ssum[1024];
    int base, n;
    if (blockIdx.x == 0)      { base = RP_PA; n = NP + 1;  }
    else if (blockIdx.x == 1) { base = RP_AP; n = NA + 1;  }
    else if (blockIdx.x == 2) { base = RP_PS; n = NP + 1;  }
    else                      { base = RP_SP; n = NSU + 1; }
    int tid = threadIdx.x;
    int chunk = (n + 1023) >> 10;
    int s0 = tid * chunk;
    int s1 = s0 + chunk; if (s1 > n) s1 = n; if (s0 > n) s0 = n;

    int sum = 0;
    for (int j = s0; j < s1; j++) sum += g_rowptr[base + j];
    ssum[tid] = sum;
    __syncthreads();
    for (int off = 1; off < 1024; off <<= 1) {
        int v = (tid >= off) ? ssum[tid - off] : 0;
        __syncthreads();
        ssum[tid] += v;
        __syncthreads();
    }
    int run = (tid == 0) ? 0 : ssum[tid - 1];
    for (int j = s0; j < s1; j++) {
        run += g_rowptr[base + j];
        g_rowptr[base + j] = run;
        g_cursor[base + j] = run;
    }
}

__global__ void scatter_kernel(const int* __restrict__ ei_pa, const int* __restrict__ ei_ap,
                               const int* __restrict__ ei_ps, const int* __restrict__ ei_sp)
{
    int e = blockIdx.x * blockDim.x + threadIdx.x;
    if (e >= E_TOT) return;
    const int* ei; int l, rpb, cb, En;
    if (e < E_PA)                   { ei = ei_pa; l = e;                      rpb = RP_PA; cb = CB_PA; En = E_PA; }
    else if (e < E_PA + E_AP)       { ei = ei_ap; l = e - E_PA;               rpb = RP_AP; cb = CB_AP; En = E_AP; }
    else if (e < E_PA + E_AP + E_PS){ ei = ei_ps; l = e - E_PA - E_AP;        rpb = RP_PS; cb = CB_PS; En = E_PS; }
    else                            { ei = ei_sp; l = e - E_PA - E_AP - E_PS; rpb = RP_SP; cb = CB_SP; En = E_SP; }
    int s = ei[l];
    int t = ei[En + l];
    int pos = atomicAdd(&g_cursor[rpb + s], 1);
    g_col[cb + pos] = t;
}

// ---------------- reductions ----------------
__device__ __forceinline__ float wsum32(float v)
{
#pragma unroll
    for (int o = 16; o; o >>= 1) v += __shfl_xor_sync(0xffffffffu, v, o);
    return v;
}

__device__ __forceinline__ float wsum16(float v)
{
#pragma unroll
    for (int o = 8; o; o >>= 1) v += __shfl_xor_sync(0xffffffffu, v, o);
    return v;
}

// ---------------- one-time: source-side d1/w2 + hop-0 target h1 ----------
// Author/subject skip hop HOPS-1 (their final-hop aggregation is dead work).
__global__ void d1w2_kernel(const float* __restrict__ attn1, const float* __restrict__ attn2)
{
    int gw = (blockIdx.x * blockDim.x + threadIdx.x) >> 5;
    int lane = threadIdx.x & 31;
    if (gw >= NTOT) return;
    const float* xr = g_x + (long)gw * D;
    float x0 = xr[lane], x1 = xr[lane + 32];

    int k0, k1, base0, base1, l;
    if (gw < NP)            { l = gw;            k0 = 0; base0 = D1_PA; k1 = 2;  base1 = D1_PS; }
    else if (gw < NP + NA)  { l = gw - NP;       k0 = 1; base0 = D1_AP; k1 = -1; base1 = 0; }
    else                    { l = gw - NP - NA;  k0 = 3; base0 = D1_SP; k1 = -1; base1 = 0; }

#pragma unroll
    for (int hop = 0; hop < HOPS; hop++) {
        if (k1 >= 0 || hop < HOPS - 1) {
            const float* a1 = attn1 + (hop * 4 + k0) * D;
            const float* a2 = attn2 + (hop * 4 + k0) * D;
            float d1 = wsum32(x0 * a1[lane] + x1 * a1[lane + 32]);
            float d2 = wsum32(x0 * a2[lane] + x1 * a2[lane + 32]);
            float z = d1 + d2; z = z > 0.f ? z : 0.2f * z;
            if (lane == 0) {
                g_d1[hop * D1_TOT + base0 + l] = d1;
                g_w2[hop * D1_TOT + base0 + l] = __expf(z);
            }
        }
        if (k1 >= 0) {
            const float* a1 = attn1 + (hop * 4 + k1) * D;
            const float* a2 = attn2 + (hop * 4 + k1) * D;
            float d1 = wsum32(x0 * a1[lane] + x1 * a1[lane + 32]);
            float d2 = wsum32(x0 * a2[lane] + x1 * a2[lane + 32]);
            float z = d1 + d2; z = z > 0.f ? z : 0.2f * z;
            if (lane == 0) {
                g_d1[hop * D1_TOT + base1 + l] = d1;
                g_w2[hop * D1_TOT + base1 + l] = __expf(z);
            }
        }
    }

    // hop-0 target-side h1 (h == x at hop 0), written into buffer A
    if (gw < NP) {
        const float* a2a = attn2 + (0 * 4 + 1) * D;   // targets of ap edges
        const float* a2b = attn2 + (0 * 4 + 3) * D;   // targets of sp edges
        float va = wsum32(x0 * a2a[lane] + x1 * a2a[lane + 32]);
        float vb = wsum32(x0 * a2b[lane] + x1 * a2b[lane + 32]);
        if (lane == 0) { g_h1A[H1_AP + l] = va; g_h1A[H1_SP + l] = vb; }
    } else if (gw < NP + NA) {
        const float* a2a = attn2 + (0 * 4 + 0) * D;   // targets of pa edges
        float va = wsum32(x0 * a2a[lane] + x1 * a2a[lane + 32]);
        if (lane == 0) g_h1A[H1_PA + l] = va;
    } else {
        const float* a2a = attn2 + (0 * 4 + 2) * D;   // targets of ps edges
        float va = wsum32(x0 * a2a[lane] + x1 * a2a[lane + 32]);
        if (lane == 0) g_h1A[H1_PS + l] = va;
    }
}

// ---------------- shared inner loop: half-warp per node, fp16 h gather --------------
__device__ __forceinline__ void aggr_et_h(
    int nodeLocal, int rpBase, int colBase, int d1Base, int tOff, int hop,
    const __half2* __restrict__ h, const float* __restrict__ h1b, int hlane,
    uint64_t pol, const float4& x4, float wk, float4& acc)
{
    float d1 = g_d1[hop * D1_TOT + d1Base + nodeLocal];
    float w2 = g_w2[hop * D1_TOT + d1Base + nodeLocal];
    float4 num = make_float4(w2 * x4.x, w2 * x4.y, w2 * x4.z, w2 * x4.w);
    float div = w2;
    int e0 = g_rowptr[rpBase + nodeLocal];
    int e1 = g_rowptr[rpBase + nodeLocal + 1];
    const __half2* hb = h + (long)tOff * H2W + 2 * hlane;

    int e = e0;
    for (; e + 2 <= e1; e += 2) {
        int t0 = __ldcs(&g_col[colBase + e]);
        int t1 = __ldcs(&g_col[colBase + e + 1]);
        float p0 = ldg_keep(h1b + t0, pol);
        float p1 = ldg_keep(h1b + t1, pol);
        uint2 ru = ldg2u_keep(hb + (long)t0 * H2W, pol);
        uint2 rv = ldg2u_keep(hb + (long)t1 * H2W, pol);
        float2 u0 = __half22float2(*(__half2*)&ru.x);
        float2 u1 = __half22float2(*(__half2*)&ru.y);
        float2 v0 = __half22float2(*(__half2*)&rv.x);
        float2 v1 = __half22float2(*(__half2*)&rv.y);
        float z0 = d1 + p0; z0 = z0 > 0.f ? z0 : 0.2f * z0;
        float z1 = d1 + p1; z1 = z1 > 0.f ? z1 : 0.2f * z1;
        float w0 = __expf(z0);
        float w1 = __expf(z1);
        num.x += w0 * u0.x + w1 * v0.x;
        num.y += w0 * u0.y + w1 * v0.y;
        num.z += w0 * u1.x + w1 * v1.x;
        num.w += w0 * u1.y + w1 * v1.y;
        div   += w0 + w1;
    }
    if (e < e1) {
        int t = __ldcs(&g_col[colBase + e]);
        float zz = d1 + ldg_keep(h1b + t, pol);
        zz = zz > 0.f ? zz : 0.2f * zz;
        float w1 = __expf(zz);
        uint2 ru = ldg2u_keep(hb + (long)t * H2W, pol);
        float2 u0 = __half22float2(*(__half2*)&ru.x);
        float2 u1 = __half22float2(*(__half2*)&ru.y);
        num.x += w1 * u0.x; num.y += w1 * u0.y;
        num.z += w1 * u1.x; num.w += w1 * u1.y;
        div   += w1;
    }
    float s = wk / div;
    acc.x += num.x * s; acc.y += num.y * s; acc.z += num.z * s; acc.w += num.w * s;
}

// ---------------- hops 0..HOPS-2: all nodes, h1 epilogue for next hop ---------------
__global__ void __launch_bounds__(256) aggr_kernel(
    const float* __restrict__ attn2, const float* __restrict__ lw, int hop, int curB)
{
    int gn0 = (blockIdx.x * blockDim.x + threadIdx.x) >> 4;  // half-warp slot
    int hlane = threadIdx.x & 15;
    if (gn0 >= NTOT) return;
    // subject nodes first (highest degree -> avoid end-of-grid tail)
    int gn = (gn0 < NSU) ? (NP + NA + gn0) : (gn0 - NSU);
    uint64_t pol = mkpol_evict_last();
    const __half2* h  = curB ? g_hB : g_hA;
    __half2*       hn = curB ? g_hA : g_hB;
    const float* h1r = (hop & 1) ? g_h1B : g_h1A;
    float*       h1w = (hop & 1) ? g_h1A : g_h1B;
    const float4 x4 = __ldcs((const float4*)(g_x + (long)gn * D + 4 * hlane));
    float4 acc = make_float4(0.f, 0.f, 0.f, 0.f);

    if (gn < NP) {
        float l0 = lw[hop * 4 + 0], l2 = lw[hop * 4 + 2];
        float m = fmaxf(l0, l2);
        float e0 = __expf(l0 - m), e2 = __expf(l2 - m);
        float inv = 1.f / (e0 + e2);
        aggr_et_h(gn, RP_PA, CB_PA, D1_PA, NP,      hop, h, h1r + H1_PA, hlane, pol, x4, e0 * inv, acc);
        aggr_et_h(gn, RP_PS, CB_PS, D1_PS, NP + NA, hop, h, h1r + H1_PS, hlane, pol, x4, e2 * inv, acc);
    } else if (gn < NP + NA) {
        aggr_et_h(gn - NP, RP_AP, CB_AP, D1_AP, 0,  hop, h, h1r + H1_AP, hlane, pol, x4, 1.f, acc);
    } else {
        aggr_et_h(gn - NP - NA, RP_SP, CB_SP, D1_SP, 0, hop, h, h1r + H1_SP, hlane, pol, x4, 1.f, acc);
    }
    acc.x = acc.x > 0.f ? acc.x : __expf(acc.x) - 1.f;
    acc.y = acc.y > 0.f ? acc.y : __expf(acc.y) - 1.f;
    acc.z = acc.z > 0.f ? acc.z : __expf(acc.z) - 1.f;
    acc.w = acc.w > 0.f ? acc.w : __expf(acc.w) - 1.f;
    {
        uint2 packed;
        *(__half2*)&packed.x = __floats2half2_rn(acc.x, acc.y);
        *(__half2*)&packed.y = __floats2half2_rn(acc.z, acc.w);
        __stcs((uint2*)(hn + (long)gn * H2W + 2 * hlane), packed);
    }

    // ---- fused: target-side h1 for the NEXT hop from the fresh hn row ----
    int nhop = hop + 1;
    {
        if (gn < NP) {
            const float4 a2a = *(const float4*)(attn2 + (nhop * 4 + 1) * D + 4 * hlane);
            const float4 a2b = *(const float4*)(attn2 + (nhop * 4 + 3) * D + 4 * hlane);
            float va = wsum16(acc.x * a2a.x + acc.y * a2a.y + acc.z * a2a.z + acc.w * a2a.w);
            float vb = wsum16(acc.x * a2b.x + acc.y * a2b.y + acc.z * a2b.z + acc.w * a2b.w);
            if (hlane == 0) { h1w[H1_AP + gn] = va; h1w[H1_SP + gn] = vb; }
        } else if (gn < NP + NA) {
            const float4 a2a = *(const float4*)(attn2 + (nhop * 4 + 0) * D + 4 * hlane);
            float va = wsum16(acc.x * a2a.x + acc.y * a2a.y + acc.z * a2a.z + acc.w * a2a.w);
            if (hlane == 0) h1w[H1_PA + (gn - NP)] = va;
        } else {
            const float4 a2a = *(const float4*)(attn2 + (nhop * 4 + 2) * D + 4 * hlane);
            float va = wsum16(acc.x * a2a.x + acc.y * a2a.y + acc.z * a2a.z + acc.w * a2a.w);
            if (hlane == 0) h1w[H1_PS + (gn - NP - NA)] = va;
        }
    }
}

// ---------------- final hop: paper nodes only, fc2 fused ----------------------------
// hop = HOPS-1 = 4 (even) -> reads g_hA / g_h1A. No hn or h1 writes.
__global__ void __launch_bounds__(256) aggr_final_kernel(
    const float* __restrict__ W, const float* __restrict__ bias,
    const float* __restrict__ lw, float* __restrict__ out)
{
    __shared__ float Ws[NOUT * D];
    __shared__ float bs[NOUT];
    int tid = threadIdx.x;
    for (int i = tid; i < NOUT * D; i += 256) Ws[i] = W[i];
    if (tid < NOUT) bs[tid] = bias[tid];
    __syncthreads();

    int gn = (blockIdx.x * 256 + tid) >> 4;
    int hlane = tid & 15;
    if (gn >= NP) return;
    const int hop = HOPS - 1;   // 4
    uint64_t pol = mkpol_evict_last();
    const float4 x4 = __ldcs((const float4*)(g_x + (long)gn * D + 4 * hlane));
    float4 acc = make_float4(0.f, 0.f, 0.f, 0.f);

    float l0 = lw[hop * 4 + 0], l2 = lw[hop * 4 + 2];
    float m = fmaxf(l0, l2);
    float e0 = __expf(l0 - m), e2 = __expf(l2 - m);
    float inv = 1.f / (e0 + e2);
    aggr_et_h(gn, RP_PA, CB_PA, D1_PA, NP,      hop, g_hA, g_h1A + H1_PA, hlane, pol, x4, e0 * inv, acc);
    aggr_et_h(gn, RP_PS, CB_PS, D1_PS, NP + NA, hop, g_hA, g_h1A + H1_PS, hlane, pol, x4, e2 * inv, acc);

    acc.x = acc.x > 0.f ? acc.x : __expf(acc.x) - 1.f;
    acc.y = acc.y > 0.f ? acc.y : __expf(acc.y) - 1.f;
    acc.z = acc.z > 0.f ? acc.z : __expf(acc.z) - 1.f;
    acc.w = acc.w > 0.f ? acc.w : __expf(acc.w) - 1.f;

    // fused fc2: out[gn, o] = sum_d acc_d * W[o, d] + b[o]
    float res = 0.f;
#pragma unroll
    for (int o = 0; o < NOUT; o++) {
        const float* wr = Ws + o * D + 4 * hlane;
        float s = acc.x * wr[0] + acc.y * wr[1] + acc.z * wr[2] + acc.w * wr[3];
        s = wsum16(s);
        if (hlane == o) res = s;
    }
    out[gn * NOUT + hlane] = res + bs[hlane];
}

// ---------------- launch ----------------
extern "C" void kernel_launch(void* const* d_in, const int* in_sizes, int n_in,
                              void* d_out, int out_size)
{
    const float* x_paper   = (const float*)d_in[0];
    const float* x_author  = (const float*)d_in[1];
    const float* x_subject = (const float*)d_in[2];
    const float* fc1p_w = (const float*)d_in[3];
    const float* fc1p_b = (const float*)d_in[4];
    const float* fc1a_w = (const float*)d_in[5];
    const float* fc1a_b = (const float*)d_in[6];
    const float* fc1s_w = (const float*)d_in[7];
    const float* fc1s_b = (const float*)d_in[8];
    const float* attn1  = (const float*)d_in[9];
    const float* attn2  = (const float*)d_in[10];
    const float* lw     = (const float*)d_in[11];
    const float* fc2_w  = (const float*)d_in[12];
    const float* fc2_b  = (const float*)d_in[13];
    const int* ei_pa = (const int*)d_in[14];
    const int* ei_ap = (const int*)d_in[15];
    const int* ei_ps = (const int*)d_in[16];
    const int* ei_sp = (const int*)d_in[17];
    float* out = (float*)d_out;

    zero_rowptr_kernel<<<(RP_TOT + 255) / 256, 256>>>();

    fc1_kernel<<<(NP  + 127) / 128, 256>>>(x_paper,   fc1p_w, fc1p_b, NP,  512, 0);
    fc1_kernel<<<(NA  + 127) / 128, 256>>>(x_author,  fc1a_w, fc1a_b, NA,  256, NP);
    fc1_kernel<<<(NSU + 127) / 128, 256>>>(x_subject, fc1s_w, fc1s_b, NSU, 128, NP + NA);

    hist_kernel<<<(E_TOT + 255) / 256, 256>>>(ei_pa, ei_ap, ei_ps, ei_sp);
    scan_kernel<<<4, 1024>>>();
    scatter_kernel<<<(E_TOT + 255) / 256, 256>>>(ei_pa, ei_ap, ei_ps, ei_sp);

    d1w2_kernel<<<(NTOT * 32 + 255) / 256, 256>>>(attn1, attn2);

    for (int hop = 0; hop < HOPS - 1; hop++) {
        int curB = hop & 1;
        aggr_kernel<<<(NTOT * 16 + 255) / 256, 256>>>(attn2, lw, hop, curB);
    }

    aggr_final_kernel<<<(NP * 16 + 255) / 256, 256>>>(fc2_w, fc2_b, lw, out);
}

// round 16
// speedup vs baseline: 1.6353x; 1.0331x over previous
#include <cuda_runtime.h>
#include <cuda_fp16.h>
#include <cstdint>

// ---------------- problem constants ----------------
#define NP   100000
#define NA   200000
#define NSU  1000
#define NTOT (NP + NA + NSU)          // 301000
#define D    64
#define HOPS 5
#define NOUT 16

#define E_PA 800000
#define E_AP 800000
#define E_PS 100000
#define E_SP 100000
#define E_TOT (E_PA + E_AP + E_PS + E_SP)   // 1800000

// row_ptr segment bases (each segment length = Ns+1)
#define RP_PA 0
#define RP_AP (NP + 1)
#define RP_PS (RP_AP + NA + 1)
#define RP_SP (RP_PS + NP + 1)
#define RP_TOT (RP_SP + NSU + 1)

// col array bases
#define CB_PA 0
#define CB_AP E_PA
#define CB_PS (E_PA + E_AP)
#define CB_SP (E_PA + E_AP + E_PS)

// h1 (target-side attention score) bases
#define H1_PA 0                        // len NA  (targets: author)
#define H1_AP NA                       // len NP  (targets: paper)
#define H1_PS (NA + NP)                // len NSU (targets: subject)
#define H1_SP (NA + NP + NSU)          // len NP  (targets: paper)
#define H1_TOT (NA + NP + NSU + NP)    // 401000

// d1/w2 (source-side) segment bases, ordered [pa, ap, ps, sp]
#define D1_PA 0                        // len NP
#define D1_AP NP                       // len NA
#define D1_PS (NP + NA)                // len NP
#define D1_SP (NP + NA + NP)           // len NSU
#define D1_TOT (NP + NA + NP + NSU)    // 401000

#define H2W 32                         // half2 words per h row (64 halves)
#define XS  20                         // fc1 smem stride in half2 words (bank-conflict-free)

// ---------------- scratch (static device memory; no runtime alloc) ----------------
__device__ float  g_x  [NTOT * D];
__device__ __half2 g_hA [NTOT * H2W];  // h double buffers in fp16
__device__ __half2 g_hB [NTOT * H2W];
__device__ float  g_h1A[H1_TOT];       // h1 double buffer (hop parity)
__device__ float  g_h1B[H1_TOT];
__device__ float  g_d1 [HOPS * D1_TOT];
__device__ float  g_w2 [HOPS * D1_TOT];
__device__ int    g_rowptr[RP_TOT];
__device__ int    g_cursor[RP_TOT];
__device__ int    g_col[E_TOT];

// ---------------- L2 policy helpers ----------------
__device__ __forceinline__ uint64_t mkpol_evict_last()
{
    uint64_t p;
    asm("createpolicy.fractional.L2::evict_last.b64 %0;" : "=l"(p));
    return p;
}

__device__ __forceinline__ float ldg_keep(const float* p, uint64_t pol)
{
    float v;
    asm("ld.global.nc.L2::cache_hint.f32 %0, [%1], %2;" : "=f"(v) : "l"(p), "l"(pol));
    return v;
}

__device__ __forceinline__ uint2 ldg2u_keep(const void* p, uint64_t pol)
{
    uint2 v;
    asm("ld.global.nc.L2::cache_hint.v2.u32 {%0,%1}, [%2], %3;"
        : "=r"(v.x), "=r"(v.y) : "l"(p), "l"(pol));
    return v;
}

// ---------------- bf16 helpers ----------------
__device__ __forceinline__ uint32_t packbf(float e_lo, float e_hi)
{
    uint32_t r;
    asm("cvt.rn.bf16x2.f32 %0, %1, %2;" : "=r"(r) : "f"(e_hi), "f"(e_lo));
    return r;
}

__device__ __forceinline__ float2 unpackbf(uint32_t h)
{
    float2 r;
    r.x = __uint_as_float(h << 16);
    r.y = __uint_as_float(h & 0xffff0000u);
    return r;
}

#define MMA_BF16(c, a, b) \
    asm volatile("mma.sync.aligned.m16n8k16.row.col.f32.bf16.bf16.f32 " \
                 "{%0,%1,%2,%3},{%4,%5,%6,%7},{%8,%9},{%0,%1,%2,%3};" \
                 : "+f"((c)[0]), "+f"((c)[1]), "+f"((c)[2]), "+f"((c)[3]) \
                 : "r"((a)[0]), "r"((a)[1]), "r"((a)[2]), "r"((a)[3]), \
                   "r"((b)[0]), "r"((b)[1]))

// ---------------- fc1: Y = relu(X @ W^T + b), bf16x3 m16n8k16, software-pipelined ---
// Block tile 128(M) x 64(N) x 32(K); 8 warps. Next K-tile is prefetched into
// registers BEFORE the MMA phase so global latency hides under compute.
__global__ void __launch_bounds__(256, 2) fc1_kernel(
    const float* __restrict__ X, const float* __restrict__ W,
    const float* __restrict__ bias, int N, int F, int nodeBase)
{
    __shared__ uint32_t Xhi[128][XS];
    __shared__ uint32_t Xlo[128][XS];
    __shared__ uint32_t Whi[64][XS];
    __shared__ uint32_t Wlo[64][XS];

    const int tid  = threadIdx.x;
    const int lane = tid & 31;
    const int warp = tid >> 5;
    const int warp_m = warp & 3;
    const int warp_n = warp >> 2;
    const int bm0 = blockIdx.x * 128;

    float c[2][4][4];
#pragma unroll
    for (int mt = 0; mt < 2; mt++)
#pragma unroll
        for (int nt = 0; nt < 4; nt++)
#pragma unroll
            for (int i = 0; i < 4; i++) c[mt][nt][i] = 0.f;

    const int lr = tid >> 3;          // 0..31 : row within 32-row chunk
    const int lc = (tid & 7) * 4;     // float k-offset 0,4,...,28
    const int wq = (tid & 7) * 2;     // half2 word index (even)

    float4 xv[4], wv[2];

#define LOAD_TILES(K0) do { \
    _Pragma("unroll") \
    for (int i = 0; i < 4; i++) { \
        int row = bm0 + lr + i * 32; \
        float4 v = make_float4(0.f, 0.f, 0.f, 0.f); \
        if (row < N) v = *(const float4*)&X[(long)row * F + (K0) + lc]; \
        xv[i] = v; \
    } \
    _Pragma("unroll") \
    for (int i = 0; i < 2; i++) { \
        int r = lr + i * 32; \
        wv[i] = *(const float4*)&W[(long)r * F + (K0) + lc]; \
    } \
} while (0)

#define STORE_TILES() do { \
    _Pragma("unroll") \
    for (int i = 0; i < 4; i++) { \
        int r = lr + i * 32; \
        uint32_t h01 = packbf(xv[i].x, xv[i].y); \
        uint32_t h23 = packbf(xv[i].z, xv[i].w); \
        float2 b01 = unpackbf(h01); \
        float2 b23 = unpackbf(h23); \
        *(uint2*)&Xhi[r][wq] = make_uint2(h01, h23); \
        *(uint2*)&Xlo[r][wq] = make_uint2(packbf(xv[i].x - b01.x, xv[i].y - b01.y), \
                                          packbf(xv[i].z - b23.x, xv[i].w - b23.y)); \
    } \
    _Pragma("unroll") \
    for (int i = 0; i < 2; i++) { \
        int r = lr + i * 32; \
        uint32_t h01 = packbf(wv[i].x, wv[i].y); \
        uint32_t h23 = packbf(wv[i].z, wv[i].w); \
        float2 b01 = unpackbf(h01); \
        float2 b23 = unpackbf(h23); \
        *(uint2*)&Whi[r][wq] = make_uint2(h01, h23); \
        *(uint2*)&Wlo[r][wq] = make_uint2(packbf(wv[i].x - b01.x, wv[i].y - b01.y), \
                                          packbf(wv[i].z - b23.x, wv[i].w - b23.y)); \
    } \
} while (0)

    // prologue: tile 0 -> regs -> smem
    LOAD_TILES(0);
    STORE_TILES();
    __syncthreads();

    for (int k0 = 0; k0 < F; k0 += 32) {
        int kn = k0 + 32;
        if (kn < F) LOAD_TILES(kn);   // prefetch next tile (hidden under MMAs)

        const int g  = lane >> 2;     // 0..7
        const int tg = lane & 3;      // 0..3
#pragma unroll
        for (int ks = 0; ks < 2; ks++) {
            int wb = ks * 8;
            uint32_t ahi[2][4], alo[2][4], bhi[4][2], blo[4][2];
#pragma unroll
            for (int mt = 0; mt < 2; mt++) {
                int r0 = warp_m * 32 + mt * 16 + g;
                ahi[mt][0] = Xhi[r0][wb + tg];
                ahi[mt][1] = Xhi[r0 + 8][wb + tg];
                ahi[mt][2] = Xhi[r0][wb + tg + 4];
                ahi[mt][3] = Xhi[r0 + 8][wb + tg + 4];
                alo[mt][0] = Xlo[r0][wb + tg];
                alo[mt][1] = Xlo[r0 + 8][wb + tg];
                alo[mt][2] = Xlo[r0][wb + tg + 4];
                alo[mt][3] = Xlo[r0 + 8][wb + tg + 4];
            }
#pragma unroll
            for (int nt = 0; nt < 4; nt++) {
                int n = warp_n * 32 + nt * 8 + g;
                bhi[nt][0] = Whi[n][wb + tg];
                bhi[nt][1] = Whi[n][wb + tg + 4];
                blo[nt][0] = Wlo[n][wb + tg];
                blo[nt][1] = Wlo[n][wb + tg + 4];
            }
#pragma unroll
            for (int mt = 0; mt < 2; mt++)
#pragma unroll
                for (int nt = 0; nt < 4; nt++) {
                    MMA_BF16(c[mt][nt], ahi[mt], bhi[nt]);
                    MMA_BF16(c[mt][nt], ahi[mt], blo[nt]);
                    MMA_BF16(c[mt][nt], alo[mt], bhi[nt]);
                }
        }
        __syncthreads();
        if (kn < F) {
            STORE_TILES();
            __syncthreads();
        }
    }

#undef LOAD_TILES
#undef STORE_TILES

    // ---- epilogue: bias + relu, write g_x (fp32) and g_hA (fp16) ----
#pragma unroll
    for (int mt = 0; mt < 2; mt++) {
#pragma unroll
        for (int nt = 0; nt < 4; nt++) {
            int row = bm0 + warp_m * 32 + mt * 16 + (lane >> 2);
            int col = warp_n * 32 + nt * 8 + (lane & 3) * 2;
            float b0 = __ldg(&bias[col]);
            float b1 = __ldg(&bias[col + 1]);
            if (row < N) {
                float v0 = fmaxf(c[mt][nt][0] + b0, 0.f);
                float v1 = fmaxf(c[mt][nt][1] + b1, 0.f);
                long node = nodeBase + row;
                *(float2*)&g_x[node * D + col] = make_float2(v0, v1);
                g_hA[node * H2W + (col >> 1)] = __floats2half2_rn(v0, v1);
            }
            if (row + 8 < N) {
                float v2 = fmaxf(c[mt][nt][2] + b0, 0.f);
                float v3 = fmaxf(c[mt][nt][3] + b1, 0.f);
                long node = nodeBase + row + 8;
                *(float2*)&g_x[node * D + col] = make_float2(v2, v3);
                g_hA[node * H2W + (col >> 1)] = __floats2half2_rn(v2, v3);
            }
        }
    }
}

// ---------------- CSR build ----------------
__global__ void zero_rowptr_kernel()
{
    int i = blockIdx.x * blockDim.x + threadIdx.x;
    if (i < RP_TOT) g_rowptr[i] = 0;
}

__global__ void hist_kernel(const int* __restrict__ ei_pa, const int* __restrict__ ei_ap,
                            const int* __restrict__ ei_ps, const int* __restrict__ ei_sp)
{
    int e = blockIdx.x * blockDim.x + threadIdx.x;
    if (e >= E_TOT) return;
    const int* ei; int l, rpb;
    if (e < E_PA)                   { ei = ei_pa; l = e;                      rpb = RP_PA; }
    else if (e < E_PA + E_AP)       { ei = ei_ap; l = e - E_PA;               rpb = RP_AP; }
    else if (e < E_PA + E_AP + E_PS){ ei = ei_ps; l = e - E_PA - E_AP;        rpb = RP_PS; }
    else                            { ei = ei_sp; l = e - E_PA - E_AP - E_PS; rpb = RP_SP; }
    atomicAdd(&g_rowptr[rpb + 1 + ei[l]], 1);
}

__global__ void scan_kernel()
{
    __shared__ int ssum[1024];
    int base, n;
    if (blockIdx.x == 0)      { base = RP_PA; n = NP + 1;  }
    else if (blockIdx.x == 1) { base = RP_AP; n = NA + 1;  }
    else if (blockIdx.x == 2) { base = RP_PS; n = NP + 1;  }
    else                      { base = RP_SP; n = NSU + 1; }
    int tid = threadIdx.x;
    int chunk = (n + 1023) >> 10;
    int s0 = tid * chunk;
    int s1 = s0 + chunk; if (s1 > n) s1 = n; if (s0 > n) s0 = n;

    int sum = 0;
    for (int j = s0; j < s1; j++) sum += g_rowptr[base + j];
    ssum[tid] = sum;
    __syncthreads();
    for (int off = 1; off < 1024; off <<= 1) {
        int v = (tid >= off) ? ssum[tid - off] : 0;
        __syncthreads();
        ssum[tid] += v;
        __syncthreads();
    }
    int run = (tid == 0) ? 0 : ssum[tid - 1];
    for (int j = s0; j < s1; j++) {
        run += g_rowptr[base + j];
        g_rowptr[base + j] = run;
        g_cursor[base + j] = run;
    }
}

__global__ void scatter_kernel(const int* __restrict__ ei_pa, const int* __restrict__ ei_ap,
                               const int* __restrict__ ei_ps, const int* __restrict__ ei_sp)
{
    int e = blockIdx.x * blockDim.x + threadIdx.x;
    if (e >= E_TOT) return;
    const int* ei; int l, rpb, cb, En;
    if (e < E_PA)                   { ei = ei_pa; l = e;                      rpb = RP_PA; cb = CB_PA; En = E_PA; }
    else if (e < E_PA + E_AP)       { ei = ei_ap; l = e - E_PA;               rpb = RP_AP; cb = CB_AP; En = E_AP; }
    else if (e < E_PA + E_AP + E_PS){ ei = ei_ps; l = e - E_PA - E_AP;        rpb = RP_PS; cb = CB_PS; En = E_PS; }
    else                            { ei = ei_sp; l = e - E_PA - E_AP - E_PS; rpb = RP_SP; cb = CB_SP; En = E_SP; }
    int s = ei[l];
    int t = ei[En + l];
    int pos = atomicAdd(&g_cursor[rpb + s], 1);
    g_col[cb + pos] = t;
}

// ---------------- reductions ----------------
__device__ __forceinline__ float wsum32(float v)
{
#pragma unroll
    for (int o = 16; o; o >>= 1) v += __shfl_xor_sync(0xffffffffu, v, o);
    return v;
}

__device__ __forceinline__ float wsum16(float v)
{
#pragma unroll
    for (int o = 8; o; o >>= 1) v += __shfl_xor_sync(0xffffffffu, v, o);
    return v;
}

// ---------------- one-time: source-side d1/w2 + hop-0 target h1 ----------
__global__ void d1w2_kernel(const float* __restrict__ attn1, const float* __restrict__ attn2)
{
    int gw = (blockIdx.x * blockDim.x + threadIdx.x) >> 5;
    int lane = threadIdx.x & 31;
    if (gw >= NTOT) return;
    const float* xr = g_x + (long)gw * D;
    float x0 = xr[lane], x1 = xr[lane + 32];

    int k0, k1, base0, base1, l;
    if (gw < NP)            { l = gw;            k0 = 0; base0 = D1_PA; k1 = 2;  base1 = D1_PS; }
    else if (gw < NP + NA)  { l = gw - NP;       k0 = 1; base0 = D1_AP; k1 = -1; base1 = 0; }
    else                    { l = gw - NP - NA;  k0 = 3; base0 = D1_SP; k1 = -1; base1 = 0; }

#pragma unroll
    for (int hop = 0; hop < HOPS; hop++) {
        if (k1 >= 0 || hop < HOPS - 1) {
            const float* a1 = attn1 + (hop * 4 + k0) * D;
            const float* a2 = attn2 + (hop * 4 + k0) * D;
            float d1 = wsum32(x0 * a1[lane] + x1 * a1[lane + 32]);
            float d2 = wsum32(x0 * a2[lane] + x1 * a2[lane + 32]);
            float z = d1 + d2; z = z > 0.f ? z : 0.2f * z;
            if (lane == 0) {
                g_d1[hop * D1_TOT + base0 + l] = d1;
                g_w2[hop * D1_TOT + base0 + l] = __expf(z);
            }
        }
        if (k1 >= 0) {
            const float* a1 = attn1 + (hop * 4 + k1) * D;
            const float* a2 = attn2 + (hop * 4 + k1) * D;
            float d1 = wsum32(x0 * a1[lane] + x1 * a1[lane + 32]);
            float d2 = wsum32(x0 * a2[lane] + x1 * a2[lane + 32]);
            float z = d1 + d2; z = z > 0.f ? z : 0.2f * z;
            if (lane == 0) {
                g_d1[hop * D1_TOT + base1 + l] = d1;
                g_w2[hop * D1_TOT + base1 + l] = __expf(z);
            }
        }
    }

    // hop-0 target-side h1 (h == x at hop 0), written into buffer A
    if (gw < NP) {
        const float* a2a = attn2 + (0 * 4 + 1) * D;   // targets of ap edges
        const float* a2b = attn2 + (0 * 4 + 3) * D;   // targets of sp edges
        float va = wsum32(x0 * a2a[lane] + x1 * a2a[lane + 32]);
        float vb = wsum32(x0 * a2b[lane] + x1 * a2b[lane + 32]);
        if (lane == 0) { g_h1A[H1_AP + l] = va; g_h1A[H1_SP + l] = vb; }
    } else if (gw < NP + NA) {
        const float* a2a = attn2 + (0 * 4 + 0) * D;   // targets of pa edges
        float va = wsum32(x0 * a2a[lane] + x1 * a2a[lane + 32]);
        if (lane == 0) g_h1A[H1_PA + l] = va;
    } else {
        const float* a2a = attn2 + (0 * 4 + 2) * D;   // targets of ps edges
        float va = wsum32(x0 * a2a[lane] + x1 * a2a[lane + 32]);
        if (lane == 0) g_h1A[H1_PS + l] = va;
    }
}

// ---------------- shared inner loop: half-warp per node, fp16 h gather --------------
__device__ __forceinline__ void aggr_et_h(
    int nodeLocal, int rpBase, int colBase, int d1Base, int tOff, int hop,
    const __half2* __restrict__ h, const float* __restrict__ h1b, int hlane,
    uint64_t pol, const float4& x4, float wk, float4& acc)
{
    float d1 = g_d1[hop * D1_TOT + d1Base + nodeLocal];
    float w2 = g_w2[hop * D1_TOT + d1Base + nodeLocal];
    float4 num = make_float4(w2 * x4.x, w2 * x4.y, w2 * x4.z, w2 * x4.w);
    float div = w2;
    int e0 = g_rowptr[rpBase + nodeLocal];
    int e1 = g_rowptr[rpBase + nodeLocal + 1];
    const __half2* hb = h + (long)tOff * H2W + 2 * hlane;

    int e = e0;
    for (; e + 2 <= e1; e += 2) {
        int t0 = __ldcs(&g_col[colBase + e]);
        int t1 = __ldcs(&g_col[colBase + e + 1]);
        float p0 = ldg_keep(h1b + t0, pol);
        float p1 = ldg_keep(h1b + t1, pol);
        uint2 ru = ldg2u_keep(hb + (long)t0 * H2W, pol);
        uint2 rv = ldg2u_keep(hb + (long)t1 * H2W, pol);
        float2 u0 = __half22float2(*(__half2*)&ru.x);
        float2 u1 = __half22float2(*(__half2*)&ru.y);
        float2 v0 = __half22float2(*(__half2*)&rv.x);
        float2 v1 = __half22float2(*(__half2*)&rv.y);
        float z0 = d1 + p0; z0 = z0 > 0.f ? z0 : 0.2f * z0;
        float z1 = d1 + p1; z1 = z1 > 0.f ? z1 : 0.2f * z1;
        float w0 = __expf(z0);
        float w1 = __expf(z1);
        num.x += w0 * u0.x + w1 * v0.x;
        num.y += w0 * u0.y + w1 * v0.y;
        num.z += w0 * u1.x + w1 * v1.x;
        num.w += w0 * u1.y + w1 * v1.y;
        div   += w0 + w1;
    }
    if (e < e1) {
        int t = __ldcs(&g_col[colBase + e]);
        float zz = d1 + ldg_keep(h1b + t, pol);
        zz = zz > 0.f ? zz : 0.2f * zz;
        float w1 = __expf(zz);
        uint2 ru = ldg2u_keep(hb + (long)t * H2W, pol);
        float2 u0 = __half22float2(*(__half2*)&ru.x);
        float2 u1 = __half22float2(*(__half2*)&ru.y);
        num.x += w1 * u0.x; num.y += w1 * u0.y;
        num.z += w1 * u1.x; num.w += w1 * u1.y;
        div   += w1;
    }
    float s = wk / div;
    acc.x += num.x * s; acc.y += num.y * s; acc.z += num.z * s; acc.w += num.w * s;
}

// ---------------- hops 0..HOPS-2: all nodes, h1 epilogue for next hop ---------------
__global__ void __launch_bounds__(256) aggr_kernel(
    const float* __restrict__ attn2, const float* __restrict__ lw, int hop, int curB)
{
    int gn0 = (blockIdx.x * blockDim.x + threadIdx.x) >> 4;  // half-warp slot
    int hlane = threadIdx.x & 15;
    if (gn0 >= NTOT) return;
    // subject nodes first (highest degree -> avoid end-of-grid tail)
    int gn = (gn0 < NSU) ? (NP + NA + gn0) : (gn0 - NSU);
    uint64_t pol = mkpol_evict_last();
    const __half2* h  = curB ? g_hB : g_hA;
    __half2*       hn = curB ? g_hA : g_hB;
    const float* h1r = (hop & 1) ? g_h1B : g_h1A;
    float*       h1w = (hop & 1) ? g_h1A : g_h1B;
    const float4 x4 = __ldcs((const float4*)(g_x + (long)gn * D + 4 * hlane));
    float4 acc = make_float4(0.f, 0.f, 0.f, 0.f);

    if (gn < NP) {
        float l0 = lw[hop * 4 + 0], l2 = lw[hop * 4 + 2];
        float m = fmaxf(l0, l2);
        float e0 = __expf(l0 - m), e2 = __expf(l2 - m);
        float inv = 1.f / (e0 + e2);
        aggr_et_h(gn, RP_PA, CB_PA, D1_PA, NP,      hop, h, h1r + H1_PA, hlane, pol, x4, e0 * inv, acc);
        aggr_et_h(gn, RP_PS, CB_PS, D1_PS, NP + NA, hop, h, h1r + H1_PS, hlane, pol, x4, e2 * inv, acc);
    } else if (gn < NP + NA) {
        aggr_et_h(gn - NP, RP_AP, CB_AP, D1_AP, 0,  hop, h, h1r + H1_AP, hlane, pol, x4, 1.f, acc);
    } else {
        aggr_et_h(gn - NP - NA, RP_SP, CB_SP, D1_SP, 0, hop, h, h1r + H1_SP, hlane, pol, x4, 1.f, acc);
    }
    acc.x = acc.x > 0.f ? acc.x : __expf(acc.x) - 1.f;
    acc.y = acc.y > 0.f ? acc.y : __expf(acc.y) - 1.f;
    acc.z = acc.z > 0.f ? acc.z : __expf(acc.z) - 1.f;
    acc.w = acc.w > 0.f ? acc.w : __expf(acc.w) - 1.f;
    {
        uint2 packed;
        *(__half2*)&packed.x = __floats2half2_rn(acc.x, acc.y);
        *(__half2*)&packed.y = __floats2half2_rn(acc.z, acc.w);
        __stcs((uint2*)(hn + (long)gn * H2W + 2 * hlane), packed);
    }

    // ---- fused: target-side h1 for the NEXT hop from the fresh hn row ----
    int nhop = hop + 1;
    {
        if (gn < NP) {
            const float4 a2a = *(const float4*)(attn2 + (nhop * 4 + 1) * D + 4 * hlane);
            const float4 a2b = *(const float4*)(attn2 + (nhop * 4 + 3) * D + 4 * hlane);
            float va = wsum16(acc.x * a2a.x + acc.y * a2a.y + acc.z * a2a.z + acc.w * a2a.w);
            float vb = wsum16(acc.x * a2b.x + acc.y * a2b.y + acc.z * a2b.z + acc.w * a2b.w);
            if (hlane == 0) { h1w[H1_AP + gn] = va; h1w[H1_SP + gn] = vb; }
        } else if (gn < NP + NA) {
            const float4 a2a = *(const float4*)(attn2 + (nhop * 4 + 0) * D + 4 * hlane);
            float va = wsum16(acc.x * a2a.x + acc.y * a2a.y + acc.z * a2a.z + acc.w * a2a.w);
            if (hlane == 0) h1w[H1_PA + (gn - NP)] = va;
        } else {
            const float4 a2a = *(const float4*)(attn2 + (nhop * 4 + 2) * D + 4 * hlane);
            float va = wsum16(acc.x * a2a.x + acc.y * a2a.y + acc.z * a2a.z + acc.w * a2a.w);
            if (hlane == 0) h1w[H1_PS + (gn - NP - NA)] = va;
        }
    }
}

// ---------------- final hop: paper nodes only, fc2 fused ----------------------------
__global__ void __launch_bounds__(256) aggr_final_kernel(
    const float* __restrict__ W, const float* __restrict__ bias,
    const float* __restrict__ lw, float* __restrict__ out)
{
    __shared__ float Ws[NOUT * D];
    __shared__ float bs[NOUT];
    int tid = threadIdx.x;
    for (int i = tid; i < NOUT * D; i += 256) Ws[i] = W[i];
    if (tid < NOUT) bs[tid] = bias[tid];
    __syncthreads();

    int gn = (blockIdx.x * 256 + tid) >> 4;
    int hlane = tid & 15;
    if (gn >= NP) return;
    const int hop = HOPS - 1;   // 4
    uint64_t pol = mkpol_evict_last();
    const float4 x4 = __ldcs((const float4*)(g_x + (long)gn * D + 4 * hlane));
    float4 acc = make_float4(0.f, 0.f, 0.f, 0.f);

    float l0 = lw[hop * 4 + 0], l2 = lw[hop * 4 + 2];
    float m = fmaxf(l0, l2);
    float e0 = __expf(l0 - m), e2 = __expf(l2 - m);
    float inv = 1.f / (e0 + e2);
    aggr_et_h(gn, RP_PA, CB_PA, D1_PA, NP,      hop, g_hA, g_h1A + H1_PA, hlane, pol, x4, e0 * inv, acc);
    aggr_et_h(gn, RP_PS, CB_PS, D1_PS, NP + NA, hop, g_hA, g_h1A + H1_PS, hlane, pol, x4, e2 * inv, acc);

    acc.x = acc.x > 0.f ? acc.x : __expf(acc.x) - 1.f;
    acc.y = acc.y > 0.f ? acc.y : __expf(acc.y) - 1.f;
    acc.z = acc.z > 0.f ? acc.z : __expf(acc.z) - 1.f;
    acc.w = acc.w > 0.f ? acc.w : __expf(acc.w) - 1.f;

    // fused fc2: out[gn, o] = sum_d acc_d * W[o, d] + b[o]
    float res = 0.f;
#pragma unroll
    for (int o = 0; o < NOUT; o++) {
        const float* wr = Ws + o * D + 4 * hlane;
        float s = acc.x * wr[0] + acc.y * wr[1] + acc.z * wr[2] + acc.w * wr[3];
        s = wsum16(s);
        if (hlane == o) res = s;
    }
    out[gn * NOUT + hlane] = res + bs[hlane];
}

// ---------------- launch ----------------
extern "C" void kernel_launch(void* const* d_in, const int* in_sizes, int n_in,
                              void* d_out, int out_size)
{
    const float* x_paper   = (const float*)d_in[0];
    const float* x_author  = (const float*)d_in[1];
    const float* x_subject = (const float*)d_in[2];
    const float* fc1p_w = (const float*)d_in[3];
    const float* fc1p_b = (const float*)d_in[4];
    const float* fc1a_w = (const float*)d_in[5];
    const float* fc1a_b = (const float*)d_in[6];
    const float* fc1s_w = (const float*)d_in[7];
    const float* fc1s_b = (const float*)d_in[8];
    const float* attn1  = (const float*)d_in[9];
    const float* attn2  = (const float*)d_in[10];
    const float* lw     = (const float*)d_in[11];
    const float* fc2_w  = (const float*)d_in[12];
    const float* fc2_b  = (const float*)d_in[13];
    const int* ei_pa = (const int*)d_in[14];
    const int* ei_ap = (const int*)d_in[15];
    const int* ei_ps = (const int*)d_in[16];
    const int* ei_sp = (const int*)d_in[17];
    float* out = (float*)d_out;

    zero_rowptr_kernel<<<(RP_TOT + 255) / 256, 256>>>();

    fc1_kernel<<<(NP  + 127) / 128, 256>>>(x_paper,   fc1p_w, fc1p_b, NP,  512, 0);
    fc1_kernel<<<(NA  + 127) / 128, 256>>>(x_author,  fc1a_w, fc1a_b, NA,  256, NP);
    fc1_kernel<<<(NSU + 127) / 128, 256>>>(x_subject, fc1s_w, fc1s_b, NSU, 128, NP + NA);

    hist_kernel<<<(E_TOT + 255) / 256, 256>>>(ei_pa, ei_ap, ei_ps, ei_sp);
    scan_kernel<<<4, 1024>>>();
    scatter_kernel<<<(E_TOT + 255) / 256, 256>>>(ei_pa, ei_ap, ei_ps, ei_sp);

    d1w2_kernel<<<(NTOT * 32 + 255) / 256, 256>>>(attn1, attn2);

    for (int hop = 0; hop < HOPS - 1; hop++) {
        int curB = hop & 1;
        aggr_kernel<<<(NTOT * 16 + 255) / 256, 256>>>(attn2, lw, hop, curB);
    }

    aggr_final_kernel<<<(NP * 16 + 255) / 256, 256>>>(fc2_w, fc2_b, lw, out);
}